// round 9
// baseline (speedup 1.0000x reference)
#include <cuda_runtime.h>
#include <cuda_bf16.h>
#include <math.h>
#include <stdint.h>

// ---------------------------------------------------------------------------
// SHMA block: mma.sync bf16 GEMMs, fused 3-term hi/lo segments, XOR-swizzled
// smem (3 CTAs/SM), BN1 stats fused in GEMM1, BN2 stats fused in proj GEMM.
// B=8, dim=d=512, N=4096, qkvg=2048.
// ---------------------------------------------------------------------------

#define BATCH 8
#define DIM   512
#define NPIX  4096
#define C4    2048

// ---------------- scratch (static device globals) --------------------------
__device__ __nv_bfloat16 g_ythi[67108864], g_ytlo[67108864]; // y^T (8*4096,2048)
__device__ __nv_bfloat16 g_athi[16777216], g_atlo[16777216]; // attn^T (8*4096,512)
__device__ float g_ypre[16777216];                   // ypre (8, 512, 4096) f32
__device__ float g_vkp[8388608];                     // vk split-K partials
__device__ __nv_bfloat16 g_khi[16777216], g_klo[16777216];   // k [b][d][n]
__device__ __nv_bfloat16 g_vhi[16777216], g_vlo[16777216];   // v [b][d][n]
__device__ __nv_bfloat16 g_qthi[16777216], g_qtlo[16777216]; // q^T [b][n][d]
__device__ __nv_bfloat16 g_xthi[16777216], g_xtlo[16777216]; // x^T [b][n][c]
__device__ __nv_bfloat16 g_othi[16777216], g_otlo[16777216]; // o^T [b][n][d]
__device__ __nv_bfloat16 g_vkhi[2097152], g_vklo[2097152];   // vk [b][d][e]
__device__ __nv_bfloat16 g_wqhi[1048576], g_wqlo[1048576];   // qkvg_w
__device__ __nv_bfloat16 g_pwhi[262144],  g_pwlo[262144];    // proj_w
__device__ float g_a1[2048], g_b1[2048], g_a2[512], g_b2[512];
__device__ float g_s1[2048], g_s2[2048];             // BN1 accum
__device__ float g_t1[512], g_t2[512];               // BN2 accum
__device__ float g_ksum[4096], g_z[32768];

// ---------------- helpers ---------------------------------------------------
__device__ __forceinline__ uint32_t smem_u32(const void* p) {
    uint32_t a;
    asm("{ .reg .u64 t; cvta.to.shared.u64 t, %1; cvt.u32.u64 %0, t; }"
        : "=r"(a) : "l"(p));
    return a;
}
__device__ __forceinline__ void ldsm_x4(uint32_t& r0, uint32_t& r1,
                                        uint32_t& r2, uint32_t& r3,
                                        uint32_t addr) {
    asm volatile("ldmatrix.sync.aligned.m8n8.x4.shared.b16 {%0,%1,%2,%3}, [%4];"
                 : "=r"(r0), "=r"(r1), "=r"(r2), "=r"(r3) : "r"(addr));
}
__device__ __forceinline__ void mma16816(float* c, const uint32_t* a,
                                         uint32_t b0, uint32_t b1) {
    asm volatile(
        "mma.sync.aligned.m16n8k16.row.col.f32.bf16.bf16.f32 "
        "{%0,%1,%2,%3}, {%4,%5,%6,%7}, {%8,%9}, {%0,%1,%2,%3};"
        : "+f"(c[0]), "+f"(c[1]), "+f"(c[2]), "+f"(c[3])
        : "r"(a[0]), "r"(a[1]), "r"(a[2]), "r"(a[3]), "r"(b0), "r"(b1));
}
__device__ __forceinline__ void cpasync16(uint32_t dst, const void* src) {
    asm volatile("cp.async.cg.shared.global [%0], [%1], 16;"
                 :: "r"(dst), "l"(src));
}
#define CP_COMMIT() asm volatile("cp.async.commit_group;" ::: "memory")
#define CP_WAIT(n)  asm volatile("cp.async.wait_group %0;" :: "n"(n) : "memory")

__device__ __forceinline__ __nv_bfloat162 split_hi2(float a, float b,
                                                    __nv_bfloat162& lo) {
    __nv_bfloat16 h0 = __float2bfloat16(a), h1 = __float2bfloat16(b);
    lo = __halves2bfloat162(__float2bfloat16(a - __bfloat162float(h0)),
                            __float2bfloat16(b - __bfloat162float(h1)));
    return __halves2bfloat162(h0, h1);
}

// swizzled smem offset within a tile: row (0..127) of 64B, 16B unit u (0..3)
__device__ __forceinline__ uint32_t swz(int row, int u) {
    return (uint32_t)((row << 6) + ((u ^ ((row >> 1) & 3)) << 4));
}

// ---------------------------------------------------------------------------
// mma.sync GEMM, fused 3-segment hi/lo (Ah*Bh + Ah*Bl + Al*Bh, fragment
// reuse). 128x128 CTA tile, BK=32, 128 threads (2x2 warps, 64x64 warp
// tiles), 2-stage cp.async double buffer, XOR-swizzled smem (32KB/stage).
// Split-K via blockIdx.z = b*kchunks + ks (f32 C offset by zi*sC).
// ZDIV: row-divide by zb. OUTSPLIT: hi/lo bf16 out.
// STATS: per-column sum/sumsq atomics (g_s1/g_s2).
// ROWSTATS: per-row sum/sumsq atomics (g_t1/g_t2).
// ---------------------------------------------------------------------------
#define BUFB 8192u                     // 128 rows x 64B per operand tile
#define STAGEB (4u * BUFB)             // Ah, Al, Bh, Bl
#define GSMEM (2 * STAGEB + 512)       // 2 stages + zsm

template <bool ZDIV, bool OUTSPLIT, bool STATS, bool ROWSTATS>
__global__ void __launch_bounds__(128, 3)
gemm_mma(const __nv_bfloat16* __restrict__ Ahi_, const __nv_bfloat16* __restrict__ Alo_,
         const __nv_bfloat16* __restrict__ Bhi_, const __nv_bfloat16* __restrict__ Blo_,
         float* __restrict__ C_, __nv_bfloat16* __restrict__ Chi_,
         __nv_bfloat16* __restrict__ Clo_,
         int N, int K, int ldk, int kchunks,
         long long sA, long long sB, long long sC,
         float alpha, const float* __restrict__ zb)
{
    extern __shared__ char smem[];
    const int zi = blockIdx.z;
    const int b  = zi / kchunks;
    const int ks = zi - b * kchunks;
    const long long koff = (long long)ks * K;

    const __nv_bfloat16* Ah = Ahi_ + (long long)b * sA + koff;
    const __nv_bfloat16* Al = Alo_ + (long long)b * sA + koff;
    const __nv_bfloat16* Bh = Bhi_ + (long long)b * sB + koff;
    const __nv_bfloat16* Bl = Blo_ + (long long)b * sB + koff;
    const int m0 = blockIdx.y << 7, n0 = blockIdx.x << 7;
    const int tid = threadIdx.x, wid = tid >> 5, lane = tid & 31;
    const int wm = wid & 1, wn = wid >> 1;
    const int tig = lane & 3, grp = lane >> 2;

    const uint32_t sb = smem_u32(smem);
    float* zsm = (float*)(smem + 2 * STAGEB);
    if (ZDIV) zsm[tid] = 1.f / zb[(long long)b * 4096 + m0 + tid];

    const int CH = K >> 5;

    float acc[4][8][4];
#pragma unroll
    for (int i = 0; i < 4; i++)
#pragma unroll
        for (int j = 0; j < 8; j++)
#pragma unroll
            for (int t = 0; t < 4; t++) acc[i][j][t] = 0.f;

    // load all 4 operand tiles for K-chunk c into stage st
    auto load = [&](int c, int st) {
        long long kp = (long long)c << 5;
        uint32_t base = sb + (uint32_t)st * STAGEB;
#pragma unroll
        for (int i = 0; i < 4; i++) {
            int slot = tid + (i << 7);
            int row = slot >> 2, u = slot & 3;
            uint32_t d = swz(row, u);
            long long aoff = (long long)(m0 + row) * ldk + kp + (u << 3);
            long long boff = (long long)(n0 + row) * ldk + kp + (u << 3);
            cpasync16(base + d, Ah + aoff);
            cpasync16(base + BUFB + d, Al + aoff);
            cpasync16(base + 2 * BUFB + d, Bh + boff);
            cpasync16(base + 3 * BUFB + d, Bl + boff);
        }
        CP_COMMIT();
    };

    load(0, 0);

    const int lrow16 = lane & 15;
    const int lhalf = lane >> 4;        // 0/1 -> 16B unit within k-16 group

    int buf = 0;
    for (int c = 0; c < CH; c++) {
        if (c + 1 < CH) { load(c + 1, buf ^ 1); CP_WAIT(1); }
        else            { CP_WAIT(0); }
        __syncthreads();

        uint32_t base = sb + (uint32_t)buf * STAGEB;
#pragma unroll
        for (int ko2 = 0; ko2 < 2; ko2++) {
            const int cu = (ko2 << 1) + lhalf;   // 16B unit index 0..3
            uint32_t ah[4][4], bh[4][4], tt[4][4];
#pragma unroll
            for (int mi = 0; mi < 4; mi++) {
                int r = (wm << 6) + (mi << 4) + lrow16;
                ldsm_x4(ah[mi][0], ah[mi][1], ah[mi][2], ah[mi][3],
                        base + swz(r, cu));
            }
#pragma unroll
            for (int nb = 0; nb < 4; nb++) {
                int r = (wn << 6) + (nb << 4) + lrow16;
                ldsm_x4(bh[nb][0], bh[nb][1], bh[nb][2], bh[nb][3],
                        base + 2 * BUFB + swz(r, cu));
            }
            // seg1: Ah * Bh
#pragma unroll
            for (int mi = 0; mi < 4; mi++)
#pragma unroll
                for (int ni = 0; ni < 8; ni++) {
                    int nb = ni >> 1, hf = ni & 1;
                    mma16816(acc[mi][ni], ah[mi], bh[nb][hf], bh[nb][hf + 2]);
                }
            // seg2: Ah * Bl (reuse ah fragments)
#pragma unroll
            for (int nb = 0; nb < 4; nb++) {
                int r = (wn << 6) + (nb << 4) + lrow16;
                ldsm_x4(tt[nb][0], tt[nb][1], tt[nb][2], tt[nb][3],
                        base + 3 * BUFB + swz(r, cu));
            }
#pragma unroll
            for (int mi = 0; mi < 4; mi++)
#pragma unroll
                for (int ni = 0; ni < 8; ni++) {
                    int nb = ni >> 1, hf = ni & 1;
                    mma16816(acc[mi][ni], ah[mi], tt[nb][hf], tt[nb][hf + 2]);
                }
            // seg3: Al * Bh (reuse bh fragments)
#pragma unroll
            for (int mi = 0; mi < 4; mi++) {
                int r = (wm << 6) + (mi << 4) + lrow16;
                ldsm_x4(tt[mi][0], tt[mi][1], tt[mi][2], tt[mi][3],
                        base + BUFB + swz(r, cu));
            }
#pragma unroll
            for (int mi = 0; mi < 4; mi++)
#pragma unroll
                for (int ni = 0; ni < 8; ni++) {
                    int nb = ni >> 1, hf = ni & 1;
                    mma16816(acc[mi][ni], tt[mi], bh[nb][hf], bh[nb][hf + 2]);
                }
        }
        __syncthreads();
        buf ^= 1;
    }

    // epilogue
    float* C = C_ + (long long)zi * sC;
    __nv_bfloat16* Chi = Chi_ + (long long)b * sC;
    __nv_bfloat16* Clo = Clo_ + (long long)b * sC;
    float cs1[8][2], cs2[8][2];
    float rs1[4][2], rs2[4][2];
    if (STATS) {
#pragma unroll
        for (int ni = 0; ni < 8; ni++) {
            cs1[ni][0] = cs1[ni][1] = 0.f;
            cs2[ni][0] = cs2[ni][1] = 0.f;
        }
    }
    if (ROWSTATS) {
#pragma unroll
        for (int mi = 0; mi < 4; mi++) {
            rs1[mi][0] = rs1[mi][1] = 0.f;
            rs2[mi][0] = rs2[mi][1] = 0.f;
        }
    }
#pragma unroll
    for (int mi = 0; mi < 4; mi++) {
        int rl = (wm << 6) + (mi << 4) + grp;
        int row = m0 + rl;
        float zr0 = 1.f, zr1 = 1.f;
        if (ZDIV) { zr0 = zsm[rl]; zr1 = zsm[rl + 8]; }
#pragma unroll
        for (int ni = 0; ni < 8; ni++) {
            int col = n0 + (wn << 6) + (ni << 3) + (tig << 1);
            float v0 = acc[mi][ni][0] * alpha;
            float v1 = acc[mi][ni][1] * alpha;
            float v2 = acc[mi][ni][2] * alpha;
            float v3 = acc[mi][ni][3] * alpha;
            if (ZDIV) { v0 *= zr0; v1 *= zr0; v2 *= zr1; v3 *= zr1; }
            if (STATS) {
                cs1[ni][0] += v0 + v2;
                cs1[ni][1] += v1 + v3;
                cs2[ni][0] += v0 * v0 + v2 * v2;
                cs2[ni][1] += v1 * v1 + v3 * v3;
            }
            if (ROWSTATS) {
                rs1[mi][0] += v0 + v1;
                rs2[mi][0] += v0 * v0 + v1 * v1;
                rs1[mi][1] += v2 + v3;
                rs2[mi][1] += v2 * v2 + v3 * v3;
            }
            if (OUTSPLIT) {
                __nv_bfloat162 l0, l1;
                __nv_bfloat162 h0 = split_hi2(v0, v1, l0);
                __nv_bfloat162 h1 = split_hi2(v2, v3, l1);
                *(__nv_bfloat162*)(Chi + (long long)row * N + col) = h0;
                *(__nv_bfloat162*)(Chi + (long long)(row + 8) * N + col) = h1;
                *(__nv_bfloat162*)(Clo + (long long)row * N + col) = l0;
                *(__nv_bfloat162*)(Clo + (long long)(row + 8) * N + col) = l1;
            } else {
                float2 p0; p0.x = v0; p0.y = v1;
                float2 p1; p1.x = v2; p1.y = v3;
                *(float2*)(C + (long long)row * N + col) = p0;
                *(float2*)(C + (long long)(row + 8) * N + col) = p1;
            }
        }
    }
    if (STATS) {
#pragma unroll
        for (int ni = 0; ni < 8; ni++)
#pragma unroll
            for (int h = 0; h < 2; h++) {
                float s1 = cs1[ni][h], s2 = cs2[ni][h];
                s1 += __shfl_down_sync(0xffffffffu, s1, 16);
                s2 += __shfl_down_sync(0xffffffffu, s2, 16);
                s1 += __shfl_down_sync(0xffffffffu, s1, 8);
                s2 += __shfl_down_sync(0xffffffffu, s2, 8);
                s1 += __shfl_down_sync(0xffffffffu, s1, 4);
                s2 += __shfl_down_sync(0xffffffffu, s2, 4);
                if (lane < 4) {
                    int col = n0 + (wn << 6) + (ni << 3) + (lane << 1) + h;
                    atomicAdd(&g_s1[col], s1);
                    atomicAdd(&g_s2[col], s2);
                }
            }
    }
    if (ROWSTATS) {
#pragma unroll
        for (int mi = 0; mi < 4; mi++)
#pragma unroll
            for (int h = 0; h < 2; h++) {
                float s1 = rs1[mi][h], s2 = rs2[mi][h];
                s1 += __shfl_down_sync(0xffffffffu, s1, 2, 4);
                s2 += __shfl_down_sync(0xffffffffu, s2, 2, 4);
                s1 += __shfl_down_sync(0xffffffffu, s1, 1, 4);
                s2 += __shfl_down_sync(0xffffffffu, s2, 1, 4);
                if (tig == 0) {
                    int row = m0 + (wm << 6) + (mi << 4) + grp + (h << 3);
                    atomicAdd(&g_t1[row], s1);
                    atomicAdd(&g_t2[row], s2);
                }
            }
    }
}

// ---------------------------------------------------------------------------
// vk split-K reduce -> hi/lo bf16 with alpha
// ---------------------------------------------------------------------------
__global__ void vkred_kernel()
{
    long long i4 = (long long)(blockIdx.x * 256 + threadIdx.x) * 4;
    int b = (int)(i4 >> 18);
    long long off = i4 & 262143;
    const float* p = g_vkp + ((long long)b * 4) * 262144 + off;
    float4 s0 = *(const float4*)p;
    float4 s1 = *(const float4*)(p + 262144);
    float4 s2 = *(const float4*)(p + 2 * 262144);
    float4 s3 = *(const float4*)(p + 3 * 262144);
    const float al = 1.f / 4096.f;
    float v0 = ((s0.x + s1.x) + (s2.x + s3.x)) * al;
    float v1 = ((s0.y + s1.y) + (s2.y + s3.y)) * al;
    float v2 = ((s0.z + s1.z) + (s2.z + s3.z)) * al;
    float v3 = ((s0.w + s1.w) + (s2.w + s3.w)) * al;
    __nv_bfloat162 l0, l1;
    __nv_bfloat162 h0 = split_hi2(v0, v1, l0);
    __nv_bfloat162 h1 = split_hi2(v2, v3, l1);
    *(__nv_bfloat162*)(g_vkhi + i4)     = h0;
    *(__nv_bfloat162*)(g_vkhi + i4 + 2) = h1;
    *(__nv_bfloat162*)(g_vklo + i4)     = l0;
    *(__nv_bfloat162*)(g_vklo + i4 + 2) = l1;
}

// ---------------------------------------------------------------------------
__global__ void zero_kernel()
{
    int i = blockIdx.x * 256 + threadIdx.x;
    if (i < 2048) { g_s1[i] = 0.f; g_s2[i] = 0.f; }
    if (i < 512)  { g_t1[i] = 0.f; g_t2[i] = 0.f; }
    if (i < 4096) g_ksum[i] = 0.f;
}

__global__ void bn1_finalize(const float* __restrict__ gamma,
                             const float* __restrict__ beta)
{
    int c = blockIdx.x * 256 + threadIdx.x;
    const float inv = 1.f / (BATCH * NPIX);
    float mean = g_s1[c] * inv;
    float var = g_s2[c] * inv - mean * mean;
    float av = gamma[c] * rsqrtf(var + 1e-5f);
    g_a1[c] = av;
    g_b1[c] = beta[c] - mean * av;
}

__global__ void bn2_finalize(const float* __restrict__ gamma,
                             const float* __restrict__ beta)
{
    int c = blockIdx.x * 256 + threadIdx.x;
    const float inv = 1.f / (BATCH * NPIX);
    float mean = g_t1[c] * inv;
    float var = g_t2[c] * inv - mean * mean;
    float av = gamma[c] * rsqrtf(var + 1e-5f);
    g_a2[c] = av;
    g_b2[c] = beta[c] - mean * av;
}

// q: sigmoid(affine(y[:, 0:512])) -> q^T hi/lo bf16
__global__ void q_kernel()
{
    int i = blockIdx.x * 256 + threadIdx.x;
    int r = i >> 7;
    int dg = (i & 127) << 2;
    long long yb = (long long)r * C4 + dg;
    __nv_bfloat162 yh0 = *(const __nv_bfloat162*)(g_ythi + yb);
    __nv_bfloat162 yh1 = *(const __nv_bfloat162*)(g_ythi + yb + 2);
    __nv_bfloat162 yl0 = *(const __nv_bfloat162*)(g_ytlo + yb);
    __nv_bfloat162 yl1 = *(const __nv_bfloat162*)(g_ytlo + yb + 2);
    float4 a4 = *(const float4*)(g_a1 + dg);
    float4 b4 = *(const float4*)(g_b1 + dg);
    float y0 = __bfloat162float(yh0.x) + __bfloat162float(yl0.x);
    float y1 = __bfloat162float(yh0.y) + __bfloat162float(yl0.y);
    float y2 = __bfloat162float(yh1.x) + __bfloat162float(yl1.x);
    float y3 = __bfloat162float(yh1.y) + __bfloat162float(yl1.y);
    float q0 = 1.f / (1.f + expf(-(a4.x * y0 + b4.x)));
    float q1 = 1.f / (1.f + expf(-(a4.y * y1 + b4.y)));
    float q2 = 1.f / (1.f + expf(-(a4.z * y2 + b4.z)));
    float q3 = 1.f / (1.f + expf(-(a4.w * y3 + b4.w)));
    __nv_bfloat162 l0, l1;
    __nv_bfloat162 h0 = split_hi2(q0, q1, l0);
    __nv_bfloat162 h1 = split_hi2(q2, q3, l1);
    long long o = (long long)r * DIM + dg;
    *(__nv_bfloat162*)(g_qthi + o)     = h0;
    *(__nv_bfloat162*)(g_qthi + o + 2) = h1;
    *(__nv_bfloat162*)(g_qtlo + o)     = l0;
    *(__nv_bfloat162*)(g_qtlo + o + 2) = l1;
}

// k,v: 64x64 transpose y^T -> [b][d][n] hi/lo bf16, sigmoid/affine, ksum
__global__ void kvt_kernel()
{
    __shared__ float tk[64][65], tv[64][65];
    int bz = blockIdx.z;
    int n0 = blockIdx.x << 6, d0 = blockIdx.y << 6;
    int tx = threadIdx.x, ty = threadIdx.y;
    int dloc = tx << 1;
    float2 akp = *(const float2*)(g_a1 + 512 + d0 + dloc);
    float2 bkp = *(const float2*)(g_b1 + 512 + d0 + dloc);
    float2 avp = *(const float2*)(g_a1 + 1024 + d0 + dloc);
    float2 bvp = *(const float2*)(g_b1 + 1024 + d0 + dloc);
#pragma unroll
    for (int i = 0; i < 8; i++) {
        int nl = ty + (i << 3);
        long long rb = ((long long)(bz << 12) + n0 + nl) * C4;
        __nv_bfloat162 kh2 = *(const __nv_bfloat162*)(g_ythi + rb + 512 + d0 + dloc);
        __nv_bfloat162 kl2 = *(const __nv_bfloat162*)(g_ytlo + rb + 512 + d0 + dloc);
        __nv_bfloat162 vh2 = *(const __nv_bfloat162*)(g_ythi + rb + 1024 + d0 + dloc);
        __nv_bfloat162 vl2 = *(const __nv_bfloat162*)(g_ytlo + rb + 1024 + d0 + dloc);
        float k0 = __bfloat162float(kh2.x) + __bfloat162float(kl2.x);
        float k1 = __bfloat162float(kh2.y) + __bfloat162float(kl2.y);
        float v0 = __bfloat162float(vh2.x) + __bfloat162float(vl2.x);
        float v1 = __bfloat162float(vh2.y) + __bfloat162float(vl2.y);
        tk[nl][dloc]     = 1.f / (1.f + expf(-(akp.x * k0 + bkp.x)));
        tk[nl][dloc + 1] = 1.f / (1.f + expf(-(akp.y * k1 + bkp.y)));
        tv[nl][dloc]     = avp.x * v0 + bvp.x;
        tv[nl][dloc + 1] = avp.y * v1 + bvp.y;
    }
    __syncthreads();
#pragma unroll
    for (int i = 0; i < 8; i++) {
        int dl = ty + (i << 3);
        int d = d0 + dl;
        int nl = tx << 1;
        float k0 = tk[nl][dl], k1 = tk[nl + 1][dl];
        float v0 = tv[nl][dl], v1 = tv[nl + 1][dl];
        long long o = ((long long)(bz << 9) + d) * NPIX + n0 + nl;
        __nv_bfloat162 kl2, vl2;
        __nv_bfloat162 kh2 = split_hi2(k0, k1, kl2);
        __nv_bfloat162 vh2 = split_hi2(v0, v1, vl2);
        *(__nv_bfloat162*)(g_khi + o) = kh2;
        *(__nv_bfloat162*)(g_klo + o) = kl2;
        *(__nv_bfloat162*)(g_vhi + o) = vh2;
        *(__nv_bfloat162*)(g_vlo + o) = vl2;
        float s = k0 + k1;
#pragma unroll
        for (int off = 16; off > 0; off >>= 1)
            s += __shfl_down_sync(0xffffffffu, s, off);
        if (tx == 0) atomicAdd(&g_ksum[(bz << 9) + d], s);
    }
}

// z[r] = sum_d kmean[d] * q[r][d] + eps
__global__ void z_kernel()
{
    __shared__ float km[512];
    int r0 = blockIdx.x << 3;
    int bb = r0 >> 12;
    for (int i = threadIdx.x; i < 512; i += 256)
        km[i] = g_ksum[(bb << 9) + i] * (1.f / NPIX);
    __syncthreads();
    int w = threadIdx.x >> 5, lane = threadIdx.x & 31;
    int r = r0 + w;
    const __nv_bfloat16* qh = g_qthi + (long long)r * DIM;
    const __nv_bfloat16* ql = g_qtlo + (long long)r * DIM;
    float s = 0.f;
#pragma unroll
    for (int i = 0; i < 16; i++) {
        int d = lane + (i << 5);
        s += km[d] * (__bfloat162float(qh[d]) + __bfloat162float(ql[d]));
    }
#pragma unroll
    for (int off = 16; off > 0; off >>= 1)
        s += __shfl_down_sync(0xffffffffu, s, off);
    if (lane == 0) g_z[r] = s + 5e-4f;
}

// RMSNorm row + anw + SiLU(gate) -> o^T hi/lo
__global__ void rmsgate_kernel(const float* __restrict__ anw)
{
    __shared__ float red[4];
    int r = blockIdx.x;
    int t = threadIdx.x;
    int dg = t << 2;
    long long arow = (long long)r * DIM + dg;
    __nv_bfloat162 ah0 = *(const __nv_bfloat162*)(g_athi + arow);
    __nv_bfloat162 ah1 = *(const __nv_bfloat162*)(g_athi + arow + 2);
    __nv_bfloat162 al0 = *(const __nv_bfloat162*)(g_atlo + arow);
    __nv_bfloat162 al1 = *(const __nv_bfloat162*)(g_atlo + arow + 2);
    float a0 = __bfloat162float(ah0.x) + __bfloat162float(al0.x);
    float a1 = __bfloat162float(ah0.y) + __bfloat162float(al0.y);
    float a2 = __bfloat162float(ah1.x) + __bfloat162float(al1.x);
    float a3 = __bfloat162float(ah1.y) + __bfloat162float(al1.y);
    float ss = a0 * a0 + a1 * a1 + a2 * a2 + a3 * a3;
    int lane = t & 31, w = t >> 5;
#pragma unroll
    for (int off = 16; off > 0; off >>= 1)
        ss += __shfl_down_sync(0xffffffffu, ss, off);
    if (lane == 0) red[w] = ss;
    __syncthreads();
    float tot = red[0] + red[1] + red[2] + red[3];
    float rms = rsqrtf(tot * (1.f / DIM) + 1e-6f);

    long long grow = (long long)r * C4 + 1536 + dg;
    __nv_bfloat162 gh0 = *(const __nv_bfloat162*)(g_ythi + grow);
    __nv_bfloat162 gh1 = *(const __nv_bfloat162*)(g_ythi + grow + 2);
    __nv_bfloat162 gl0 = *(const __nv_bfloat162*)(g_ytlo + grow);
    __nv_bfloat162 gl1 = *(const __nv_bfloat162*)(g_ytlo + grow + 2);
    float yg0 = __bfloat162float(gh0.x) + __bfloat162float(gl0.x);
    float yg1 = __bfloat162float(gh0.y) + __bfloat162float(gl0.y);
    float yg2 = __bfloat162float(gh1.x) + __bfloat162float(gl1.x);
    float yg3 = __bfloat162float(gh1.y) + __bfloat162float(gl1.y);
    float4 ga = *(const float4*)(g_a1 + 1536 + dg);
    float4 gb = *(const float4*)(g_b1 + 1536 + dg);
    float4 wn = *(const float4*)(anw + dg);
    float g0 = ga.x * yg0 + gb.x, g1 = ga.y * yg1 + gb.y;
    float g2 = ga.z * yg2 + gb.z, g3 = ga.w * yg3 + gb.w;
    float o0 = a0 * rms * wn.x * (g0 / (1.f + expf(-g0)));
    float o1 = a1 * rms * wn.y * (g1 / (1.f + expf(-g1)));
    float o2 = a2 * rms * wn.z * (g2 / (1.f + expf(-g2)));
    float o3 = a3 * rms * wn.w * (g3 / (1.f + expf(-g3)));
    __nv_bfloat162 l0, l1;
    __nv_bfloat162 h0 = split_hi2(o0, o1, l0);
    __nv_bfloat162 h1 = split_hi2(o2, o3, l1);
    long long o = (long long)r * DIM + dg;
    *(__nv_bfloat162*)(g_othi + o)     = h0;
    *(__nv_bfloat162*)(g_othi + o + 2) = h1;
    *(__nv_bfloat162*)(g_otlo + o)     = l0;
    *(__nv_bfloat162*)(g_otlo + o + 2) = l1;
}

__global__ void bnapply_kernel(float* __restrict__ out)
{
    long long i = (long long)(blockIdx.x * blockDim.x + threadIdx.x) * 4;
    int c = (int)((i >> 12) & 511);
    float a = g_a2[c], bb = g_b2[c];
    float4 v = *reinterpret_cast<const float4*>(g_ypre + i);
    v.x = a * v.x + bb; v.y = a * v.y + bb;
    v.z = a * v.z + bb; v.w = a * v.w + bb;
    *reinterpret_cast<float4*>(out + i) = v;
}

__global__ void convert_split(const float* __restrict__ s,
                              __nv_bfloat16* __restrict__ hi,
                              __nv_bfloat16* __restrict__ lo, int n)
{
    int i = blockIdx.x * blockDim.x + threadIdx.x;
    if (i < n) {
        float v = s[i];
        __nv_bfloat16 h = __float2bfloat16(v);
        hi[i] = h;
        lo[i] = __float2bfloat16(v - __bfloat162float(h));
    }
}

__global__ void transpose_split(const float* __restrict__ src,
                                __nv_bfloat16* __restrict__ dhi,
                                __nv_bfloat16* __restrict__ dlo, int R, int Cc)
{
    __shared__ float t[32][33];
    int b = blockIdx.z;
    long long o = (long long)b * R * Cc;
    src += o; dhi += o; dlo += o;
    int c0 = blockIdx.x * 32, r0 = blockIdx.y * 32;
    int tx = threadIdx.x, ty = threadIdx.y;
#pragma unroll
    for (int i = 0; i < 4; i++)
        t[ty + 8 * i][tx] = src[(long long)(r0 + ty + 8 * i) * Cc + c0 + tx];
    __syncthreads();
#pragma unroll
    for (int i = 0; i < 4; i++) {
        int cc = c0 + ty + 8 * i;
        float v = t[tx][ty + 8 * i];
        __nv_bfloat16 h = __float2bfloat16(v);
        dhi[(long long)cc * R + r0 + tx] = h;
        dlo[(long long)cc * R + r0 + tx] = __float2bfloat16(v - __bfloat162float(h));
    }
}

// ---------------------------------------------------------------------------
extern "C" void kernel_launch(void* const* d_in, const int* in_sizes, int n_in,
                              void* d_out, int out_size)
{
    const float* x           = (const float*)d_in[0];
    const float* qkvg_w      = (const float*)d_in[1];
    const float* qkvg_gamma  = (const float*)d_in[2];
    const float* qkvg_beta   = (const float*)d_in[3];
    const float* attn_norm_w = (const float*)d_in[4];
    const float* proj_w      = (const float*)d_in[5];
    const float* proj_gamma  = (const float*)d_in[6];
    const float* proj_beta   = (const float*)d_in[7];
    float* out = (float*)d_out;

    cudaFuncSetAttribute(gemm_mma<false, false, false, false>,
                         cudaFuncAttributeMaxDynamicSharedMemorySize, GSMEM);
    cudaFuncSetAttribute(gemm_mma<false, true, true, false>,
                         cudaFuncAttributeMaxDynamicSharedMemorySize, GSMEM);
    cudaFuncSetAttribute(gemm_mma<true, true, false, false>,
                         cudaFuncAttributeMaxDynamicSharedMemorySize, GSMEM);
    cudaFuncSetAttribute(gemm_mma<false, false, false, true>,
                         cudaFuncAttributeMaxDynamicSharedMemorySize, GSMEM);

    float *pypre, *pvkp, *pz;
    __nv_bfloat16 *pythi, *pytlo, *pathi, *patlo;
    __nv_bfloat16 *pkhi, *pklo, *pvhi, *pvlo, *pqthi, *pqtlo, *pxthi, *pxtlo;
    __nv_bfloat16 *pothi, *potlo, *pvkhi, *pvklo, *pwqhi, *pwqlo, *ppwhi, *ppwlo;
    cudaGetSymbolAddress((void**)&pythi, g_ythi);
    cudaGetSymbolAddress((void**)&pytlo, g_ytlo);
    cudaGetSymbolAddress((void**)&pathi, g_athi);
    cudaGetSymbolAddress((void**)&patlo, g_atlo);
    cudaGetSymbolAddress((void**)&pypre, g_ypre);
    cudaGetSymbolAddress((void**)&pvkp,  g_vkp);
    cudaGetSymbolAddress((void**)&pz,    g_z);
    cudaGetSymbolAddress((void**)&pkhi,  g_khi);
    cudaGetSymbolAddress((void**)&pklo,  g_klo);
    cudaGetSymbolAddress((void**)&pvhi,  g_vhi);
    cudaGetSymbolAddress((void**)&pvlo,  g_vlo);
    cudaGetSymbolAddress((void**)&pqthi, g_qthi);
    cudaGetSymbolAddress((void**)&pqtlo, g_qtlo);
    cudaGetSymbolAddress((void**)&pxthi, g_xthi);
    cudaGetSymbolAddress((void**)&pxtlo, g_xtlo);
    cudaGetSymbolAddress((void**)&pothi, g_othi);
    cudaGetSymbolAddress((void**)&potlo, g_otlo);
    cudaGetSymbolAddress((void**)&pvkhi, g_vkhi);
    cudaGetSymbolAddress((void**)&pvklo, g_vklo);
    cudaGetSymbolAddress((void**)&pwqhi, g_wqhi);
    cudaGetSymbolAddress((void**)&pwqlo, g_wqlo);
    cudaGetSymbolAddress((void**)&ppwhi, g_pwhi);
    cudaGetSymbolAddress((void**)&ppwlo, g_pwlo);

    const long long sQKV = (long long)DIM * NPIX;   // 2097152
    const long long sYT  = (long long)NPIX * C4;    // 8388608
    const long long sVK  = (long long)DIM * DIM;    // 262144

    zero_kernel<<<32, 256>>>();
    convert_split<<<4096, 256>>>(qkvg_w, pwqhi, pwqlo, C4 * DIM);
    convert_split<<<1024, 256>>>(proj_w, ppwhi, ppwlo, DIM * DIM);
    transpose_split<<<dim3(128, 16, BATCH), dim3(32, 8)>>>(x, pxthi, pxtlo, DIM, NPIX);

    // 1) y^T = x^T @ w^T -> bf16 hi/lo + fused BN1 column stats
    gemm_mma<false, true, true, false><<<dim3(16, 32, BATCH), 128, GSMEM>>>(
        pxthi, pxtlo, pwqhi, pwqlo, nullptr, pythi, pytlo,
        2048, 512, 512, 1, sQKV, 0, sYT, 1.f, nullptr);

    // 2) BN1 finalize
    bn1_finalize<<<8, 256>>>(qkvg_gamma, qkvg_beta);

    // 3) q^T hi/lo; k,v -> [d][n] hi/lo + ksum
    q_kernel<<<16384, 256>>>();
    kvt_kernel<<<dim3(64, 8, BATCH), dim3(32, 8)>>>();

    // 4) z
    z_kernel<<<4096, 256>>>();

    // 5) vk = v @ k^T, split-K x4; reduce -> hi/lo bf16
    gemm_mma<false, false, false, false><<<dim3(4, 4, BATCH * 4), 128, GSMEM>>>(
        pvhi, pvlo, pkhi, pklo, pvkp, nullptr, nullptr,
        512, 1024, 4096, 4, sQKV, sQKV, sVK, 1.f, nullptr);
    vkred_kernel<<<2048, 256>>>();

    // 6) attn^T = q^T @ vk^T / z -> hi/lo bf16
    gemm_mma<true, true, false, false><<<dim3(4, 32, BATCH), 128, GSMEM>>>(
        pqthi, pqtlo, pvkhi, pvklo, nullptr, pathi, patlo,
        512, 512, 512, 1, sQKV, sVK, sQKV, 1.f, pz);

    // 7) RMSNorm + gate -> o^T hi/lo
    rmsgate_kernel<<<32768, 128>>>(attn_norm_w);

    // 8) ypre = proj_w @ o + fused BN2 row stats
    gemm_mma<false, false, false, true><<<dim3(32, 4, BATCH), 128, GSMEM>>>(
        ppwhi, ppwlo, pothi, potlo, pypre, nullptr, nullptr,
        4096, 512, 512, 1, 0, sQKV, sQKV, 1.f, nullptr);

    // 9) BN2 finalize + apply
    bn2_finalize<<<2, 256>>>(proj_gamma, proj_beta);
    bnapply_kernel<<<16384, 256>>>(out);
}

// round 10
// speedup vs baseline: 1.1615x; 1.1615x over previous
#include <cuda_runtime.h>
#include <cuda_bf16.h>
#include <math.h>
#include <stdint.h>

// ---------------------------------------------------------------------------
// SHMA block: mma.sync bf16 GEMMs, fused 3-term hi/lo segments (R8 core),
// BN1 stats fused in GEMM1, BN2 stats fused in proj GEMM.
// B=8, dim=d=512, N=4096, qkvg=2048.
// ---------------------------------------------------------------------------

#define BATCH 8
#define DIM   512
#define NPIX  4096
#define C4    2048

// ---------------- scratch (static device globals) --------------------------
__device__ __nv_bfloat16 g_ythi[67108864], g_ytlo[67108864]; // y^T (8*4096,2048)
__device__ __nv_bfloat16 g_athi[16777216], g_atlo[16777216]; // attn^T (8*4096,512)
__device__ float g_ypre[16777216];                   // ypre (8, 512, 4096) f32
__device__ float g_vkp[8388608];                     // vk split-K partials
__device__ __nv_bfloat16 g_khi[16777216], g_klo[16777216];   // k [b][d][n]
__device__ __nv_bfloat16 g_vhi[16777216], g_vlo[16777216];   // v [b][d][n]
__device__ __nv_bfloat16 g_qthi[16777216], g_qtlo[16777216]; // q^T [b][n][d]
__device__ __nv_bfloat16 g_xthi[16777216], g_xtlo[16777216]; // x^T [b][n][c]
__device__ __nv_bfloat16 g_othi[16777216], g_otlo[16777216]; // o^T [b][n][d]
__device__ __nv_bfloat16 g_vkhi[2097152], g_vklo[2097152];   // vk [b][d][e]
__device__ __nv_bfloat16 g_wqhi[1048576], g_wqlo[1048576];   // qkvg_w
__device__ __nv_bfloat16 g_pwhi[262144],  g_pwlo[262144];    // proj_w
__device__ float g_a1[2048], g_b1[2048], g_a2[512], g_b2[512];
__device__ float g_s1[2048], g_s2[2048];             // BN1 accum
__device__ float g_t1[512], g_t2[512];               // BN2 accum
__device__ float g_ksum[4096], g_z[32768];

// ---------------- helpers ---------------------------------------------------
__device__ __forceinline__ uint32_t smem_u32(const void* p) {
    uint32_t a;
    asm("{ .reg .u64 t; cvta.to.shared.u64 t, %1; cvt.u32.u64 %0, t; }"
        : "=r"(a) : "l"(p));
    return a;
}
__device__ __forceinline__ void ldsm_x4(uint32_t& r0, uint32_t& r1,
                                        uint32_t& r2, uint32_t& r3,
                                        uint32_t addr) {
    asm volatile("ldmatrix.sync.aligned.m8n8.x4.shared.b16 {%0,%1,%2,%3}, [%4];"
                 : "=r"(r0), "=r"(r1), "=r"(r2), "=r"(r3) : "r"(addr));
}
__device__ __forceinline__ void mma16816(float* c, const uint32_t* a,
                                         uint32_t b0, uint32_t b1) {
    asm volatile(
        "mma.sync.aligned.m16n8k16.row.col.f32.bf16.bf16.f32 "
        "{%0,%1,%2,%3}, {%4,%5,%6,%7}, {%8,%9}, {%0,%1,%2,%3};"
        : "+f"(c[0]), "+f"(c[1]), "+f"(c[2]), "+f"(c[3])
        : "r"(a[0]), "r"(a[1]), "r"(a[2]), "r"(a[3]), "r"(b0), "r"(b1));
}
__device__ __forceinline__ void cpasync16(uint32_t dst, const void* src) {
    asm volatile("cp.async.cg.shared.global [%0], [%1], 16;"
                 :: "r"(dst), "l"(src));
}
#define CP_COMMIT() asm volatile("cp.async.commit_group;" ::: "memory")
#define CP_WAIT(n)  asm volatile("cp.async.wait_group %0;" :: "n"(n) : "memory")

__device__ __forceinline__ __nv_bfloat162 split_hi2(float a, float b,
                                                    __nv_bfloat162& lo) {
    __nv_bfloat16 h0 = __float2bfloat16(a), h1 = __float2bfloat16(b);
    lo = __halves2bfloat162(__float2bfloat16(a - __bfloat162float(h0)),
                            __float2bfloat16(b - __bfloat162float(h1)));
    return __halves2bfloat162(h0, h1);
}

// ---------------------------------------------------------------------------
// mma.sync GEMM, fused 3-segment hi/lo: per 32-wide K-chunk all four tiles
// (Ah, Al, Bh, Bl) staged; Ah fragments reused for seg2, Bh for seg3.
// 128x128 CTA tile, BK=32, 128 threads (2x2 warps, 64x64 warp tiles),
// 2-stage cp.async double buffer, padded smem (SROW=40, conflict-free).
// Split-K via blockIdx.z = b*kchunks + ks (f32 C offset by zi*sC).
// ZDIV: row-divide by zb. OUTSPLIT: hi/lo bf16 out.
// STATS: per-column sum/sumsq atomics (g_s1/g_s2).
// ROWSTATS: per-row sum/sumsq atomics (g_t1/g_t2).
// ---------------------------------------------------------------------------
#define SROW 40
#define BUFB (128 * SROW * 2)          // 10240 B per operand tile
#define STAGEB (4 * BUFB)              // Ah, Al, Bh, Bl
#define GSMEM (2 * STAGEB + 512)       // 2 stages + zsm

template <bool ZDIV, bool OUTSPLIT, bool STATS, bool ROWSTATS>
__global__ void __launch_bounds__(128)
gemm_mma(const __nv_bfloat16* __restrict__ Ahi_, const __nv_bfloat16* __restrict__ Alo_,
         const __nv_bfloat16* __restrict__ Bhi_, const __nv_bfloat16* __restrict__ Blo_,
         float* __restrict__ C_, __nv_bfloat16* __restrict__ Chi_,
         __nv_bfloat16* __restrict__ Clo_,
         int N, int K, int ldk, int kchunks,
         long long sA, long long sB, long long sC,
         float alpha, const float* __restrict__ zb)
{
    extern __shared__ char smem[];
    const int zi = blockIdx.z;
    const int b  = zi / kchunks;
    const int ks = zi - b * kchunks;
    const long long koff = (long long)ks * K;

    const __nv_bfloat16* Ah = Ahi_ + (long long)b * sA + koff;
    const __nv_bfloat16* Al = Alo_ + (long long)b * sA + koff;
    const __nv_bfloat16* Bh = Bhi_ + (long long)b * sB + koff;
    const __nv_bfloat16* Bl = Blo_ + (long long)b * sB + koff;
    const int m0 = blockIdx.y << 7, n0 = blockIdx.x << 7;
    const int tid = threadIdx.x, wid = tid >> 5, lane = tid & 31;
    const int wm = wid & 1, wn = wid >> 1;
    const int tig = lane & 3, grp = lane >> 2;

    const uint32_t sb = smem_u32(smem);
    float* zsm = (float*)(smem + 2 * STAGEB);
    if (ZDIV) zsm[tid] = 1.f / zb[(long long)b * 4096 + m0 + tid];

    const int CH = K >> 5;

    float acc[4][8][4];
#pragma unroll
    for (int i = 0; i < 4; i++)
#pragma unroll
        for (int j = 0; j < 8; j++)
#pragma unroll
            for (int t = 0; t < 4; t++) acc[i][j][t] = 0.f;

    // load all 4 operand tiles for K-chunk c into stage st
    auto load = [&](int c, int st) {
        long long kp = (long long)c << 5;
        uint32_t base = sb + (uint32_t)st * STAGEB;
#pragma unroll
        for (int i = 0; i < 4; i++) {
            int slot = tid + (i << 7);
            int row = slot >> 2, u = slot & 3;
            uint32_t d = (uint32_t)(row * (SROW * 2) + (u << 4));
            long long aoff = (long long)(m0 + row) * ldk + kp + (u << 3);
            long long boff = (long long)(n0 + row) * ldk + kp + (u << 3);
            cpasync16(base + d, Ah + aoff);
            cpasync16(base + BUFB + d, Al + aoff);
            cpasync16(base + 2 * BUFB + d, Bh + boff);
            cpasync16(base + 3 * BUFB + d, Bl + boff);
        }
        CP_COMMIT();
    };

    load(0, 0);

    const uint32_t lrow16 = lane & 15;
    const uint32_t lcol8 = (lane >> 4) << 3;

    int buf = 0;
    for (int c = 0; c < CH; c++) {
        if (c + 1 < CH) { load(c + 1, buf ^ 1); CP_WAIT(1); }
        else            { CP_WAIT(0); }
        __syncthreads();

        uint32_t base = sb + (uint32_t)buf * STAGEB;
#pragma unroll
        for (int ko2 = 0; ko2 < 2; ko2++) {
            const uint32_t ko = ko2 << 4;
            uint32_t ah[4][4], bh[4][4], tt[4][4];
#pragma unroll
            for (int mi = 0; mi < 4; mi++) {
                uint32_t ad = base +
                    (((wm << 6) + (mi << 4) + lrow16) * SROW + ko + lcol8) * 2;
                ldsm_x4(ah[mi][0], ah[mi][1], ah[mi][2], ah[mi][3], ad);
            }
#pragma unroll
            for (int nb = 0; nb < 4; nb++) {
                uint32_t bd = base + 2 * BUFB +
                    (((wn << 6) + (nb << 4) + lrow16) * SROW + ko + lcol8) * 2;
                ldsm_x4(bh[nb][0], bh[nb][1], bh[nb][2], bh[nb][3], bd);
            }
            // seg1: Ah * Bh
#pragma unroll
            for (int mi = 0; mi < 4; mi++)
#pragma unroll
                for (int ni = 0; ni < 8; ni++) {
                    int nb = ni >> 1, hf = ni & 1;
                    mma16816(acc[mi][ni], ah[mi], bh[nb][hf], bh[nb][hf + 2]);
                }
            // seg2: Ah * Bl (reuse ah fragments)
#pragma unroll
            for (int nb = 0; nb < 4; nb++) {
                uint32_t bd = base + 3 * BUFB +
                    (((wn << 6) + (nb << 4) + lrow16) * SROW + ko + lcol8) * 2;
                ldsm_x4(tt[nb][0], tt[nb][1], tt[nb][2], tt[nb][3], bd);
            }
#pragma unroll
            for (int mi = 0; mi < 4; mi++)
#pragma unroll
                for (int ni = 0; ni < 8; ni++) {
                    int nb = ni >> 1, hf = ni & 1;
                    mma16816(acc[mi][ni], ah[mi], tt[nb][hf], tt[nb][hf + 2]);
                }
            // seg3: Al * Bh (reuse bh fragments)
#pragma unroll
            for (int mi = 0; mi < 4; mi++) {
                uint32_t ad = base + BUFB +
                    (((wm << 6) + (mi << 4) + lrow16) * SROW + ko + lcol8) * 2;
                ldsm_x4(tt[mi][0], tt[mi][1], tt[mi][2], tt[mi][3], ad);
            }
#pragma unroll
            for (int mi = 0; mi < 4; mi++)
#pragma unroll
                for (int ni = 0; ni < 8; ni++) {
                    int nb = ni >> 1, hf = ni & 1;
                    mma16816(acc[mi][ni], tt[mi], bh[nb][hf], bh[nb][hf + 2]);
                }
        }
        __syncthreads();
        buf ^= 1;
    }

    // epilogue
    float* C = C_ + (long long)zi * sC;
    __nv_bfloat16* Chi = Chi_ + (long long)b * sC;
    __nv_bfloat16* Clo = Clo_ + (long long)b * sC;
    float cs1[8][2], cs2[8][2];
    float rs1[4][2], rs2[4][2];
    if (STATS) {
#pragma unroll
        for (int ni = 0; ni < 8; ni++) {
            cs1[ni][0] = cs1[ni][1] = 0.f;
            cs2[ni][0] = cs2[ni][1] = 0.f;
        }
    }
    if (ROWSTATS) {
#pragma unroll
        for (int mi = 0; mi < 4; mi++) {
            rs1[mi][0] = rs1[mi][1] = 0.f;
            rs2[mi][0] = rs2[mi][1] = 0.f;
        }
    }
#pragma unroll
    for (int mi = 0; mi < 4; mi++) {
        int rl = (wm << 6) + (mi << 4) + grp;
        int row = m0 + rl;
        float zr0 = 1.f, zr1 = 1.f;
        if (ZDIV) { zr0 = zsm[rl]; zr1 = zsm[rl + 8]; }
#pragma unroll
        for (int ni = 0; ni < 8; ni++) {
            int col = n0 + (wn << 6) + (ni << 3) + (tig << 1);
            float v0 = acc[mi][ni][0] * alpha;
            float v1 = acc[mi][ni][1] * alpha;
            float v2 = acc[mi][ni][2] * alpha;
            float v3 = acc[mi][ni][3] * alpha;
            if (ZDIV) { v0 *= zr0; v1 *= zr0; v2 *= zr1; v3 *= zr1; }
            if (STATS) {
                cs1[ni][0] += v0 + v2;
                cs1[ni][1] += v1 + v3;
                cs2[ni][0] += v0 * v0 + v2 * v2;
                cs2[ni][1] += v1 * v1 + v3 * v3;
            }
            if (ROWSTATS) {
                rs1[mi][0] += v0 + v1;
                rs2[mi][0] += v0 * v0 + v1 * v1;
                rs1[mi][1] += v2 + v3;
                rs2[mi][1] += v2 * v2 + v3 * v3;
            }
            if (OUTSPLIT) {
                __nv_bfloat162 l0, l1;
                __nv_bfloat162 h0 = split_hi2(v0, v1, l0);
                __nv_bfloat162 h1 = split_hi2(v2, v3, l1);
                *(__nv_bfloat162*)(Chi + (long long)row * N + col) = h0;
                *(__nv_bfloat162*)(Chi + (long long)(row + 8) * N + col) = h1;
                *(__nv_bfloat162*)(Clo + (long long)row * N + col) = l0;
                *(__nv_bfloat162*)(Clo + (long long)(row + 8) * N + col) = l1;
            } else {
                float2 p0; p0.x = v0; p0.y = v1;
                float2 p1; p1.x = v2; p1.y = v3;
                *(float2*)(C + (long long)row * N + col) = p0;
                *(float2*)(C + (long long)(row + 8) * N + col) = p1;
            }
        }
    }
    if (STATS) {
#pragma unroll
        for (int ni = 0; ni < 8; ni++)
#pragma unroll
            for (int h = 0; h < 2; h++) {
                float s1 = cs1[ni][h], s2 = cs2[ni][h];
                s1 += __shfl_down_sync(0xffffffffu, s1, 16);
                s2 += __shfl_down_sync(0xffffffffu, s2, 16);
                s1 += __shfl_down_sync(0xffffffffu, s1, 8);
                s2 += __shfl_down_sync(0xffffffffu, s2, 8);
                s1 += __shfl_down_sync(0xffffffffu, s1, 4);
                s2 += __shfl_down_sync(0xffffffffu, s2, 4);
                if (lane < 4) {
                    int col = n0 + (wn << 6) + (ni << 3) + (lane << 1) + h;
                    atomicAdd(&g_s1[col], s1);
                    atomicAdd(&g_s2[col], s2);
                }
            }
    }
    if (ROWSTATS) {
#pragma unroll
        for (int mi = 0; mi < 4; mi++)
#pragma unroll
            for (int h = 0; h < 2; h++) {
                float s1 = rs1[mi][h], s2 = rs2[mi][h];
                s1 += __shfl_down_sync(0xffffffffu, s1, 2, 4);
                s2 += __shfl_down_sync(0xffffffffu, s2, 2, 4);
                s1 += __shfl_down_sync(0xffffffffu, s1, 1, 4);
                s2 += __shfl_down_sync(0xffffffffu, s2, 1, 4);
                if (tig == 0) {
                    int row = m0 + (wm << 6) + (mi << 4) + grp + (h << 3);
                    atomicAdd(&g_t1[row], s1);
                    atomicAdd(&g_t2[row], s2);
                }
            }
    }
}

// ---------------------------------------------------------------------------
// vk split-K reduce -> hi/lo bf16 with alpha
// ---------------------------------------------------------------------------
__global__ void vkred_kernel()
{
    long long i4 = (long long)(blockIdx.x * 256 + threadIdx.x) * 4;
    int b = (int)(i4 >> 18);
    long long off = i4 & 262143;
    const float* p = g_vkp + ((long long)b * 4) * 262144 + off;
    float4 s0 = *(const float4*)p;
    float4 s1 = *(const float4*)(p + 262144);
    float4 s2 = *(const float4*)(p + 2 * 262144);
    float4 s3 = *(const float4*)(p + 3 * 262144);
    const float al = 1.f / 4096.f;
    float v0 = ((s0.x + s1.x) + (s2.x + s3.x)) * al;
    float v1 = ((s0.y + s1.y) + (s2.y + s3.y)) * al;
    float v2 = ((s0.z + s1.z) + (s2.z + s3.z)) * al;
    float v3 = ((s0.w + s1.w) + (s2.w + s3.w)) * al;
    __nv_bfloat162 l0, l1;
    __nv_bfloat162 h0 = split_hi2(v0, v1, l0);
    __nv_bfloat162 h1 = split_hi2(v2, v3, l1);
    *(__nv_bfloat162*)(g_vkhi + i4)     = h0;
    *(__nv_bfloat162*)(g_vkhi + i4 + 2) = h1;
    *(__nv_bfloat162*)(g_vklo + i4)     = l0;
    *(__nv_bfloat162*)(g_vklo + i4 + 2) = l1;
}

// ---------------------------------------------------------------------------
__global__ void zero_kernel()
{
    int i = blockIdx.x * 256 + threadIdx.x;
    if (i < 2048) { g_s1[i] = 0.f; g_s2[i] = 0.f; }
    if (i < 512)  { g_t1[i] = 0.f; g_t2[i] = 0.f; }
    if (i < 4096) g_ksum[i] = 0.f;
}

__global__ void bn1_finalize(const float* __restrict__ gamma,
                             const float* __restrict__ beta)
{
    int c = blockIdx.x * 256 + threadIdx.x;
    const float inv = 1.f / (BATCH * NPIX);
    float mean = g_s1[c] * inv;
    float var = g_s2[c] * inv - mean * mean;
    float av = gamma[c] * rsqrtf(var + 1e-5f);
    g_a1[c] = av;
    g_b1[c] = beta[c] - mean * av;
}

__global__ void bn2_finalize(const float* __restrict__ gamma,
                             const float* __restrict__ beta)
{
    int c = blockIdx.x * 256 + threadIdx.x;
    const float inv = 1.f / (BATCH * NPIX);
    float mean = g_t1[c] * inv;
    float var = g_t2[c] * inv - mean * mean;
    float av = gamma[c] * rsqrtf(var + 1e-5f);
    g_a2[c] = av;
    g_b2[c] = beta[c] - mean * av;
}

// q: sigmoid(affine(y[:, 0:512])) -> q^T hi/lo bf16
__global__ void q_kernel()
{
    int i = blockIdx.x * 256 + threadIdx.x;
    int r = i >> 7;
    int dg = (i & 127) << 2;
    long long yb = (long long)r * C4 + dg;
    __nv_bfloat162 yh0 = *(const __nv_bfloat162*)(g_ythi + yb);
    __nv_bfloat162 yh1 = *(const __nv_bfloat162*)(g_ythi + yb + 2);
    __nv_bfloat162 yl0 = *(const __nv_bfloat162*)(g_ytlo + yb);
    __nv_bfloat162 yl1 = *(const __nv_bfloat162*)(g_ytlo + yb + 2);
    float4 a4 = *(const float4*)(g_a1 + dg);
    float4 b4 = *(const float4*)(g_b1 + dg);
    float y0 = __bfloat162float(yh0.x) + __bfloat162float(yl0.x);
    float y1 = __bfloat162float(yh0.y) + __bfloat162float(yl0.y);
    float y2 = __bfloat162float(yh1.x) + __bfloat162float(yl1.x);
    float y3 = __bfloat162float(yh1.y) + __bfloat162float(yl1.y);
    float q0 = 1.f / (1.f + expf(-(a4.x * y0 + b4.x)));
    float q1 = 1.f / (1.f + expf(-(a4.y * y1 + b4.y)));
    float q2 = 1.f / (1.f + expf(-(a4.z * y2 + b4.z)));
    float q3 = 1.f / (1.f + expf(-(a4.w * y3 + b4.w)));
    __nv_bfloat162 l0, l1;
    __nv_bfloat162 h0 = split_hi2(q0, q1, l0);
    __nv_bfloat162 h1 = split_hi2(q2, q3, l1);
    long long o = (long long)r * DIM + dg;
    *(__nv_bfloat162*)(g_qthi + o)     = h0;
    *(__nv_bfloat162*)(g_qthi + o + 2) = h1;
    *(__nv_bfloat162*)(g_qtlo + o)     = l0;
    *(__nv_bfloat162*)(g_qtlo + o + 2) = l1;
}

// k,v: 64x64 transpose y^T -> [b][d][n] hi/lo bf16, sigmoid/affine, ksum
__global__ void kvt_kernel()
{
    __shared__ float tk[64][65], tv[64][65];
    int bz = blockIdx.z;
    int n0 = blockIdx.x << 6, d0 = blockIdx.y << 6;
    int tx = threadIdx.x, ty = threadIdx.y;
    int dloc = tx << 1;
    float2 akp = *(const float2*)(g_a1 + 512 + d0 + dloc);
    float2 bkp = *(const float2*)(g_b1 + 512 + d0 + dloc);
    float2 avp = *(const float2*)(g_a1 + 1024 + d0 + dloc);
    float2 bvp = *(const float2*)(g_b1 + 1024 + d0 + dloc);
#pragma unroll
    for (int i = 0; i < 8; i++) {
        int nl = ty + (i << 3);
        long long rb = ((long long)(bz << 12) + n0 + nl) * C4;
        __nv_bfloat162 kh2 = *(const __nv_bfloat162*)(g_ythi + rb + 512 + d0 + dloc);
        __nv_bfloat162 kl2 = *(const __nv_bfloat162*)(g_ytlo + rb + 512 + d0 + dloc);
        __nv_bfloat162 vh2 = *(const __nv_bfloat162*)(g_ythi + rb + 1024 + d0 + dloc);
        __nv_bfloat162 vl2 = *(const __nv_bfloat162*)(g_ytlo + rb + 1024 + d0 + dloc);
        float k0 = __bfloat162float(kh2.x) + __bfloat162float(kl2.x);
        float k1 = __bfloat162float(kh2.y) + __bfloat162float(kl2.y);
        float v0 = __bfloat162float(vh2.x) + __bfloat162float(vl2.x);
        float v1 = __bfloat162float(vh2.y) + __bfloat162float(vl2.y);
        tk[nl][dloc]     = 1.f / (1.f + expf(-(akp.x * k0 + bkp.x)));
        tk[nl][dloc + 1] = 1.f / (1.f + expf(-(akp.y * k1 + bkp.y)));
        tv[nl][dloc]     = avp.x * v0 + bvp.x;
        tv[nl][dloc + 1] = avp.y * v1 + bvp.y;
    }
    __syncthreads();
#pragma unroll
    for (int i = 0; i < 8; i++) {
        int dl = ty + (i << 3);
        int d = d0 + dl;
        int nl = tx << 1;
        float k0 = tk[nl][dl], k1 = tk[nl + 1][dl];
        float v0 = tv[nl][dl], v1 = tv[nl + 1][dl];
        long long o = ((long long)(bz << 9) + d) * NPIX + n0 + nl;
        __nv_bfloat162 kl2, vl2;
        __nv_bfloat162 kh2 = split_hi2(k0, k1, kl2);
        __nv_bfloat162 vh2 = split_hi2(v0, v1, vl2);
        *(__nv_bfloat162*)(g_khi + o) = kh2;
        *(__nv_bfloat162*)(g_klo + o) = kl2;
        *(__nv_bfloat162*)(g_vhi + o) = vh2;
        *(__nv_bfloat162*)(g_vlo + o) = vl2;
        float s = k0 + k1;
#pragma unroll
        for (int off = 16; off > 0; off >>= 1)
            s += __shfl_down_sync(0xffffffffu, s, off);
        if (tx == 0) atomicAdd(&g_ksum[(bz << 9) + d], s);
    }
}

// z[r] = sum_d kmean[d] * q[r][d] + eps
__global__ void z_kernel()
{
    __shared__ float km[512];
    int r0 = blockIdx.x << 3;
    int bb = r0 >> 12;
    for (int i = threadIdx.x; i < 512; i += 256)
        km[i] = g_ksum[(bb << 9) + i] * (1.f / NPIX);
    __syncthreads();
    int w = threadIdx.x >> 5, lane = threadIdx.x & 31;
    int r = r0 + w;
    const __nv_bfloat16* qh = g_qthi + (long long)r * DIM;
    const __nv_bfloat16* ql = g_qtlo + (long long)r * DIM;
    float s = 0.f;
#pragma unroll
    for (int i = 0; i < 16; i++) {
        int d = lane + (i << 5);
        s += km[d] * (__bfloat162float(qh[d]) + __bfloat162float(ql[d]));
    }
#pragma unroll
    for (int off = 16; off > 0; off >>= 1)
        s += __shfl_down_sync(0xffffffffu, s, off);
    if (lane == 0) g_z[r] = s + 5e-4f;
}

// RMSNorm row + anw + SiLU(gate) -> o^T hi/lo
__global__ void rmsgate_kernel(const float* __restrict__ anw)
{
    __shared__ float red[4];
    int r = blockIdx.x;
    int t = threadIdx.x;
    int dg = t << 2;
    long long arow = (long long)r * DIM + dg;
    __nv_bfloat162 ah0 = *(const __nv_bfloat162*)(g_athi + arow);
    __nv_bfloat162 ah1 = *(const __nv_bfloat162*)(g_athi + arow + 2);
    __nv_bfloat162 al0 = *(const __nv_bfloat162*)(g_atlo + arow);
    __nv_bfloat162 al1 = *(const __nv_bfloat162*)(g_atlo + arow + 2);
    float a0 = __bfloat162float(ah0.x) + __bfloat162float(al0.x);
    float a1 = __bfloat162float(ah0.y) + __bfloat162float(al0.y);
    float a2 = __bfloat162float(ah1.x) + __bfloat162float(al1.x);
    float a3 = __bfloat162float(ah1.y) + __bfloat162float(al1.y);
    float ss = a0 * a0 + a1 * a1 + a2 * a2 + a3 * a3;
    int lane = t & 31, w = t >> 5;
#pragma unroll
    for (int off = 16; off > 0; off >>= 1)
        ss += __shfl_down_sync(0xffffffffu, ss, off);
    if (lane == 0) red[w] = ss;
    __syncthreads();
    float tot = red[0] + red[1] + red[2] + red[3];
    float rms = rsqrtf(tot * (1.f / DIM) + 1e-6f);

    long long grow = (long long)r * C4 + 1536 + dg;
    __nv_bfloat162 gh0 = *(const __nv_bfloat162*)(g_ythi + grow);
    __nv_bfloat162 gh1 = *(const __nv_bfloat162*)(g_ythi + grow + 2);
    __nv_bfloat162 gl0 = *(const __nv_bfloat162*)(g_ytlo + grow);
    __nv_bfloat162 gl1 = *(const __nv_bfloat162*)(g_ytlo + grow + 2);
    float yg0 = __bfloat162float(gh0.x) + __bfloat162float(gl0.x);
    float yg1 = __bfloat162float(gh0.y) + __bfloat162float(gl0.y);
    float yg2 = __bfloat162float(gh1.x) + __bfloat162float(gl1.x);
    float yg3 = __bfloat162float(gh1.y) + __bfloat162float(gl1.y);
    float4 ga = *(const float4*)(g_a1 + 1536 + dg);
    float4 gb = *(const float4*)(g_b1 + 1536 + dg);
    float4 wn = *(const float4*)(anw + dg);
    float g0 = ga.x * yg0 + gb.x, g1 = ga.y * yg1 + gb.y;
    float g2 = ga.z * yg2 + gb.z, g3 = ga.w * yg3 + gb.w;
    float o0 = a0 * rms * wn.x * (g0 / (1.f + expf(-g0)));
    float o1 = a1 * rms * wn.y * (g1 / (1.f + expf(-g1)));
    float o2 = a2 * rms * wn.z * (g2 / (1.f + expf(-g2)));
    float o3 = a3 * rms * wn.w * (g3 / (1.f + expf(-g3)));
    __nv_bfloat162 l0, l1;
    __nv_bfloat162 h0 = split_hi2(o0, o1, l0);
    __nv_bfloat162 h1 = split_hi2(o2, o3, l1);
    long long o = (long long)r * DIM + dg;
    *(__nv_bfloat162*)(g_othi + o)     = h0;
    *(__nv_bfloat162*)(g_othi + o + 2) = h1;
    *(__nv_bfloat162*)(g_otlo + o)     = l0;
    *(__nv_bfloat162*)(g_otlo + o + 2) = l1;
}

__global__ void bnapply_kernel(float* __restrict__ out)
{
    long long i = (long long)(blockIdx.x * blockDim.x + threadIdx.x) * 4;
    int c = (int)((i >> 12) & 511);
    float a = g_a2[c], bb = g_b2[c];
    float4 v = *reinterpret_cast<const float4*>(g_ypre + i);
    v.x = a * v.x + bb; v.y = a * v.y + bb;
    v.z = a * v.z + bb; v.w = a * v.w + bb;
    *reinterpret_cast<float4*>(out + i) = v;
}

__global__ void convert_split(const float* __restrict__ s,
                              __nv_bfloat16* __restrict__ hi,
                              __nv_bfloat16* __restrict__ lo, int n)
{
    int i = blockIdx.x * blockDim.x + threadIdx.x;
    if (i < n) {
        float v = s[i];
        __nv_bfloat16 h = __float2bfloat16(v);
        hi[i] = h;
        lo[i] = __float2bfloat16(v - __bfloat162float(h));
    }
}

__global__ void transpose_split(const float* __restrict__ src,
                                __nv_bfloat16* __restrict__ dhi,
                                __nv_bfloat16* __restrict__ dlo, int R, int Cc)
{
    __shared__ float t[32][33];
    int b = blockIdx.z;
    long long o = (long long)b * R * Cc;
    src += o; dhi += o; dlo += o;
    int c0 = blockIdx.x * 32, r0 = blockIdx.y * 32;
    int tx = threadIdx.x, ty = threadIdx.y;
#pragma unroll
    for (int i = 0; i < 4; i++)
        t[ty + 8 * i][tx] = src[(long long)(r0 + ty + 8 * i) * Cc + c0 + tx];
    __syncthreads();
#pragma unroll
    for (int i = 0; i < 4; i++) {
        int cc = c0 + ty + 8 * i;
        float v = t[tx][ty + 8 * i];
        __nv_bfloat16 h = __float2bfloat16(v);
        dhi[(long long)cc * R + r0 + tx] = h;
        dlo[(long long)cc * R + r0 + tx] = __float2bfloat16(v - __bfloat162float(h));
    }
}

// ---------------------------------------------------------------------------
extern "C" void kernel_launch(void* const* d_in, const int* in_sizes, int n_in,
                              void* d_out, int out_size)
{
    const float* x           = (const float*)d_in[0];
    const float* qkvg_w      = (const float*)d_in[1];
    const float* qkvg_gamma  = (const float*)d_in[2];
    const float* qkvg_beta   = (const float*)d_in[3];
    const float* attn_norm_w = (const float*)d_in[4];
    const float* proj_w      = (const float*)d_in[5];
    const float* proj_gamma  = (const float*)d_in[6];
    const float* proj_beta   = (const float*)d_in[7];
    float* out = (float*)d_out;

    cudaFuncSetAttribute(gemm_mma<false, false, false, false>,
                         cudaFuncAttributeMaxDynamicSharedMemorySize, GSMEM);
    cudaFuncSetAttribute(gemm_mma<false, true, true, false>,
                         cudaFuncAttributeMaxDynamicSharedMemorySize, GSMEM);
    cudaFuncSetAttribute(gemm_mma<true, true, false, false>,
                         cudaFuncAttributeMaxDynamicSharedMemorySize, GSMEM);
    cudaFuncSetAttribute(gemm_mma<false, false, false, true>,
                         cudaFuncAttributeMaxDynamicSharedMemorySize, GSMEM);

    float *pypre, *pvkp, *pz;
    __nv_bfloat16 *pythi, *pytlo, *pathi, *patlo;
    __nv_bfloat16 *pkhi, *pklo, *pvhi, *pvlo, *pqthi, *pqtlo, *pxthi, *pxtlo;
    __nv_bfloat16 *pothi, *potlo, *pvkhi, *pvklo, *pwqhi, *pwqlo, *ppwhi, *ppwlo;
    cudaGetSymbolAddress((void**)&pythi, g_ythi);
    cudaGetSymbolAddress((void**)&pytlo, g_ytlo);
    cudaGetSymbolAddress((void**)&pathi, g_athi);
    cudaGetSymbolAddress((void**)&patlo, g_atlo);
    cudaGetSymbolAddress((void**)&pypre, g_ypre);
    cudaGetSymbolAddress((void**)&pvkp,  g_vkp);
    cudaGetSymbolAddress((void**)&pz,    g_z);
    cudaGetSymbolAddress((void**)&pkhi,  g_khi);
    cudaGetSymbolAddress((void**)&pklo,  g_klo);
    cudaGetSymbolAddress((void**)&pvhi,  g_vhi);
    cudaGetSymbolAddress((void**)&pvlo,  g_vlo);
    cudaGetSymbolAddress((void**)&pqthi, g_qthi);
    cudaGetSymbolAddress((void**)&pqtlo, g_qtlo);
    cudaGetSymbolAddress((void**)&pxthi, g_xthi);
    cudaGetSymbolAddress((void**)&pxtlo, g_xtlo);
    cudaGetSymbolAddress((void**)&pothi, g_othi);
    cudaGetSymbolAddress((void**)&potlo, g_otlo);
    cudaGetSymbolAddress((void**)&pvkhi, g_vkhi);
    cudaGetSymbolAddress((void**)&pvklo, g_vklo);
    cudaGetSymbolAddress((void**)&pwqhi, g_wqhi);
    cudaGetSymbolAddress((void**)&pwqlo, g_wqlo);
    cudaGetSymbolAddress((void**)&ppwhi, g_pwhi);
    cudaGetSymbolAddress((void**)&ppwlo, g_pwlo);

    const long long sQKV = (long long)DIM * NPIX;   // 2097152
    const long long sYT  = (long long)NPIX * C4;    // 8388608
    const long long sVK  = (long long)DIM * DIM;    // 262144

    zero_kernel<<<32, 256>>>();
    convert_split<<<4096, 256>>>(qkvg_w, pwqhi, pwqlo, C4 * DIM);
    convert_split<<<1024, 256>>>(proj_w, ppwhi, ppwlo, DIM * DIM);
    transpose_split<<<dim3(128, 16, BATCH), dim3(32, 8)>>>(x, pxthi, pxtlo, DIM, NPIX);

    // 1) y^T = x^T @ w^T -> bf16 hi/lo + fused BN1 column stats
    gemm_mma<false, true, true, false><<<dim3(16, 32, BATCH), 128, GSMEM>>>(
        pxthi, pxtlo, pwqhi, pwqlo, nullptr, pythi, pytlo,
        2048, 512, 512, 1, sQKV, 0, sYT, 1.f, nullptr);

    // 2) BN1 finalize
    bn1_finalize<<<8, 256>>>(qkvg_gamma, qkvg_beta);

    // 3) q^T hi/lo; k,v -> [d][n] hi/lo + ksum
    q_kernel<<<16384, 256>>>();
    kvt_kernel<<<dim3(64, 8, BATCH), dim3(32, 8)>>>();

    // 4) z
    z_kernel<<<4096, 256>>>();

    // 5) vk = v @ k^T, split-K x4; reduce -> hi/lo bf16
    gemm_mma<false, false, false, false><<<dim3(4, 4, BATCH * 4), 128, GSMEM>>>(
        pvhi, pvlo, pkhi, pklo, pvkp, nullptr, nullptr,
        512, 1024, 4096, 4, sQKV, sQKV, sVK, 1.f, nullptr);
    vkred_kernel<<<2048, 256>>>();

    // 6) attn^T = q^T @ vk^T / z -> hi/lo bf16
    gemm_mma<true, true, false, false><<<dim3(4, 32, BATCH), 128, GSMEM>>>(
        pqthi, pqtlo, pvkhi, pvklo, nullptr, pathi, patlo,
        512, 512, 512, 1, sQKV, sVK, sQKV, 1.f, pz);

    // 7) RMSNorm + gate -> o^T hi/lo
    rmsgate_kernel<<<32768, 128>>>(attn_norm_w);

    // 8) ypre = proj_w @ o + fused BN2 row stats
    gemm_mma<false, false, false, true><<<dim3(32, 4, BATCH), 128, GSMEM>>>(
        ppwhi, ppwlo, pothi, potlo, pypre, nullptr, nullptr,
        4096, 512, 512, 1, 0, sQKV, sQKV, 1.f, nullptr);

    // 9) BN2 finalize + apply
    bn2_finalize<<<2, 256>>>(proj_gamma, proj_beta);
    bnapply_kernel<<<16384, 256>>>(out);
}

// round 11
// speedup vs baseline: 1.5706x; 1.3522x over previous
#include <cuda_runtime.h>
#include <cuda_fp16.h>
#include <math.h>
#include <stdint.h>

// ---------------------------------------------------------------------------
// SHMA block: mma.sync fp16 GEMMs, 2-product hi/lo scheme
// (C = Ah*(Bh+Bl), A single fp16-RN, B split; err ~1.4e-4/GEMM),
// n-major dataflow, BN1/BN2 stats fused into GEMM epilogues.
// B=8, dim=d=512, N=4096, qkvg=2048.
// ---------------------------------------------------------------------------

#define BATCH 8
#define DIM   512
#define NPIX  4096
#define C4    2048

// ---------------- scratch (static device globals) --------------------------
__device__ __half g_ythi[67108864], g_ytlo[67108864]; // y^T (8*4096,2048)
__device__ __half g_athi[16777216], g_atlo[16777216]; // attn^T (8*4096,512)
__device__ float g_ypre[16777216];                    // ypre (8, 512, 4096) f32
__device__ float g_vkp[8388608];                      // vk split-K partials
__device__ __half g_khi[16777216], g_klo[16777216];   // k [b][d][n]  (B op)
__device__ __half g_vhi[16777216];                    // v [b][d][n]  (A op)
__device__ __half g_qthi[16777216];                   // q^T [b][n][d] (A op)
__device__ __half g_xthi[16777216];                   // x^T [b][n][c] (A op)
__device__ __half g_othi[16777216], g_otlo[16777216]; // o^T [b][n][d] (B op)
__device__ __half g_vkhi[2097152], g_vklo[2097152];   // vk [b][d][e] (B op)
__device__ __half g_wqhi[1048576], g_wqlo[1048576];   // qkvg_w (B op)
__device__ __half g_pwhi[262144];                     // proj_w (A op)
__device__ float g_a1[2048], g_b1[2048], g_a2[512], g_b2[512];
__device__ float g_s1[2048], g_s2[2048];              // BN1 accum
__device__ float g_t1[512], g_t2[512];                // BN2 accum
__device__ float g_ksum[4096], g_z[32768];

// ---------------- helpers ---------------------------------------------------
__device__ __forceinline__ uint32_t smem_u32(const void* p) {
    uint32_t a;
    asm("{ .reg .u64 t; cvta.to.shared.u64 t, %1; cvt.u32.u64 %0, t; }"
        : "=r"(a) : "l"(p));
    return a;
}
__device__ __forceinline__ void ldsm_x4(uint32_t& r0, uint32_t& r1,
                                        uint32_t& r2, uint32_t& r3,
                                        uint32_t addr) {
    asm volatile("ldmatrix.sync.aligned.m8n8.x4.shared.b16 {%0,%1,%2,%3}, [%4];"
                 : "=r"(r0), "=r"(r1), "=r"(r2), "=r"(r3) : "r"(addr));
}
__device__ __forceinline__ void mma16816(float* c, const uint32_t* a,
                                         uint32_t b0, uint32_t b1) {
    asm volatile(
        "mma.sync.aligned.m16n8k16.row.col.f32.f16.f16.f32 "
        "{%0,%1,%2,%3}, {%4,%5,%6,%7}, {%8,%9}, {%0,%1,%2,%3};"
        : "+f"(c[0]), "+f"(c[1]), "+f"(c[2]), "+f"(c[3])
        : "r"(a[0]), "r"(a[1]), "r"(a[2]), "r"(a[3]), "r"(b0), "r"(b1));
}
__device__ __forceinline__ void cpasync16(uint32_t dst, const void* src) {
    asm volatile("cp.async.cg.shared.global [%0], [%1], 16;"
                 :: "r"(dst), "l"(src));
}
#define CP_COMMIT() asm volatile("cp.async.commit_group;" ::: "memory")
#define CP_WAIT(n)  asm volatile("cp.async.wait_group %0;" :: "n"(n) : "memory")

// fp16 hi/lo split of a pair
__device__ __forceinline__ __half2 splith2(float a, float b, __half2& lo) {
    __half h0 = __float2half_rn(a), h1 = __float2half_rn(b);
    lo = __halves2half2(__float2half_rn(a - __half2float(h0)),
                        __float2half_rn(b - __half2float(h1)));
    return __halves2half2(h0, h1);
}
__device__ __forceinline__ __half2 h2_rn(float a, float b) {
    return __halves2half2(__float2half_rn(a), __float2half_rn(b));
}

// ---------------------------------------------------------------------------
// mma.sync fp16 GEMM, 2-product: C = alpha * Ah @ (Bh + Bl)^T.
//   Ah [M][ldk] fp16, Bh/Bl [N][ldk] fp16 (K-major rows).
//   128x128 CTA tile, BK=32, 128 threads (2x2 warps, 64x64 warp tiles),
//   3-stage cp.async pipeline, padded smem (SROW=40).
//   Split-K via blockIdx.z = b*kchunks + ks (f32 C offset by zi*sC).
//   ZDIV: row-divide by zb. OUTSPLIT: hi/lo fp16 out.
//   STATS: per-column sum/sumsq atomics (g_s1/g_s2).
//   ROWSTATS: per-row sum/sumsq atomics (g_t1/g_t2).
// ---------------------------------------------------------------------------
#define SROW 40
#define BUFB (128 * SROW * 2)          // 10240 B per operand tile
#define STAGEB (3 * BUFB)              // Ah, Bh, Bl
#define GSMEM (3 * STAGEB + 512)       // 3 stages + zsm

template <bool ZDIV, bool OUTSPLIT, bool STATS, bool ROWSTATS>
__global__ void __launch_bounds__(128)
gemm_mma(const __half* __restrict__ Ah_, const __half* __restrict__ Bhi_,
         const __half* __restrict__ Blo_,
         float* __restrict__ C_, __half* __restrict__ Chi_,
         __half* __restrict__ Clo_,
         int N, int K, int ldk, int kchunks,
         long long sA, long long sB, long long sC,
         float alpha, const float* __restrict__ zb)
{
    extern __shared__ char smem[];
    const int zi = blockIdx.z;
    const int b  = zi / kchunks;
    const int ks = zi - b * kchunks;
    const long long koff = (long long)ks * K;

    const __half* Ah = Ah_ + (long long)b * sA + koff;
    const __half* Bh = Bhi_ + (long long)b * sB + koff;
    const __half* Bl = Blo_ + (long long)b * sB + koff;
    const int m0 = blockIdx.y << 7, n0 = blockIdx.x << 7;
    const int tid = threadIdx.x, wid = tid >> 5, lane = tid & 31;
    const int wm = wid & 1, wn = wid >> 1;
    const int tig = lane & 3, grp = lane >> 2;

    const uint32_t sb = smem_u32(smem);
    float* zsm = (float*)(smem + 3 * STAGEB);
    if (ZDIV) zsm[tid] = 1.f / zb[(long long)b * 4096 + m0 + tid];

    const int CH = K >> 5;

    float acc[4][8][4];
#pragma unroll
    for (int i = 0; i < 4; i++)
#pragma unroll
        for (int j = 0; j < 8; j++)
#pragma unroll
            for (int t = 0; t < 4; t++) acc[i][j][t] = 0.f;

    // load 3 operand tiles (Ah, Bh, Bl) for K-chunk c into stage st
    auto load = [&](int c, int st) {
        long long kp = (long long)c << 5;
        uint32_t base = sb + (uint32_t)st * STAGEB;
#pragma unroll
        for (int i = 0; i < 4; i++) {
            int slot = tid + (i << 7);
            int row = slot >> 2, u = slot & 3;
            uint32_t d = (uint32_t)(row * (SROW * 2) + (u << 4));
            long long aoff = (long long)(m0 + row) * ldk + kp + (u << 3);
            long long boff = (long long)(n0 + row) * ldk + kp + (u << 3);
            cpasync16(base + d, Ah + aoff);
            cpasync16(base + BUFB + d, Bh + boff);
            cpasync16(base + 2 * BUFB + d, Bl + boff);
        }
        CP_COMMIT();
    };

    load(0, 0);
    if (CH > 1) load(1, 1);

    const uint32_t lrow16 = lane & 15;
    const uint32_t lcol8 = (lane >> 4) << 3;

    int buf = 0;
    for (int c = 0; c < CH; c++) {
        if (c + 1 < CH) { CP_WAIT(1); } else { CP_WAIT(0); }
        __syncthreads();
        if (c + 2 < CH) {
            int nb = buf + 2; if (nb >= 3) nb -= 3;
            load(c + 2, nb);
        }

        uint32_t base = sb + (uint32_t)buf * STAGEB;
#pragma unroll
        for (int ko2 = 0; ko2 < 2; ko2++) {
            const uint32_t ko = ko2 << 4;
            uint32_t ah[4][4], bb[4][4];
#pragma unroll
            for (int mi = 0; mi < 4; mi++) {
                uint32_t ad = base +
                    (((wm << 6) + (mi << 4) + lrow16) * SROW + ko + lcol8) * 2;
                ldsm_x4(ah[mi][0], ah[mi][1], ah[mi][2], ah[mi][3], ad);
            }
            // seg1: Ah * Bh
#pragma unroll
            for (int nb = 0; nb < 4; nb++) {
                uint32_t bd = base + BUFB +
                    (((wn << 6) + (nb << 4) + lrow16) * SROW + ko + lcol8) * 2;
                ldsm_x4(bb[nb][0], bb[nb][1], bb[nb][2], bb[nb][3], bd);
            }
#pragma unroll
            for (int mi = 0; mi < 4; mi++)
#pragma unroll
                for (int ni = 0; ni < 8; ni++) {
                    int nb = ni >> 1, hf = ni & 1;
                    mma16816(acc[mi][ni], ah[mi], bb[nb][hf], bb[nb][hf + 2]);
                }
            // seg2: Ah * Bl (reuse ah fragments)
#pragma unroll
            for (int nb = 0; nb < 4; nb++) {
                uint32_t bd = base + 2 * BUFB +
                    (((wn << 6) + (nb << 4) + lrow16) * SROW + ko + lcol8) * 2;
                ldsm_x4(bb[nb][0], bb[nb][1], bb[nb][2], bb[nb][3], bd);
            }
#pragma unroll
            for (int mi = 0; mi < 4; mi++)
#pragma unroll
                for (int ni = 0; ni < 8; ni++) {
                    int nb = ni >> 1, hf = ni & 1;
                    mma16816(acc[mi][ni], ah[mi], bb[nb][hf], bb[nb][hf + 2]);
                }
        }
        buf++; if (buf == 3) buf = 0;
    }

    // epilogue
    float* C = C_ + (long long)zi * sC;
    __half* Chi = Chi_ + (long long)b * sC;
    __half* Clo = Clo_ + (long long)b * sC;
    float cs1[8][2], cs2[8][2];
    float rs1[4][2], rs2[4][2];
    if (STATS) {
#pragma unroll
        for (int ni = 0; ni < 8; ni++) {
            cs1[ni][0] = cs1[ni][1] = 0.f;
            cs2[ni][0] = cs2[ni][1] = 0.f;
        }
    }
    if (ROWSTATS) {
#pragma unroll
        for (int mi = 0; mi < 4; mi++) {
            rs1[mi][0] = rs1[mi][1] = 0.f;
            rs2[mi][0] = rs2[mi][1] = 0.f;
        }
    }
#pragma unroll
    for (int mi = 0; mi < 4; mi++) {
        int rl = (wm << 6) + (mi << 4) + grp;
        int row = m0 + rl;
        float zr0 = 1.f, zr1 = 1.f;
        if (ZDIV) { zr0 = zsm[rl]; zr1 = zsm[rl + 8]; }
#pragma unroll
        for (int ni = 0; ni < 8; ni++) {
            int col = n0 + (wn << 6) + (ni << 3) + (tig << 1);
            float v0 = acc[mi][ni][0] * alpha;
            float v1 = acc[mi][ni][1] * alpha;
            float v2 = acc[mi][ni][2] * alpha;
            float v3 = acc[mi][ni][3] * alpha;
            if (ZDIV) { v0 *= zr0; v1 *= zr0; v2 *= zr1; v3 *= zr1; }
            if (STATS) {
                cs1[ni][0] += v0 + v2;
                cs1[ni][1] += v1 + v3;
                cs2[ni][0] += v0 * v0 + v2 * v2;
                cs2[ni][1] += v1 * v1 + v3 * v3;
            }
            if (ROWSTATS) {
                rs1[mi][0] += v0 + v1;
                rs2[mi][0] += v0 * v0 + v1 * v1;
                rs1[mi][1] += v2 + v3;
                rs2[mi][1] += v2 * v2 + v3 * v3;
            }
            if (OUTSPLIT) {
                __half2 l0, l1;
                __half2 h0 = splith2(v0, v1, l0);
                __half2 h1 = splith2(v2, v3, l1);
                *(__half2*)(Chi + (long long)row * N + col) = h0;
                *(__half2*)(Chi + (long long)(row + 8) * N + col) = h1;
                *(__half2*)(Clo + (long long)row * N + col) = l0;
                *(__half2*)(Clo + (long long)(row + 8) * N + col) = l1;
            } else {
                float2 p0; p0.x = v0; p0.y = v1;
                float2 p1; p1.x = v2; p1.y = v3;
                *(float2*)(C + (long long)row * N + col) = p0;
                *(float2*)(C + (long long)(row + 8) * N + col) = p1;
            }
        }
    }
    if (STATS) {
#pragma unroll
        for (int ni = 0; ni < 8; ni++)
#pragma unroll
            for (int h = 0; h < 2; h++) {
                float s1 = cs1[ni][h], s2 = cs2[ni][h];
                s1 += __shfl_down_sync(0xffffffffu, s1, 16);
                s2 += __shfl_down_sync(0xffffffffu, s2, 16);
                s1 += __shfl_down_sync(0xffffffffu, s1, 8);
                s2 += __shfl_down_sync(0xffffffffu, s2, 8);
                s1 += __shfl_down_sync(0xffffffffu, s1, 4);
                s2 += __shfl_down_sync(0xffffffffu, s2, 4);
                if (lane < 4) {
                    int col = n0 + (wn << 6) + (ni << 3) + (lane << 1) + h;
                    atomicAdd(&g_s1[col], s1);
                    atomicAdd(&g_s2[col], s2);
                }
            }
    }
    if (ROWSTATS) {
#pragma unroll
        for (int mi = 0; mi < 4; mi++)
#pragma unroll
            for (int h = 0; h < 2; h++) {
                float s1 = rs1[mi][h], s2 = rs2[mi][h];
                s1 += __shfl_down_sync(0xffffffffu, s1, 2, 4);
                s2 += __shfl_down_sync(0xffffffffu, s2, 2, 4);
                s1 += __shfl_down_sync(0xffffffffu, s1, 1, 4);
                s2 += __shfl_down_sync(0xffffffffu, s2, 1, 4);
                if (tig == 0) {
                    int row = m0 + (wm << 6) + (mi << 4) + grp + (h << 3);
                    atomicAdd(&g_t1[row], s1);
                    atomicAdd(&g_t2[row], s2);
                }
            }
    }
}

// ---------------------------------------------------------------------------
// vk split-K reduce -> hi/lo fp16 with alpha
// ---------------------------------------------------------------------------
__global__ void vkred_kernel()
{
    long long i4 = (long long)(blockIdx.x * 256 + threadIdx.x) * 4;
    int b = (int)(i4 >> 18);
    long long off = i4 & 262143;
    const float* p = g_vkp + ((long long)b * 4) * 262144 + off;
    float4 s0 = *(const float4*)p;
    float4 s1 = *(const float4*)(p + 262144);
    float4 s2 = *(const float4*)(p + 2 * 262144);
    float4 s3 = *(const float4*)(p + 3 * 262144);
    const float al = 1.f / 4096.f;
    float v0 = ((s0.x + s1.x) + (s2.x + s3.x)) * al;
    float v1 = ((s0.y + s1.y) + (s2.y + s3.y)) * al;
    float v2 = ((s0.z + s1.z) + (s2.z + s3.z)) * al;
    float v3 = ((s0.w + s1.w) + (s2.w + s3.w)) * al;
    __half2 l0, l1;
    __half2 h0 = splith2(v0, v1, l0);
    __half2 h1 = splith2(v2, v3, l1);
    *(__half2*)(g_vkhi + i4)     = h0;
    *(__half2*)(g_vkhi + i4 + 2) = h1;
    *(__half2*)(g_vklo + i4)     = l0;
    *(__half2*)(g_vklo + i4 + 2) = l1;
}

// ---------------------------------------------------------------------------
__global__ void zero_kernel()
{
    int i = blockIdx.x * 256 + threadIdx.x;
    if (i < 2048) { g_s1[i] = 0.f; g_s2[i] = 0.f; }
    if (i < 512)  { g_t1[i] = 0.f; g_t2[i] = 0.f; }
    if (i < 4096) g_ksum[i] = 0.f;
}

__global__ void bn1_finalize(const float* __restrict__ gamma,
                             const float* __restrict__ beta)
{
    int c = blockIdx.x * 256 + threadIdx.x;
    const float inv = 1.f / (BATCH * NPIX);
    float mean = g_s1[c] * inv;
    float var = g_s2[c] * inv - mean * mean;
    float av = gamma[c] * rsqrtf(var + 1e-5f);
    g_a1[c] = av;
    g_b1[c] = beta[c] - mean * av;
}

__global__ void bn2_finalize(const float* __restrict__ gamma,
                             const float* __restrict__ beta)
{
    int c = blockIdx.x * 256 + threadIdx.x;
    const float inv = 1.f / (BATCH * NPIX);
    float mean = g_t1[c] * inv;
    float var = g_t2[c] * inv - mean * mean;
    float av = gamma[c] * rsqrtf(var + 1e-5f);
    g_a2[c] = av;
    g_b2[c] = beta[c] - mean * av;
}

// q: sigmoid(affine(y[:, 0:512])) -> q^T fp16 (hi only; A operand)
__global__ void q_kernel()
{
    int i = blockIdx.x * 256 + threadIdx.x;
    int r = i >> 7;
    int dg = (i & 127) << 2;
    long long yb = (long long)r * C4 + dg;
    __half2 yh0 = *(const __half2*)(g_ythi + yb);
    __half2 yh1 = *(const __half2*)(g_ythi + yb + 2);
    __half2 yl0 = *(const __half2*)(g_ytlo + yb);
    __half2 yl1 = *(const __half2*)(g_ytlo + yb + 2);
    float4 a4 = *(const float4*)(g_a1 + dg);
    float4 b4 = *(const float4*)(g_b1 + dg);
    float y0 = __half2float(yh0.x) + __half2float(yl0.x);
    float y1 = __half2float(yh0.y) + __half2float(yl0.y);
    float y2 = __half2float(yh1.x) + __half2float(yl1.x);
    float y3 = __half2float(yh1.y) + __half2float(yl1.y);
    float q0 = 1.f / (1.f + expf(-(a4.x * y0 + b4.x)));
    float q1 = 1.f / (1.f + expf(-(a4.y * y1 + b4.y)));
    float q2 = 1.f / (1.f + expf(-(a4.z * y2 + b4.z)));
    float q3 = 1.f / (1.f + expf(-(a4.w * y3 + b4.w)));
    long long o = (long long)r * DIM + dg;
    *(__half2*)(g_qthi + o)     = h2_rn(q0, q1);
    *(__half2*)(g_qthi + o + 2) = h2_rn(q2, q3);
}

// k,v: 64x64 transpose y^T -> [b][d][n]; k hi/lo fp16, v hi fp16, ksum
__global__ void kvt_kernel()
{
    __shared__ float tk[64][65], tv[64][65];
    int bz = blockIdx.z;
    int n0 = blockIdx.x << 6, d0 = blockIdx.y << 6;
    int tx = threadIdx.x, ty = threadIdx.y;
    int dloc = tx << 1;
    float2 akp = *(const float2*)(g_a1 + 512 + d0 + dloc);
    float2 bkp = *(const float2*)(g_b1 + 512 + d0 + dloc);
    float2 avp = *(const float2*)(g_a1 + 1024 + d0 + dloc);
    float2 bvp = *(const float2*)(g_b1 + 1024 + d0 + dloc);
#pragma unroll
    for (int i = 0; i < 8; i++) {
        int nl = ty + (i << 3);
        long long rb = ((long long)(bz << 12) + n0 + nl) * C4;
        __half2 kh2 = *(const __half2*)(g_ythi + rb + 512 + d0 + dloc);
        __half2 kl2 = *(const __half2*)(g_ytlo + rb + 512 + d0 + dloc);
        __half2 vh2 = *(const __half2*)(g_ythi + rb + 1024 + d0 + dloc);
        __half2 vl2 = *(const __half2*)(g_ytlo + rb + 1024 + d0 + dloc);
        float k0 = __half2float(kh2.x) + __half2float(kl2.x);
        float k1 = __half2float(kh2.y) + __half2float(kl2.y);
        float v0 = __half2float(vh2.x) + __half2float(vl2.x);
        float v1 = __half2float(vh2.y) + __half2float(vl2.y);
        tk[nl][dloc]     = 1.f / (1.f + expf(-(akp.x * k0 + bkp.x)));
        tk[nl][dloc + 1] = 1.f / (1.f + expf(-(akp.y * k1 + bkp.y)));
        tv[nl][dloc]     = avp.x * v0 + bvp.x;
        tv[nl][dloc + 1] = avp.y * v1 + bvp.y;
    }
    __syncthreads();
#pragma unroll
    for (int i = 0; i < 8; i++) {
        int dl = ty + (i << 3);
        int d = d0 + dl;
        int nl = tx << 1;
        float k0 = tk[nl][dl], k1 = tk[nl + 1][dl];
        float v0 = tv[nl][dl], v1 = tv[nl + 1][dl];
        long long o = ((long long)(bz << 9) + d) * NPIX + n0 + nl;
        __half2 kl2;
        __half2 kh2 = splith2(k0, k1, kl2);
        *(__half2*)(g_khi + o) = kh2;
        *(__half2*)(g_klo + o) = kl2;
        *(__half2*)(g_vhi + o) = h2_rn(v0, v1);
        float s = k0 + k1;
#pragma unroll
        for (int off = 16; off > 0; off >>= 1)
            s += __shfl_down_sync(0xffffffffu, s, off);
        if (tx == 0) atomicAdd(&g_ksum[(bz << 9) + d], s);
    }
}

// z[r] = sum_d kmean[d] * q[r][d] + eps
__global__ void z_kernel()
{
    __shared__ float km[512];
    int r0 = blockIdx.x << 3;
    int bb = r0 >> 12;
    for (int i = threadIdx.x; i < 512; i += 256)
        km[i] = g_ksum[(bb << 9) + i] * (1.f / NPIX);
    __syncthreads();
    int w = threadIdx.x >> 5, lane = threadIdx.x & 31;
    int r = r0 + w;
    const __half* qh = g_qthi + (long long)r * DIM;
    float s = 0.f;
#pragma unroll
    for (int i = 0; i < 16; i++) {
        int d = lane + (i << 5);
        s += km[d] * __half2float(qh[d]);
    }
#pragma unroll
    for (int off = 16; off > 0; off >>= 1)
        s += __shfl_down_sync(0xffffffffu, s, off);
    if (lane == 0) g_z[r] = s + 5e-4f;
}

// RMSNorm row + anw + SiLU(gate) -> o^T hi/lo fp16
__global__ void rmsgate_kernel(const float* __restrict__ anw)
{
    __shared__ float red[4];
    int r = blockIdx.x;
    int t = threadIdx.x;
    int dg = t << 2;
    long long arow = (long long)r * DIM + dg;
    __half2 ah0 = *(const __half2*)(g_athi + arow);
    __half2 ah1 = *(const __half2*)(g_athi + arow + 2);
    __half2 al0 = *(const __half2*)(g_atlo + arow);
    __half2 al1 = *(const __half2*)(g_atlo + arow + 2);
    float a0 = __half2float(ah0.x) + __half2float(al0.x);
    float a1 = __half2float(ah0.y) + __half2float(al0.y);
    float a2 = __half2float(ah1.x) + __half2float(al1.x);
    float a3 = __half2float(ah1.y) + __half2float(al1.y);
    float ss = a0 * a0 + a1 * a1 + a2 * a2 + a3 * a3;
    int lane = t & 31, w = t >> 5;
#pragma unroll
    for (int off = 16; off > 0; off >>= 1)
        ss += __shfl_down_sync(0xffffffffu, ss, off);
    if (lane == 0) red[w] = ss;
    __syncthreads();
    float tot = red[0] + red[1] + red[2] + red[3];
    float rms = rsqrtf(tot * (1.f / DIM) + 1e-6f);

    long long grow = (long long)r * C4 + 1536 + dg;
    __half2 gh0 = *(const __half2*)(g_ythi + grow);
    __half2 gh1 = *(const __half2*)(g_ythi + grow + 2);
    __half2 gl0 = *(const __half2*)(g_ytlo + grow);
    __half2 gl1 = *(const __half2*)(g_ytlo + grow + 2);
    float yg0 = __half2float(gh0.x) + __half2float(gl0.x);
    float yg1 = __half2float(gh0.y) + __half2float(gl0.y);
    float yg2 = __half2float(gh1.x) + __half2float(gl1.x);
    float yg3 = __half2float(gh1.y) + __half2float(gl1.y);
    float4 ga = *(const float4*)(g_a1 + 1536 + dg);
    float4 gb = *(const float4*)(g_b1 + 1536 + dg);
    float4 wn = *(const float4*)(anw + dg);
    float g0 = ga.x * yg0 + gb.x, g1 = ga.y * yg1 + gb.y;
    float g2 = ga.z * yg2 + gb.z, g3 = ga.w * yg3 + gb.w;
    float o0 = a0 * rms * wn.x * (g0 / (1.f + expf(-g0)));
    float o1 = a1 * rms * wn.y * (g1 / (1.f + expf(-g1)));
    float o2 = a2 * rms * wn.z * (g2 / (1.f + expf(-g2)));
    float o3 = a3 * rms * wn.w * (g3 / (1.f + expf(-g3)));
    __half2 l0, l1;
    __half2 h0 = splith2(o0, o1, l0);
    __half2 h1 = splith2(o2, o3, l1);
    long long o = (long long)r * DIM + dg;
    *(__half2*)(g_othi + o)     = h0;
    *(__half2*)(g_othi + o + 2) = h1;
    *(__half2*)(g_otlo + o)     = l0;
    *(__half2*)(g_otlo + o + 2) = l1;
}

__global__ void bnapply_kernel(float* __restrict__ out)
{
    long long i = (long long)(blockIdx.x * blockDim.x + threadIdx.x) * 4;
    int c = (int)((i >> 12) & 511);
    float a = g_a2[c], bb = g_b2[c];
    float4 v = *reinterpret_cast<const float4*>(g_ypre + i);
    v.x = a * v.x + bb; v.y = a * v.y + bb;
    v.z = a * v.z + bb; v.w = a * v.w + bb;
    *reinterpret_cast<float4*>(out + i) = v;
}

// f32 -> fp16 hi/lo
__global__ void convert_split(const float* __restrict__ s,
                              __half* __restrict__ hi,
                              __half* __restrict__ lo, int n)
{
    int i = blockIdx.x * blockDim.x + threadIdx.x;
    if (i < n) {
        float v = s[i];
        __half h = __float2half_rn(v);
        hi[i] = h;
        lo[i] = __float2half_rn(v - __half2float(h));
    }
}

// f32 -> fp16 (hi only)
__global__ void convert_half(const float* __restrict__ s,
                             __half* __restrict__ hi, int n)
{
    int i = blockIdx.x * blockDim.x + threadIdx.x;
    if (i < n) hi[i] = __float2half_rn(s[i]);
}

// transpose f32 src [b][R][Cc] -> fp16 hi-only dst [b][Cc][R]
__global__ void transpose_half(const float* __restrict__ src,
                               __half* __restrict__ dhi, int R, int Cc)
{
    __shared__ float t[32][33];
    int b = blockIdx.z;
    long long o = (long long)b * R * Cc;
    src += o; dhi += o;
    int c0 = blockIdx.x * 32, r0 = blockIdx.y * 32;
    int tx = threadIdx.x, ty = threadIdx.y;
#pragma unroll
    for (int i = 0; i < 4; i++)
        t[ty + 8 * i][tx] = src[(long long)(r0 + ty + 8 * i) * Cc + c0 + tx];
    __syncthreads();
#pragma unroll
    for (int i = 0; i < 4; i++) {
        int cc = c0 + ty + 8 * i;
        dhi[(long long)cc * R + r0 + tx] = __float2half_rn(t[tx][ty + 8 * i]);
    }
}

// ---------------------------------------------------------------------------
extern "C" void kernel_launch(void* const* d_in, const int* in_sizes, int n_in,
                              void* d_out, int out_size)
{
    const float* x           = (const float*)d_in[0];
    const float* qkvg_w      = (const float*)d_in[1];
    const float* qkvg_gamma  = (const float*)d_in[2];
    const float* qkvg_beta   = (const float*)d_in[3];
    const float* attn_norm_w = (const float*)d_in[4];
    const float* proj_w      = (const float*)d_in[5];
    const float* proj_gamma  = (const float*)d_in[6];
    const float* proj_beta   = (const float*)d_in[7];
    float* out = (float*)d_out;

    cudaFuncSetAttribute(gemm_mma<false, false, false, false>,
                         cudaFuncAttributeMaxDynamicSharedMemorySize, GSMEM);
    cudaFuncSetAttribute(gemm_mma<false, true, true, false>,
                         cudaFuncAttributeMaxDynamicSharedMemorySize, GSMEM);
    cudaFuncSetAttribute(gemm_mma<true, true, false, false>,
                         cudaFuncAttributeMaxDynamicSharedMemorySize, GSMEM);
    cudaFuncSetAttribute(gemm_mma<false, false, false, true>,
                         cudaFuncAttributeMaxDynamicSharedMemorySize, GSMEM);

    float *pypre, *pvkp, *pz;
    __half *pythi, *pytlo, *pathi, *patlo;
    __half *pkhi, *pklo, *pvhi, *pqthi, *pxthi;
    __half *pothi, *potlo, *pvkhi, *pvklo, *pwqhi, *pwqlo, *ppwhi;
    cudaGetSymbolAddress((void**)&pythi, g_ythi);
    cudaGetSymbolAddress((void**)&pytlo, g_ytlo);
    cudaGetSymbolAddress((void**)&pathi, g_athi);
    cudaGetSymbolAddress((void**)&patlo, g_atlo);
    cudaGetSymbolAddress((void**)&pypre, g_ypre);
    cudaGetSymbolAddress((void**)&pvkp,  g_vkp);
    cudaGetSymbolAddress((void**)&pz,    g_z);
    cudaGetSymbolAddress((void**)&pkhi,  g_khi);
    cudaGetSymbolAddress((void**)&pklo,  g_klo);
    cudaGetSymbolAddress((void**)&pvhi,  g_vhi);
    cudaGetSymbolAddress((void**)&pqthi, g_qthi);
    cudaGetSymbolAddress((void**)&pxthi, g_xthi);
    cudaGetSymbolAddress((void**)&pothi, g_othi);
    cudaGetSymbolAddress((void**)&potlo, g_otlo);
    cudaGetSymbolAddress((void**)&pvkhi, g_vkhi);
    cudaGetSymbolAddress((void**)&pvklo, g_vklo);
    cudaGetSymbolAddress((void**)&pwqhi, g_wqhi);
    cudaGetSymbolAddress((void**)&pwqlo, g_wqlo);
    cudaGetSymbolAddress((void**)&ppwhi, g_pwhi);

    const long long sQKV = (long long)DIM * NPIX;   // 2097152
    const long long sYT  = (long long)NPIX * C4;    // 8388608
    const long long sVK  = (long long)DIM * DIM;    // 262144

    zero_kernel<<<32, 256>>>();
    convert_split<<<4096, 256>>>(qkvg_w, pwqhi, pwqlo, C4 * DIM);
    convert_half<<<1024, 256>>>(proj_w, ppwhi, DIM * DIM);
    transpose_half<<<dim3(128, 16, BATCH), dim3(32, 8)>>>(x, pxthi, DIM, NPIX);

    // 1) y^T = x^T @ w^T -> fp16 hi/lo + fused BN1 column stats
    gemm_mma<false, true, true, false><<<dim3(16, 32, BATCH), 128, GSMEM>>>(
        pxthi, pwqhi, pwqlo, nullptr, pythi, pytlo,
        2048, 512, 512, 1, sQKV, 0, sYT, 1.f, nullptr);

    // 2) BN1 finalize
    bn1_finalize<<<8, 256>>>(qkvg_gamma, qkvg_beta);

    // 3) q^T fp16; k hi/lo + v hi -> [d][n] + ksum
    q_kernel<<<16384, 256>>>();
    kvt_kernel<<<dim3(64, 8, BATCH), dim3(32, 8)>>>();

    // 4) z
    z_kernel<<<4096, 256>>>();

    // 5) vk = v @ k^T, split-K x4; reduce -> hi/lo fp16
    gemm_mma<false, false, false, false><<<dim3(4, 4, BATCH * 4), 128, GSMEM>>>(
        pvhi, pkhi, pklo, pvkp, nullptr, nullptr,
        512, 1024, 4096, 4, sQKV, sQKV, sVK, 1.f, nullptr);
    vkred_kernel<<<2048, 256>>>();

    // 6) attn^T = q^T @ vk^T / z -> hi/lo fp16
    gemm_mma<true, true, false, false><<<dim3(4, 32, BATCH), 128, GSMEM>>>(
        pqthi, pvkhi, pvklo, nullptr, pathi, patlo,
        512, 512, 512, 1, sQKV, sVK, sQKV, 1.f, pz);

    // 7) RMSNorm + gate -> o^T hi/lo
    rmsgate_kernel<<<32768, 128>>>(attn_norm_w);

    // 8) ypre = proj_w @ o + fused BN2 row stats
    gemm_mma<false, false, false, true><<<dim3(32, 4, BATCH), 128, GSMEM>>>(
        ppwhi, pothi, potlo, pypre, nullptr, nullptr,
        4096, 512, 512, 1, 0, sQKV, sQKV, 1.f, nullptr);

    // 9) BN2 finalize + apply
    bn2_finalize<<<2, 256>>>(proj_gamma, proj_beta);
    bnapply_kernel<<<16384, 256>>>(out);
}

// round 12
// speedup vs baseline: 1.7356x; 1.1051x over previous
#include <cuda_runtime.h>
#include <cuda_fp16.h>
#include <math.h>
#include <stdint.h>

// ---------------------------------------------------------------------------
// SHMA block: mma.sync fp16 GEMMs, 2-product hi/lo scheme
// (C = Ah*(Bh+Bl)), BK=64 chunks (half the barriers), n-major dataflow,
// BN1/BN2 stats fused into GEMM epilogues.
// B=8, dim=d=512, N=4096, qkvg=2048.
// ---------------------------------------------------------------------------

#define BATCH 8
#define DIM   512
#define NPIX  4096
#define C4    2048

// ---------------- scratch (static device globals) --------------------------
__device__ __half g_ythi[67108864], g_ytlo[67108864]; // y^T (8*4096,2048)
__device__ __half g_athi[16777216], g_atlo[16777216]; // attn^T (8*4096,512)
__device__ float g_ypre[16777216];                    // ypre (8, 512, 4096) f32
__device__ float g_vkp[8388608];                      // vk split-K partials
__device__ __half g_khi[16777216], g_klo[16777216];   // k [b][d][n]  (B op)
__device__ __half g_vhi[16777216];                    // v [b][d][n]  (A op)
__device__ __half g_qthi[16777216];                   // q^T [b][n][d] (A op)
__device__ __half g_xthi[16777216];                   // x^T [b][n][c] (A op)
__device__ __half g_othi[16777216], g_otlo[16777216]; // o^T [b][n][d] (B op)
__device__ __half g_vkhi[2097152], g_vklo[2097152];   // vk [b][d][e] (B op)
__device__ __half g_wqhi[1048576], g_wqlo[1048576];   // qkvg_w (B op)
__device__ __half g_pwhi[262144];                     // proj_w (A op)
__device__ float g_a1[2048], g_b1[2048], g_a2[512], g_b2[512];
__device__ float g_s1[2048], g_s2[2048];              // BN1 accum
__device__ float g_t1[512], g_t2[512];                // BN2 accum
__device__ float g_ksum[4096], g_z[32768];

// ---------------- helpers ---------------------------------------------------
__device__ __forceinline__ uint32_t smem_u32(const void* p) {
    uint32_t a;
    asm("{ .reg .u64 t; cvta.to.shared.u64 t, %1; cvt.u32.u64 %0, t; }"
        : "=r"(a) : "l"(p));
    return a;
}
__device__ __forceinline__ void ldsm_x4(uint32_t& r0, uint32_t& r1,
                                        uint32_t& r2, uint32_t& r3,
                                        uint32_t addr) {
    asm volatile("ldmatrix.sync.aligned.m8n8.x4.shared.b16 {%0,%1,%2,%3}, [%4];"
                 : "=r"(r0), "=r"(r1), "=r"(r2), "=r"(r3) : "r"(addr));
}
__device__ __forceinline__ void mma16816(float* c, const uint32_t* a,
                                         uint32_t b0, uint32_t b1) {
    asm volatile(
        "mma.sync.aligned.m16n8k16.row.col.f32.f16.f16.f32 "
        "{%0,%1,%2,%3}, {%4,%5,%6,%7}, {%8,%9}, {%0,%1,%2,%3};"
        : "+f"(c[0]), "+f"(c[1]), "+f"(c[2]), "+f"(c[3])
        : "r"(a[0]), "r"(a[1]), "r"(a[2]), "r"(a[3]), "r"(b0), "r"(b1));
}
__device__ __forceinline__ void cpasync16(uint32_t dst, const void* src) {
    asm volatile("cp.async.cg.shared.global [%0], [%1], 16;"
                 :: "r"(dst), "l"(src));
}
#define CP_COMMIT() asm volatile("cp.async.commit_group;" ::: "memory")
#define CP_WAIT(n)  asm volatile("cp.async.wait_group %0;" :: "n"(n) : "memory")

// fp16 hi/lo split of a pair
__device__ __forceinline__ __half2 splith2(float a, float b, __half2& lo) {
    __half h0 = __float2half_rn(a), h1 = __float2half_rn(b);
    lo = __halves2half2(__float2half_rn(a - __half2float(h0)),
                        __float2half_rn(b - __half2float(h1)));
    return __halves2half2(h0, h1);
}
__device__ __forceinline__ __half2 h2_rn(float a, float b) {
    return __halves2half2(__float2half_rn(a), __float2half_rn(b));
}

// ---------------------------------------------------------------------------
// mma.sync fp16 GEMM, 2-product: C = alpha * Ah @ (Bh + Bl)^T.
//   Ah [M][ldk] fp16, Bh/Bl [N][ldk] fp16 (K-major rows).
//   128x128 CTA tile, BK=64, 128 threads (2x2 warps, 64x64 warp tiles),
//   2-stage cp.async double buffer, padded smem (SROW=72 elems: 144B rows,
//   odd 16B-unit stride -> conflict-free ldmatrix + cp.async).
//   Split-K via blockIdx.z = b*kchunks + ks (f32 C offset by zi*sC).
//   ZDIV: row-divide by zb. OUTSPLIT: hi/lo fp16 out.
//   STATS: per-column sum/sumsq atomics. ROWSTATS: per-row sum/sumsq atomics.
// ---------------------------------------------------------------------------
#define SROW 72
#define BUFB (128 * SROW * 2)          // 18432 B per operand tile
#define STAGEB (3 * BUFB)              // Ah, Bh, Bl = 55296 B
#define GSMEM (2 * STAGEB + 512)       // 2 stages + zsm = 111104 B

template <bool ZDIV, bool OUTSPLIT, bool STATS, bool ROWSTATS>
__global__ void __launch_bounds__(128)
gemm_mma(const __half* __restrict__ Ah_, const __half* __restrict__ Bhi_,
         const __half* __restrict__ Blo_,
         float* __restrict__ C_, __half* __restrict__ Chi_,
         __half* __restrict__ Clo_,
         int N, int K, int ldk, int kchunks,
         long long sA, long long sB, long long sC,
         float alpha, const float* __restrict__ zb)
{
    extern __shared__ char smem[];
    const int zi = blockIdx.z;
    const int b  = zi / kchunks;
    const int ks = zi - b * kchunks;
    const long long koff = (long long)ks * K;

    const __half* Ah = Ah_ + (long long)b * sA + koff;
    const __half* Bh = Bhi_ + (long long)b * sB + koff;
    const __half* Bl = Blo_ + (long long)b * sB + koff;
    const int m0 = blockIdx.y << 7, n0 = blockIdx.x << 7;
    const int tid = threadIdx.x, wid = tid >> 5, lane = tid & 31;
    const int wm = wid & 1, wn = wid >> 1;
    const int tig = lane & 3, grp = lane >> 2;

    const uint32_t sb = smem_u32(smem);
    float* zsm = (float*)(smem + 2 * STAGEB);
    if (ZDIV) zsm[tid] = 1.f / zb[(long long)b * 4096 + m0 + tid];

    const int CH = K >> 6;

    float acc[4][8][4];
#pragma unroll
    for (int i = 0; i < 4; i++)
#pragma unroll
        for (int j = 0; j < 8; j++)
#pragma unroll
            for (int t = 0; t < 4; t++) acc[i][j][t] = 0.f;

    // load 3 operand tiles (Ah, Bh, Bl), 128 rows x 64 fp16, into stage st
    auto load = [&](int c, int st) {
        long long kp = (long long)c << 6;
        uint32_t base = sb + (uint32_t)st * STAGEB;
#pragma unroll
        for (int i = 0; i < 8; i++) {
            int slot = tid + (i << 7);
            int row = slot >> 3, u = slot & 7;
            uint32_t d = (uint32_t)(row * (SROW * 2) + (u << 4));
            long long aoff = (long long)(m0 + row) * ldk + kp + (u << 3);
            long long boff = (long long)(n0 + row) * ldk + kp + (u << 3);
            cpasync16(base + d, Ah + aoff);
            cpasync16(base + BUFB + d, Bh + boff);
            cpasync16(base + 2 * BUFB + d, Bl + boff);
        }
        CP_COMMIT();
    };

    load(0, 0);

    const uint32_t lrow16 = lane & 15;
    const uint32_t lcol8 = (lane >> 4) << 3;

    int buf = 0;
    for (int c = 0; c < CH; c++) {
        if (c + 1 < CH) { load(c + 1, buf ^ 1); CP_WAIT(1); }
        else            { CP_WAIT(0); }
        __syncthreads();

        uint32_t base = sb + (uint32_t)buf * STAGEB;
#pragma unroll
        for (int ko2 = 0; ko2 < 4; ko2++) {
            const uint32_t ko = ko2 << 4;
            uint32_t ah[4][4], bb[4][4];
#pragma unroll
            for (int mi = 0; mi < 4; mi++) {
                uint32_t ad = base +
                    (((wm << 6) + (mi << 4) + lrow16) * SROW + ko + lcol8) * 2;
                ldsm_x4(ah[mi][0], ah[mi][1], ah[mi][2], ah[mi][3], ad);
            }
            // seg1: Ah * Bh
#pragma unroll
            for (int nb = 0; nb < 4; nb++) {
                uint32_t bd = base + BUFB +
                    (((wn << 6) + (nb << 4) + lrow16) * SROW + ko + lcol8) * 2;
                ldsm_x4(bb[nb][0], bb[nb][1], bb[nb][2], bb[nb][3], bd);
            }
#pragma unroll
            for (int mi = 0; mi < 4; mi++)
#pragma unroll
                for (int ni = 0; ni < 8; ni++) {
                    int nb = ni >> 1, hf = ni & 1;
                    mma16816(acc[mi][ni], ah[mi], bb[nb][hf], bb[nb][hf + 2]);
                }
            // seg2: Ah * Bl (reuse ah fragments)
#pragma unroll
            for (int nb = 0; nb < 4; nb++) {
                uint32_t bd = base + 2 * BUFB +
                    (((wn << 6) + (nb << 4) + lrow16) * SROW + ko + lcol8) * 2;
                ldsm_x4(bb[nb][0], bb[nb][1], bb[nb][2], bb[nb][3], bd);
            }
#pragma unroll
            for (int mi = 0; mi < 4; mi++)
#pragma unroll
                for (int ni = 0; ni < 8; ni++) {
                    int nb = ni >> 1, hf = ni & 1;
                    mma16816(acc[mi][ni], ah[mi], bb[nb][hf], bb[nb][hf + 2]);
                }
        }
        __syncthreads();
        buf ^= 1;
    }

    // epilogue
    float* C = C_ + (long long)zi * sC;
    __half* Chi = Chi_ + (long long)b * sC;
    __half* Clo = Clo_ + (long long)b * sC;
    float cs1[8][2], cs2[8][2];
    float rs1[4][2], rs2[4][2];
    if (STATS) {
#pragma unroll
        for (int ni = 0; ni < 8; ni++) {
            cs1[ni][0] = cs1[ni][1] = 0.f;
            cs2[ni][0] = cs2[ni][1] = 0.f;
        }
    }
    if (ROWSTATS) {
#pragma unroll
        for (int mi = 0; mi < 4; mi++) {
            rs1[mi][0] = rs1[mi][1] = 0.f;
            rs2[mi][0] = rs2[mi][1] = 0.f;
        }
    }
#pragma unroll
    for (int mi = 0; mi < 4; mi++) {
        int rl = (wm << 6) + (mi << 4) + grp;
        int row = m0 + rl;
        float zr0 = 1.f, zr1 = 1.f;
        if (ZDIV) { zr0 = zsm[rl]; zr1 = zsm[rl + 8]; }
#pragma unroll
        for (int ni = 0; ni < 8; ni++) {
            int col = n0 + (wn << 6) + (ni << 3) + (tig << 1);
            float v0 = acc[mi][ni][0] * alpha;
            float v1 = acc[mi][ni][1] * alpha;
            float v2 = acc[mi][ni][2] * alpha;
            float v3 = acc[mi][ni][3] * alpha;
            if (ZDIV) { v0 *= zr0; v1 *= zr0; v2 *= zr1; v3 *= zr1; }
            if (STATS) {
                cs1[ni][0] += v0 + v2;
                cs1[ni][1] += v1 + v3;
                cs2[ni][0] += v0 * v0 + v2 * v2;
                cs2[ni][1] += v1 * v1 + v3 * v3;
            }
            if (ROWSTATS) {
                rs1[mi][0] += v0 + v1;
                rs2[mi][0] += v0 * v0 + v1 * v1;
                rs1[mi][1] += v2 + v3;
                rs2[mi][1] += v2 * v2 + v3 * v3;
            }
            if (OUTSPLIT) {
                __half2 l0, l1;
                __half2 h0 = splith2(v0, v1, l0);
                __half2 h1 = splith2(v2, v3, l1);
                *(__half2*)(Chi + (long long)row * N + col) = h0;
                *(__half2*)(Chi + (long long)(row + 8) * N + col) = h1;
                *(__half2*)(Clo + (long long)row * N + col) = l0;
                *(__half2*)(Clo + (long long)(row + 8) * N + col) = l1;
            } else {
                float2 p0; p0.x = v0; p0.y = v1;
                float2 p1; p1.x = v2; p1.y = v3;
                *(float2*)(C + (long long)row * N + col) = p0;
                *(float2*)(C + (long long)(row + 8) * N + col) = p1;
            }
        }
    }
    if (STATS) {
#pragma unroll
        for (int ni = 0; ni < 8; ni++)
#pragma unroll
            for (int h = 0; h < 2; h++) {
                float s1 = cs1[ni][h], s2 = cs2[ni][h];
                s1 += __shfl_down_sync(0xffffffffu, s1, 16);
                s2 += __shfl_down_sync(0xffffffffu, s2, 16);
                s1 += __shfl_down_sync(0xffffffffu, s1, 8);
                s2 += __shfl_down_sync(0xffffffffu, s2, 8);
                s1 += __shfl_down_sync(0xffffffffu, s1, 4);
                s2 += __shfl_down_sync(0xffffffffu, s2, 4);
                if (lane < 4) {
                    int col = n0 + (wn << 6) + (ni << 3) + (lane << 1) + h;
                    atomicAdd(&g_s1[col], s1);
                    atomicAdd(&g_s2[col], s2);
                }
            }
    }
    if (ROWSTATS) {
#pragma unroll
        for (int mi = 0; mi < 4; mi++)
#pragma unroll
            for (int h = 0; h < 2; h++) {
                float s1 = rs1[mi][h], s2 = rs2[mi][h];
                s1 += __shfl_down_sync(0xffffffffu, s1, 2, 4);
                s2 += __shfl_down_sync(0xffffffffu, s2, 2, 4);
                s1 += __shfl_down_sync(0xffffffffu, s1, 1, 4);
                s2 += __shfl_down_sync(0xffffffffu, s2, 1, 4);
                if (tig == 0) {
                    int row = m0 + (wm << 6) + (mi << 4) + grp + (h << 3);
                    atomicAdd(&g_t1[row], s1);
                    atomicAdd(&g_t2[row], s2);
                }
            }
    }
}

// ---------------------------------------------------------------------------
// vk split-K reduce -> hi/lo fp16 with alpha
// ---------------------------------------------------------------------------
__global__ void vkred_kernel()
{
    long long i4 = (long long)(blockIdx.x * 256 + threadIdx.x) * 4;
    int b = (int)(i4 >> 18);
    long long off = i4 & 262143;
    const float* p = g_vkp + ((long long)b * 4) * 262144 + off;
    float4 s0 = *(const float4*)p;
    float4 s1 = *(const float4*)(p + 262144);
    float4 s2 = *(const float4*)(p + 2 * 262144);
    float4 s3 = *(const float4*)(p + 3 * 262144);
    const float al = 1.f / 4096.f;
    float v0 = ((s0.x + s1.x) + (s2.x + s3.x)) * al;
    float v1 = ((s0.y + s1.y) + (s2.y + s3.y)) * al;
    float v2 = ((s0.z + s1.z) + (s2.z + s3.z)) * al;
    float v3 = ((s0.w + s1.w) + (s2.w + s3.w)) * al;
    __half2 l0, l1;
    __half2 h0 = splith2(v0, v1, l0);
    __half2 h1 = splith2(v2, v3, l1);
    *(__half2*)(g_vkhi + i4)     = h0;
    *(__half2*)(g_vkhi + i4 + 2) = h1;
    *(__half2*)(g_vklo + i4)     = l0;
    *(__half2*)(g_vklo + i4 + 2) = l1;
}

// ---------------------------------------------------------------------------
__global__ void zero_kernel()
{
    int i = blockIdx.x * 256 + threadIdx.x;
    if (i < 2048) { g_s1[i] = 0.f; g_s2[i] = 0.f; }
    if (i < 512)  { g_t1[i] = 0.f; g_t2[i] = 0.f; }
    if (i < 4096) g_ksum[i] = 0.f;
}

__global__ void bn1_finalize(const float* __restrict__ gamma,
                             const float* __restrict__ beta)
{
    int c = blockIdx.x * 256 + threadIdx.x;
    const float inv = 1.f / (BATCH * NPIX);
    float mean = g_s1[c] * inv;
    float var = g_s2[c] * inv - mean * mean;
    float av = gamma[c] * rsqrtf(var + 1e-5f);
    g_a1[c] = av;
    g_b1[c] = beta[c] - mean * av;
}

__global__ void bn2_finalize(const float* __restrict__ gamma,
                             const float* __restrict__ beta)
{
    int c = blockIdx.x * 256 + threadIdx.x;
    const float inv = 1.f / (BATCH * NPIX);
    float mean = g_t1[c] * inv;
    float var = g_t2[c] * inv - mean * mean;
    float av = gamma[c] * rsqrtf(var + 1e-5f);
    g_a2[c] = av;
    g_b2[c] = beta[c] - mean * av;
}

// q: sigmoid(affine(y[:, 0:512])) -> q^T fp16 (hi only; A operand)
__global__ void q_kernel()
{
    int i = blockIdx.x * 256 + threadIdx.x;
    int r = i >> 7;
    int dg = (i & 127) << 2;
    long long yb = (long long)r * C4 + dg;
    __half2 yh0 = *(const __half2*)(g_ythi + yb);
    __half2 yh1 = *(const __half2*)(g_ythi + yb + 2);
    __half2 yl0 = *(const __half2*)(g_ytlo + yb);
    __half2 yl1 = *(const __half2*)(g_ytlo + yb + 2);
    float4 a4 = *(const float4*)(g_a1 + dg);
    float4 b4 = *(const float4*)(g_b1 + dg);
    float y0 = __half2float(yh0.x) + __half2float(yl0.x);
    float y1 = __half2float(yh0.y) + __half2float(yl0.y);
    float y2 = __half2float(yh1.x) + __half2float(yl1.x);
    float y3 = __half2float(yh1.y) + __half2float(yl1.y);
    float q0 = 1.f / (1.f + expf(-(a4.x * y0 + b4.x)));
    float q1 = 1.f / (1.f + expf(-(a4.y * y1 + b4.y)));
    float q2 = 1.f / (1.f + expf(-(a4.z * y2 + b4.z)));
    float q3 = 1.f / (1.f + expf(-(a4.w * y3 + b4.w)));
    long long o = (long long)r * DIM + dg;
    *(__half2*)(g_qthi + o)     = h2_rn(q0, q1);
    *(__half2*)(g_qthi + o + 2) = h2_rn(q2, q3);
}

// k,v: 64x64 transpose y^T -> [b][d][n]; k hi/lo fp16, v hi fp16, ksum
__global__ void kvt_kernel()
{
    __shared__ float tk[64][65], tv[64][65];
    int bz = blockIdx.z;
    int n0 = blockIdx.x << 6, d0 = blockIdx.y << 6;
    int tx = threadIdx.x, ty = threadIdx.y;
    int dloc = tx << 1;
    float2 akp = *(const float2*)(g_a1 + 512 + d0 + dloc);
    float2 bkp = *(const float2*)(g_b1 + 512 + d0 + dloc);
    float2 avp = *(const float2*)(g_a1 + 1024 + d0 + dloc);
    float2 bvp = *(const float2*)(g_b1 + 1024 + d0 + dloc);
#pragma unroll
    for (int i = 0; i < 8; i++) {
        int nl = ty + (i << 3);
        long long rb = ((long long)(bz << 12) + n0 + nl) * C4;
        __half2 kh2 = *(const __half2*)(g_ythi + rb + 512 + d0 + dloc);
        __half2 kl2 = *(const __half2*)(g_ytlo + rb + 512 + d0 + dloc);
        __half2 vh2 = *(const __half2*)(g_ythi + rb + 1024 + d0 + dloc);
        __half2 vl2 = *(const __half2*)(g_ytlo + rb + 1024 + d0 + dloc);
        float k0 = __half2float(kh2.x) + __half2float(kl2.x);
        float k1 = __half2float(kh2.y) + __half2float(kl2.y);
        float v0 = __half2float(vh2.x) + __half2float(vl2.x);
        float v1 = __half2float(vh2.y) + __half2float(vl2.y);
        tk[nl][dloc]     = 1.f / (1.f + expf(-(akp.x * k0 + bkp.x)));
        tk[nl][dloc + 1] = 1.f / (1.f + expf(-(akp.y * k1 + bkp.y)));
        tv[nl][dloc]     = avp.x * v0 + bvp.x;
        tv[nl][dloc + 1] = avp.y * v1 + bvp.y;
    }
    __syncthreads();
#pragma unroll
    for (int i = 0; i < 8; i++) {
        int dl = ty + (i << 3);
        int d = d0 + dl;
        int nl = tx << 1;
        float k0 = tk[nl][dl], k1 = tk[nl + 1][dl];
        float v0 = tv[nl][dl], v1 = tv[nl + 1][dl];
        long long o = ((long long)(bz << 9) + d) * NPIX + n0 + nl;
        __half2 kl2;
        __half2 kh2 = splith2(k0, k1, kl2);
        *(__half2*)(g_khi + o) = kh2;
        *(__half2*)(g_klo + o) = kl2;
        *(__half2*)(g_vhi + o) = h2_rn(v0, v1);
        float s = k0 + k1;
#pragma unroll
        for (int off = 16; off > 0; off >>= 1)
            s += __shfl_down_sync(0xffffffffu, s, off);
        if (tx == 0) atomicAdd(&g_ksum[(bz << 9) + d], s);
    }
}

// z[r] = sum_d kmean[d] * q[r][d] + eps
__global__ void z_kernel()
{
    __shared__ float km[512];
    int r0 = blockIdx.x << 3;
    int bb = r0 >> 12;
    for (int i = threadIdx.x; i < 512; i += 256)
        km[i] = g_ksum[(bb << 9) + i] * (1.f / NPIX);
    __syncthreads();
    int w = threadIdx.x >> 5, lane = threadIdx.x & 31;
    int r = r0 + w;
    const __half* qh = g_qthi + (long long)r * DIM;
    float s = 0.f;
#pragma unroll
    for (int i = 0; i < 16; i++) {
        int d = lane + (i << 5);
        s += km[d] * __half2float(qh[d]);
    }
#pragma unroll
    for (int off = 16; off > 0; off >>= 1)
        s += __shfl_down_sync(0xffffffffu, s, off);
    if (lane == 0) g_z[r] = s + 5e-4f;
}

// RMSNorm row + anw + SiLU(gate) -> o^T hi/lo fp16
__global__ void rmsgate_kernel(const float* __restrict__ anw)
{
    __shared__ float red[4];
    int r = blockIdx.x;
    int t = threadIdx.x;
    int dg = t << 2;
    long long arow = (long long)r * DIM + dg;
    __half2 ah0 = *(const __half2*)(g_athi + arow);
    __half2 ah1 = *(const __half2*)(g_athi + arow + 2);
    __half2 al0 = *(const __half2*)(g_atlo + arow);
    __half2 al1 = *(const __half2*)(g_atlo + arow + 2);
    float a0 = __half2float(ah0.x) + __half2float(al0.x);
    float a1 = __half2float(ah0.y) + __half2float(al0.y);
    float a2 = __half2float(ah1.x) + __half2float(al1.x);
    float a3 = __half2float(ah1.y) + __half2float(al1.y);
    float ss = a0 * a0 + a1 * a1 + a2 * a2 + a3 * a3;
    int lane = t & 31, w = t >> 5;
#pragma unroll
    for (int off = 16; off > 0; off >>= 1)
        ss += __shfl_down_sync(0xffffffffu, ss, off);
    if (lane == 0) red[w] = ss;
    __syncthreads();
    float tot = red[0] + red[1] + red[2] + red[3];
    float rms = rsqrtf(tot * (1.f / DIM) + 1e-6f);

    long long grow = (long long)r * C4 + 1536 + dg;
    __half2 gh0 = *(const __half2*)(g_ythi + grow);
    __half2 gh1 = *(const __half2*)(g_ythi + grow + 2);
    __half2 gl0 = *(const __half2*)(g_ytlo + grow);
    __half2 gl1 = *(const __half2*)(g_ytlo + grow + 2);
    float yg0 = __half2float(gh0.x) + __half2float(gl0.x);
    float yg1 = __half2float(gh0.y) + __half2float(gl0.y);
    float yg2 = __half2float(gh1.x) + __half2float(gl1.x);
    float yg3 = __half2float(gh1.y) + __half2float(gl1.y);
    float4 ga = *(const float4*)(g_a1 + 1536 + dg);
    float4 gb = *(const float4*)(g_b1 + 1536 + dg);
    float4 wn = *(const float4*)(anw + dg);
    float g0 = ga.x * yg0 + gb.x, g1 = ga.y * yg1 + gb.y;
    float g2 = ga.z * yg2 + gb.z, g3 = ga.w * yg3 + gb.w;
    float o0 = a0 * rms * wn.x * (g0 / (1.f + expf(-g0)));
    float o1 = a1 * rms * wn.y * (g1 / (1.f + expf(-g1)));
    float o2 = a2 * rms * wn.z * (g2 / (1.f + expf(-g2)));
    float o3 = a3 * rms * wn.w * (g3 / (1.f + expf(-g3)));
    __half2 l0, l1;
    __half2 h0 = splith2(o0, o1, l0);
    __half2 h1 = splith2(o2, o3, l1);
    long long o = (long long)r * DIM + dg;
    *(__half2*)(g_othi + o)     = h0;
    *(__half2*)(g_othi + o + 2) = h1;
    *(__half2*)(g_otlo + o)     = l0;
    *(__half2*)(g_otlo + o + 2) = l1;
}

__global__ void bnapply_kernel(float* __restrict__ out)
{
    long long i = (long long)(blockIdx.x * blockDim.x + threadIdx.x) * 4;
    int c = (int)((i >> 12) & 511);
    float a = g_a2[c], bb = g_b2[c];
    float4 v = *reinterpret_cast<const float4*>(g_ypre + i);
    v.x = a * v.x + bb; v.y = a * v.y + bb;
    v.z = a * v.z + bb; v.w = a * v.w + bb;
    *reinterpret_cast<float4*>(out + i) = v;
}

// f32 -> fp16 hi/lo
__global__ void convert_split(const float* __restrict__ s,
                              __half* __restrict__ hi,
                              __half* __restrict__ lo, int n)
{
    int i = blockIdx.x * blockDim.x + threadIdx.x;
    if (i < n) {
        float v = s[i];
        __half h = __float2half_rn(v);
        hi[i] = h;
        lo[i] = __float2half_rn(v - __half2float(h));
    }
}

// f32 -> fp16 (hi only)
__global__ void convert_half(const float* __restrict__ s,
                             __half* __restrict__ hi, int n)
{
    int i = blockIdx.x * blockDim.x + threadIdx.x;
    if (i < n) hi[i] = __float2half_rn(s[i]);
}

// transpose f32 src [b][R][Cc] -> fp16 hi-only dst [b][Cc][R]
__global__ void transpose_half(const float* __restrict__ src,
                               __half* __restrict__ dhi, int R, int Cc)
{
    __shared__ float t[32][33];
    int b = blockIdx.z;
    long long o = (long long)b * R * Cc;
    src += o; dhi += o;
    int c0 = blockIdx.x * 32, r0 = blockIdx.y * 32;
    int tx = threadIdx.x, ty = threadIdx.y;
#pragma unroll
    for (int i = 0; i < 4; i++)
        t[ty + 8 * i][tx] = src[(long long)(r0 + ty + 8 * i) * Cc + c0 + tx];
    __syncthreads();
#pragma unroll
    for (int i = 0; i < 4; i++) {
        int cc = c0 + ty + 8 * i;
        dhi[(long long)cc * R + r0 + tx] = __float2half_rn(t[tx][ty + 8 * i]);
    }
}

// ---------------------------------------------------------------------------
extern "C" void kernel_launch(void* const* d_in, const int* in_sizes, int n_in,
                              void* d_out, int out_size)
{
    const float* x           = (const float*)d_in[0];
    const float* qkvg_w      = (const float*)d_in[1];
    const float* qkvg_gamma  = (const float*)d_in[2];
    const float* qkvg_beta   = (const float*)d_in[3];
    const float* attn_norm_w = (const float*)d_in[4];
    const float* proj_w      = (const float*)d_in[5];
    const float* proj_gamma  = (const float*)d_in[6];
    const float* proj_beta   = (const float*)d_in[7];
    float* out = (float*)d_out;

    cudaFuncSetAttribute(gemm_mma<false, false, false, false>,
                         cudaFuncAttributeMaxDynamicSharedMemorySize, GSMEM);
    cudaFuncSetAttribute(gemm_mma<false, true, true, false>,
                         cudaFuncAttributeMaxDynamicSharedMemorySize, GSMEM);
    cudaFuncSetAttribute(gemm_mma<true, true, false, false>,
                         cudaFuncAttributeMaxDynamicSharedMemorySize, GSMEM);
    cudaFuncSetAttribute(gemm_mma<false, false, false, true>,
                         cudaFuncAttributeMaxDynamicSharedMemorySize, GSMEM);

    float *pypre, *pvkp, *pz;
    __half *pythi, *pytlo, *pathi, *patlo;
    __half *pkhi, *pklo, *pvhi, *pqthi, *pxthi;
    __half *pothi, *potlo, *pvkhi, *pvklo, *pwqhi, *pwqlo, *ppwhi;
    cudaGetSymbolAddress((void**)&pythi, g_ythi);
    cudaGetSymbolAddress((void**)&pytlo, g_ytlo);
    cudaGetSymbolAddress((void**)&pathi, g_athi);
    cudaGetSymbolAddress((void**)&patlo, g_atlo);
    cudaGetSymbolAddress((void**)&pypre, g_ypre);
    cudaGetSymbolAddress((void**)&pvkp,  g_vkp);
    cudaGetSymbolAddress((void**)&pz,    g_z);
    cudaGetSymbolAddress((void**)&pkhi,  g_khi);
    cudaGetSymbolAddress((void**)&pklo,  g_klo);
    cudaGetSymbolAddress((void**)&pvhi,  g_vhi);
    cudaGetSymbolAddress((void**)&pqthi, g_qthi);
    cudaGetSymbolAddress((void**)&pxthi, g_xthi);
    cudaGetSymbolAddress((void**)&pothi, g_othi);
    cudaGetSymbolAddress((void**)&potlo, g_otlo);
    cudaGetSymbolAddress((void**)&pvkhi, g_vkhi);
    cudaGetSymbolAddress((void**)&pvklo, g_vklo);
    cudaGetSymbolAddress((void**)&pwqhi, g_wqhi);
    cudaGetSymbolAddress((void**)&pwqlo, g_wqlo);
    cudaGetSymbolAddress((void**)&ppwhi, g_pwhi);

    const long long sQKV = (long long)DIM * NPIX;   // 2097152
    const long long sYT  = (long long)NPIX * C4;    // 8388608
    const long long sVK  = (long long)DIM * DIM;    // 262144

    zero_kernel<<<32, 256>>>();
    convert_split<<<4096, 256>>>(qkvg_w, pwqhi, pwqlo, C4 * DIM);
    convert_half<<<1024, 256>>>(proj_w, ppwhi, DIM * DIM);
    transpose_half<<<dim3(128, 16, BATCH), dim3(32, 8)>>>(x, pxthi, DIM, NPIX);

    // 1) y^T = x^T @ w^T -> fp16 hi/lo + fused BN1 column stats
    gemm_mma<false, true, true, false><<<dim3(16, 32, BATCH), 128, GSMEM>>>(
        pxthi, pwqhi, pwqlo, nullptr, pythi, pytlo,
        2048, 512, 512, 1, sQKV, 0, sYT, 1.f, nullptr);

    // 2) BN1 finalize
    bn1_finalize<<<8, 256>>>(qkvg_gamma, qkvg_beta);

    // 3) q^T fp16; k hi/lo + v hi -> [d][n] + ksum
    q_kernel<<<16384, 256>>>();
    kvt_kernel<<<dim3(64, 8, BATCH), dim3(32, 8)>>>();

    // 4) z
    z_kernel<<<4096, 256>>>();

    // 5) vk = v @ k^T, split-K x4; reduce -> hi/lo fp16
    gemm_mma<false, false, false, false><<<dim3(4, 4, BATCH * 4), 128, GSMEM>>>(
        pvhi, pkhi, pklo, pvkp, nullptr, nullptr,
        512, 1024, 4096, 4, sQKV, sQKV, sVK, 1.f, nullptr);
    vkred_kernel<<<2048, 256>>>();

    // 6) attn^T = q^T @ vk^T / z -> hi/lo fp16
    gemm_mma<true, true, false, false><<<dim3(4, 32, BATCH), 128, GSMEM>>>(
        pqthi, pvkhi, pvklo, nullptr, pathi, patlo,
        512, 512, 512, 1, sQKV, sVK, sQKV, 1.f, pz);

    // 7) RMSNorm + gate -> o^T hi/lo
    rmsgate_kernel<<<32768, 128>>>(attn_norm_w);

    // 8) ypre = proj_w @ o + fused BN2 row stats
    gemm_mma<false, false, false, true><<<dim3(32, 4, BATCH), 128, GSMEM>>>(
        ppwhi, pothi, potlo, pypre, nullptr, nullptr,
        4096, 512, 512, 1, 0, sQKV, sQKV, 1.f, nullptr);

    // 9) BN2 finalize + apply
    bn2_finalize<<<2, 256>>>(proj_gamma, proj_beta);
    bnapply_kernel<<<16384, 256>>>(out);
}

// round 13
// speedup vs baseline: 1.9135x; 1.1025x over previous
#include <cuda_runtime.h>
#include <cuda_fp16.h>
#include <math.h>
#include <stdint.h>

// ---------------------------------------------------------------------------
// SHMA block: mma.sync fp16 GEMMs, BK=64. GEMM1/proj use 2-product hi/lo
// (C = Ah*(Bh+Bl)); inner GEMMs (vk, attn) use 1-product (both operands
// fp16-RN). n-major dataflow, BN1/BN2 stats fused into GEMM epilogues.
// B=8, dim=d=512, N=4096, qkvg=2048.
// ---------------------------------------------------------------------------

#define BATCH 8
#define DIM   512
#define NPIX  4096
#define C4    2048

// ---------------- scratch (static device globals) --------------------------
__device__ __half g_ythi[67108864], g_ytlo[67108864]; // y^T (8*4096,2048)
__device__ __half g_athi[16777216], g_atlo[16777216]; // attn^T (8*4096,512)
__device__ float g_ypre[16777216];                    // ypre (8, 512, 4096) f32
__device__ float g_vkp[8388608];                      // vk split-K partials
__device__ __half g_khi[16777216];                    // k [b][d][n]  (B op, hi)
__device__ __half g_vhi[16777216];                    // v [b][d][n]  (A op)
__device__ __half g_qthi[16777216];                   // q^T [b][n][d] (A op)
__device__ __half g_xthi[16777216];                   // x^T [b][n][c] (A op)
__device__ __half g_othi[16777216], g_otlo[16777216]; // o^T [b][n][d] (B op)
__device__ __half g_vkhi[2097152];                    // vk [b][d][e] (B op, hi)
__device__ __half g_wqhi[1048576], g_wqlo[1048576];   // qkvg_w (B op)
__device__ __half g_pwhi[262144];                     // proj_w (A op)
__device__ float g_a1[2048], g_b1[2048], g_a2[512], g_b2[512];
__device__ float g_s1[2048], g_s2[2048];              // BN1 accum
__device__ float g_t1[512], g_t2[512];                // BN2 accum
__device__ float g_ksum[4096], g_z[32768];

// ---------------- helpers ---------------------------------------------------
__device__ __forceinline__ uint32_t smem_u32(const void* p) {
    uint32_t a;
    asm("{ .reg .u64 t; cvta.to.shared.u64 t, %1; cvt.u32.u64 %0, t; }"
        : "=r"(a) : "l"(p));
    return a;
}
__device__ __forceinline__ void ldsm_x4(uint32_t& r0, uint32_t& r1,
                                        uint32_t& r2, uint32_t& r3,
                                        uint32_t addr) {
    asm volatile("ldmatrix.sync.aligned.m8n8.x4.shared.b16 {%0,%1,%2,%3}, [%4];"
                 : "=r"(r0), "=r"(r1), "=r"(r2), "=r"(r3) : "r"(addr));
}
__device__ __forceinline__ void mma16816(float* c, const uint32_t* a,
                                         uint32_t b0, uint32_t b1) {
    asm volatile(
        "mma.sync.aligned.m16n8k16.row.col.f32.f16.f16.f32 "
        "{%0,%1,%2,%3}, {%4,%5,%6,%7}, {%8,%9}, {%0,%1,%2,%3};"
        : "+f"(c[0]), "+f"(c[1]), "+f"(c[2]), "+f"(c[3])
        : "r"(a[0]), "r"(a[1]), "r"(a[2]), "r"(a[3]), "r"(b0), "r"(b1));
}
__device__ __forceinline__ void cpasync16(uint32_t dst, const void* src) {
    asm volatile("cp.async.cg.shared.global [%0], [%1], 16;"
                 :: "r"(dst), "l"(src));
}
#define CP_COMMIT() asm volatile("cp.async.commit_group;" ::: "memory")
#define CP_WAIT(n)  asm volatile("cp.async.wait_group %0;" :: "n"(n) : "memory")

// fp16 hi/lo split of a pair
__device__ __forceinline__ __half2 splith2(float a, float b, __half2& lo) {
    __half h0 = __float2half_rn(a), h1 = __float2half_rn(b);
    lo = __halves2half2(__float2half_rn(a - __half2float(h0)),
                        __float2half_rn(b - __half2float(h1)));
    return __halves2half2(h0, h1);
}
__device__ __forceinline__ __half2 h2_rn(float a, float b) {
    return __halves2half2(__float2half_rn(a), __float2half_rn(b));
}

// ---------------------------------------------------------------------------
// mma.sync fp16 GEMM. TWOP: C = alpha * Ah @ (Bh + Bl)^T (2 products, Ah
// fragments reused); else C = alpha * Ah @ Bh^T (1 product).
//   Ah [M][ldk] fp16, Bh/Bl [N][ldk] fp16 (K-major rows).
//   128x128 CTA tile, BK=64, 128 threads (2x2 warps, 64x64 warp tiles),
//   2-stage cp.async double buffer, padded smem (SROW=72: 144B rows).
//   Split-K via blockIdx.z = b*kchunks + ks (f32 C offset by zi*sC).
//   ZDIV: row-divide by zb. OUTSPLIT: hi/lo fp16 out.
//   STATS: per-column sum/sumsq atomics. ROWSTATS: per-row sum/sumsq atomics.
// ---------------------------------------------------------------------------
#define SROW 72
#define BUFB (128u * SROW * 2u)        // 18432 B per operand tile
#define GSMEM2 (2 * 3 * BUFB + 512)    // 2 stages x (Ah,Bh,Bl) + zsm
#define GSMEM1 (2 * 2 * BUFB + 512)    // 2 stages x (Ah,Bh) + zsm

template <bool TWOP, bool ZDIV, bool OUTSPLIT, bool STATS, bool ROWSTATS>
__global__ void __launch_bounds__(128)
gemm_mma(const __half* __restrict__ Ah_, const __half* __restrict__ Bhi_,
         const __half* __restrict__ Blo_,
         float* __restrict__ C_, __half* __restrict__ Chi_,
         __half* __restrict__ Clo_,
         int N, int K, int ldk, int kchunks,
         long long sA, long long sB, long long sC,
         float alpha, const float* __restrict__ zb)
{
    extern __shared__ char smem[];
    constexpr uint32_t STB = (TWOP ? 3u : 2u) * BUFB;
    const int zi = blockIdx.z;
    const int b  = zi / kchunks;
    const int ks = zi - b * kchunks;
    const long long koff = (long long)ks * K;

    const __half* Ah = Ah_ + (long long)b * sA + koff;
    const __half* Bh = Bhi_ + (long long)b * sB + koff;
    const __half* Bl = TWOP ? (Blo_ + (long long)b * sB + koff) : nullptr;
    const int m0 = blockIdx.y << 7, n0 = blockIdx.x << 7;
    const int tid = threadIdx.x, wid = tid >> 5, lane = tid & 31;
    const int wm = wid & 1, wn = wid >> 1;
    const int tig = lane & 3, grp = lane >> 2;

    const uint32_t sb = smem_u32(smem);
    float* zsm = (float*)(smem + 2 * STB);
    if (ZDIV) zsm[tid] = 1.f / zb[(long long)b * 4096 + m0 + tid];

    const int CH = K >> 6;

    float acc[4][8][4];
#pragma unroll
    for (int i = 0; i < 4; i++)
#pragma unroll
        for (int j = 0; j < 8; j++)
#pragma unroll
            for (int t = 0; t < 4; t++) acc[i][j][t] = 0.f;

    // load operand tiles (128 rows x 64 fp16 each) for K-chunk c into stage st
    auto load = [&](int c, int st) {
        long long kp = (long long)c << 6;
        uint32_t base = sb + (uint32_t)st * STB;
#pragma unroll
        for (int i = 0; i < 8; i++) {
            int slot = tid + (i << 7);
            int row = slot >> 3, u = slot & 7;
            uint32_t d = (uint32_t)(row * (SROW * 2) + (u << 4));
            long long aoff = (long long)(m0 + row) * ldk + kp + (u << 3);
            long long boff = (long long)(n0 + row) * ldk + kp + (u << 3);
            cpasync16(base + d, Ah + aoff);
            cpasync16(base + BUFB + d, Bh + boff);
            if (TWOP) cpasync16(base + 2 * BUFB + d, Bl + boff);
        }
        CP_COMMIT();
    };

    load(0, 0);

    const uint32_t lrow16 = lane & 15;
    const uint32_t lcol8 = (lane >> 4) << 3;

    int buf = 0;
    for (int c = 0; c < CH; c++) {
        if (c + 1 < CH) { load(c + 1, buf ^ 1); CP_WAIT(1); }
        else            { CP_WAIT(0); }
        __syncthreads();

        uint32_t base = sb + (uint32_t)buf * STB;
#pragma unroll
        for (int ko2 = 0; ko2 < 4; ko2++) {
            const uint32_t ko = ko2 << 4;
            uint32_t ah[4][4], bb[4][4];
#pragma unroll
            for (int mi = 0; mi < 4; mi++) {
                uint32_t ad = base +
                    (((wm << 6) + (mi << 4) + lrow16) * SROW + ko + lcol8) * 2;
                ldsm_x4(ah[mi][0], ah[mi][1], ah[mi][2], ah[mi][3], ad);
            }
            // seg1: Ah * Bh
#pragma unroll
            for (int nb = 0; nb < 4; nb++) {
                uint32_t bd = base + BUFB +
                    (((wn << 6) + (nb << 4) + lrow16) * SROW + ko + lcol8) * 2;
                ldsm_x4(bb[nb][0], bb[nb][1], bb[nb][2], bb[nb][3], bd);
            }
#pragma unroll
            for (int mi = 0; mi < 4; mi++)
#pragma unroll
                for (int ni = 0; ni < 8; ni++) {
                    int nb = ni >> 1, hf = ni & 1;
                    mma16816(acc[mi][ni], ah[mi], bb[nb][hf], bb[nb][hf + 2]);
                }
            if (TWOP) {
                // seg2: Ah * Bl (reuse ah fragments)
#pragma unroll
                for (int nb = 0; nb < 4; nb++) {
                    uint32_t bd = base + 2 * BUFB +
                        (((wn << 6) + (nb << 4) + lrow16) * SROW + ko + lcol8) * 2;
                    ldsm_x4(bb[nb][0], bb[nb][1], bb[nb][2], bb[nb][3], bd);
                }
#pragma unroll
                for (int mi = 0; mi < 4; mi++)
#pragma unroll
                    for (int ni = 0; ni < 8; ni++) {
                        int nb = ni >> 1, hf = ni & 1;
                        mma16816(acc[mi][ni], ah[mi], bb[nb][hf], bb[nb][hf + 2]);
                    }
            }
        }
        __syncthreads();
        buf ^= 1;
    }

    // epilogue
    float* C = C_ + (long long)zi * sC;
    __half* Chi = Chi_ + (long long)b * sC;
    __half* Clo = Clo_ + (long long)b * sC;
    float cs1[8][2], cs2[8][2];
    float rs1[4][2], rs2[4][2];
    if (STATS) {
#pragma unroll
        for (int ni = 0; ni < 8; ni++) {
            cs1[ni][0] = cs1[ni][1] = 0.f;
            cs2[ni][0] = cs2[ni][1] = 0.f;
        }
    }
    if (ROWSTATS) {
#pragma unroll
        for (int mi = 0; mi < 4; mi++) {
            rs1[mi][0] = rs1[mi][1] = 0.f;
            rs2[mi][0] = rs2[mi][1] = 0.f;
        }
    }
#pragma unroll
    for (int mi = 0; mi < 4; mi++) {
        int rl = (wm << 6) + (mi << 4) + grp;
        int row = m0 + rl;
        float zr0 = 1.f, zr1 = 1.f;
        if (ZDIV) { zr0 = zsm[rl]; zr1 = zsm[rl + 8]; }
#pragma unroll
        for (int ni = 0; ni < 8; ni++) {
            int col = n0 + (wn << 6) + (ni << 3) + (tig << 1);
            float v0 = acc[mi][ni][0] * alpha;
            float v1 = acc[mi][ni][1] * alpha;
            float v2 = acc[mi][ni][2] * alpha;
            float v3 = acc[mi][ni][3] * alpha;
            if (ZDIV) { v0 *= zr0; v1 *= zr0; v2 *= zr1; v3 *= zr1; }
            if (STATS) {
                cs1[ni][0] += v0 + v2;
                cs1[ni][1] += v1 + v3;
                cs2[ni][0] += v0 * v0 + v2 * v2;
                cs2[ni][1] += v1 * v1 + v3 * v3;
            }
            if (ROWSTATS) {
                rs1[mi][0] += v0 + v1;
                rs2[mi][0] += v0 * v0 + v1 * v1;
                rs1[mi][1] += v2 + v3;
                rs2[mi][1] += v2 * v2 + v3 * v3;
            }
            if (OUTSPLIT) {
                __half2 l0, l1;
                __half2 h0 = splith2(v0, v1, l0);
                __half2 h1 = splith2(v2, v3, l1);
                *(__half2*)(Chi + (long long)row * N + col) = h0;
                *(__half2*)(Chi + (long long)(row + 8) * N + col) = h1;
                *(__half2*)(Clo + (long long)row * N + col) = l0;
                *(__half2*)(Clo + (long long)(row + 8) * N + col) = l1;
            } else {
                float2 p0; p0.x = v0; p0.y = v1;
                float2 p1; p1.x = v2; p1.y = v3;
                *(float2*)(C + (long long)row * N + col) = p0;
                *(float2*)(C + (long long)(row + 8) * N + col) = p1;
            }
        }
    }
    if (STATS) {
#pragma unroll
        for (int ni = 0; ni < 8; ni++)
#pragma unroll
            for (int h = 0; h < 2; h++) {
                float s1 = cs1[ni][h], s2 = cs2[ni][h];
                s1 += __shfl_down_sync(0xffffffffu, s1, 16);
                s2 += __shfl_down_sync(0xffffffffu, s2, 16);
                s1 += __shfl_down_sync(0xffffffffu, s1, 8);
                s2 += __shfl_down_sync(0xffffffffu, s2, 8);
                s1 += __shfl_down_sync(0xffffffffu, s1, 4);
                s2 += __shfl_down_sync(0xffffffffu, s2, 4);
                if (lane < 4) {
                    int col = n0 + (wn << 6) + (ni << 3) + (lane << 1) + h;
                    atomicAdd(&g_s1[col], s1);
                    atomicAdd(&g_s2[col], s2);
                }
            }
    }
    if (ROWSTATS) {
#pragma unroll
        for (int mi = 0; mi < 4; mi++)
#pragma unroll
            for (int h = 0; h < 2; h++) {
                float s1 = rs1[mi][h], s2 = rs2[mi][h];
                s1 += __shfl_down_sync(0xffffffffu, s1, 2, 4);
                s2 += __shfl_down_sync(0xffffffffu, s2, 2, 4);
                s1 += __shfl_down_sync(0xffffffffu, s1, 1, 4);
                s2 += __shfl_down_sync(0xffffffffu, s2, 1, 4);
                if (tig == 0) {
                    int row = m0 + (wm << 6) + (mi << 4) + grp + (h << 3);
                    atomicAdd(&g_t1[row], s1);
                    atomicAdd(&g_t2[row], s2);
                }
            }
    }
}

// ---------------------------------------------------------------------------
// vk split-K reduce -> fp16 (hi only) with alpha
// ---------------------------------------------------------------------------
__global__ void vkred_kernel()
{
    long long i4 = (long long)(blockIdx.x * 256 + threadIdx.x) * 4;
    int b = (int)(i4 >> 18);
    long long off = i4 & 262143;
    const float* p = g_vkp + ((long long)b * 4) * 262144 + off;
    float4 s0 = *(const float4*)p;
    float4 s1 = *(const float4*)(p + 262144);
    float4 s2 = *(const float4*)(p + 2 * 262144);
    float4 s3 = *(const float4*)(p + 3 * 262144);
    const float al = 1.f / 4096.f;
    float v0 = ((s0.x + s1.x) + (s2.x + s3.x)) * al;
    float v1 = ((s0.y + s1.y) + (s2.y + s3.y)) * al;
    float v2 = ((s0.z + s1.z) + (s2.z + s3.z)) * al;
    float v3 = ((s0.w + s1.w) + (s2.w + s3.w)) * al;
    *(__half2*)(g_vkhi + i4)     = h2_rn(v0, v1);
    *(__half2*)(g_vkhi + i4 + 2) = h2_rn(v2, v3);
}

// ---------------------------------------------------------------------------
__global__ void zero_kernel()
{
    int i = blockIdx.x * 256 + threadIdx.x;
    if (i < 2048) { g_s1[i] = 0.f; g_s2[i] = 0.f; }
    if (i < 512)  { g_t1[i] = 0.f; g_t2[i] = 0.f; }
    if (i < 4096) g_ksum[i] = 0.f;
}

__global__ void bn1_finalize(const float* __restrict__ gamma,
                             const float* __restrict__ beta)
{
    int c = blockIdx.x * 256 + threadIdx.x;
    const float inv = 1.f / (BATCH * NPIX);
    float mean = g_s1[c] * inv;
    float var = g_s2[c] * inv - mean * mean;
    float av = gamma[c] * rsqrtf(var + 1e-5f);
    g_a1[c] = av;
    g_b1[c] = beta[c] - mean * av;
}

__global__ void bn2_finalize(const float* __restrict__ gamma,
                             const float* __restrict__ beta)
{
    int c = blockIdx.x * 256 + threadIdx.x;
    const float inv = 1.f / (BATCH * NPIX);
    float mean = g_t1[c] * inv;
    float var = g_t2[c] * inv - mean * mean;
    float av = gamma[c] * rsqrtf(var + 1e-5f);
    g_a2[c] = av;
    g_b2[c] = beta[c] - mean * av;
}

// q: sigmoid(affine(y[:, 0:512])) -> q^T fp16 (hi only; A operand)
__global__ void q_kernel()
{
    int i = blockIdx.x * 256 + threadIdx.x;
    int r = i >> 7;
    int dg = (i & 127) << 2;
    long long yb = (long long)r * C4 + dg;
    __half2 yh0 = *(const __half2*)(g_ythi + yb);
    __half2 yh1 = *(const __half2*)(g_ythi + yb + 2);
    __half2 yl0 = *(const __half2*)(g_ytlo + yb);
    __half2 yl1 = *(const __half2*)(g_ytlo + yb + 2);
    float4 a4 = *(const float4*)(g_a1 + dg);
    float4 b4 = *(const float4*)(g_b1 + dg);
    float y0 = __half2float(yh0.x) + __half2float(yl0.x);
    float y1 = __half2float(yh0.y) + __half2float(yl0.y);
    float y2 = __half2float(yh1.x) + __half2float(yl1.x);
    float y3 = __half2float(yh1.y) + __half2float(yl1.y);
    float q0 = 1.f / (1.f + expf(-(a4.x * y0 + b4.x)));
    float q1 = 1.f / (1.f + expf(-(a4.y * y1 + b4.y)));
    float q2 = 1.f / (1.f + expf(-(a4.z * y2 + b4.z)));
    float q3 = 1.f / (1.f + expf(-(a4.w * y3 + b4.w)));
    long long o = (long long)r * DIM + dg;
    *(__half2*)(g_qthi + o)     = h2_rn(q0, q1);
    *(__half2*)(g_qthi + o + 2) = h2_rn(q2, q3);
}

// k,v: 64x64 transpose y^T -> [b][d][n]; k hi fp16, v hi fp16, ksum
__global__ void kvt_kernel()
{
    __shared__ float tk[64][65], tv[64][65];
    int bz = blockIdx.z;
    int n0 = blockIdx.x << 6, d0 = blockIdx.y << 6;
    int tx = threadIdx.x, ty = threadIdx.y;
    int dloc = tx << 1;
    float2 akp = *(const float2*)(g_a1 + 512 + d0 + dloc);
    float2 bkp = *(const float2*)(g_b1 + 512 + d0 + dloc);
    float2 avp = *(const float2*)(g_a1 + 1024 + d0 + dloc);
    float2 bvp = *(const float2*)(g_b1 + 1024 + d0 + dloc);
#pragma unroll
    for (int i = 0; i < 8; i++) {
        int nl = ty + (i << 3);
        long long rb = ((long long)(bz << 12) + n0 + nl) * C4;
        __half2 kh2 = *(const __half2*)(g_ythi + rb + 512 + d0 + dloc);
        __half2 kl2 = *(const __half2*)(g_ytlo + rb + 512 + d0 + dloc);
        __half2 vh2 = *(const __half2*)(g_ythi + rb + 1024 + d0 + dloc);
        __half2 vl2 = *(const __half2*)(g_ytlo + rb + 1024 + d0 + dloc);
        float k0 = __half2float(kh2.x) + __half2float(kl2.x);
        float k1 = __half2float(kh2.y) + __half2float(kl2.y);
        float v0 = __half2float(vh2.x) + __half2float(vl2.x);
        float v1 = __half2float(vh2.y) + __half2float(vl2.y);
        tk[nl][dloc]     = 1.f / (1.f + expf(-(akp.x * k0 + bkp.x)));
        tk[nl][dloc + 1] = 1.f / (1.f + expf(-(akp.y * k1 + bkp.y)));
        tv[nl][dloc]     = avp.x * v0 + bvp.x;
        tv[nl][dloc + 1] = avp.y * v1 + bvp.y;
    }
    __syncthreads();
#pragma unroll
    for (int i = 0; i < 8; i++) {
        int dl = ty + (i << 3);
        int d = d0 + dl;
        int nl = tx << 1;
        float k0 = tk[nl][dl], k1 = tk[nl + 1][dl];
        float v0 = tv[nl][dl], v1 = tv[nl + 1][dl];
        long long o = ((long long)(bz << 9) + d) * NPIX + n0 + nl;
        *(__half2*)(g_khi + o) = h2_rn(k0, k1);
        *(__half2*)(g_vhi + o) = h2_rn(v0, v1);
        float s = k0 + k1;
#pragma unroll
        for (int off = 16; off > 0; off >>= 1)
            s += __shfl_down_sync(0xffffffffu, s, off);
        if (tx == 0) atomicAdd(&g_ksum[(bz << 9) + d], s);
    }
}

// z[r] = sum_d kmean[d] * q[r][d] + eps
__global__ void z_kernel()
{
    __shared__ float km[512];
    int r0 = blockIdx.x << 3;
    int bb = r0 >> 12;
    for (int i = threadIdx.x; i < 512; i += 256)
        km[i] = g_ksum[(bb << 9) + i] * (1.f / NPIX);
    __syncthreads();
    int w = threadIdx.x >> 5, lane = threadIdx.x & 31;
    int r = r0 + w;
    const __half* qh = g_qthi + (long long)r * DIM;
    float s = 0.f;
#pragma unroll
    for (int i = 0; i < 16; i++) {
        int d = lane + (i << 5);
        s += km[d] * __half2float(qh[d]);
    }
#pragma unroll
    for (int off = 16; off > 0; off >>= 1)
        s += __shfl_down_sync(0xffffffffu, s, off);
    if (lane == 0) g_z[r] = s + 5e-4f;
}

// RMSNorm row + anw + SiLU(gate) -> o^T hi/lo fp16
__global__ void rmsgate_kernel(const float* __restrict__ anw)
{
    __shared__ float red[4];
    int r = blockIdx.x;
    int t = threadIdx.x;
    int dg = t << 2;
    long long arow = (long long)r * DIM + dg;
    __half2 ah0 = *(const __half2*)(g_athi + arow);
    __half2 ah1 = *(const __half2*)(g_athi + arow + 2);
    __half2 al0 = *(const __half2*)(g_atlo + arow);
    __half2 al1 = *(const __half2*)(g_atlo + arow + 2);
    float a0 = __half2float(ah0.x) + __half2float(al0.x);
    float a1 = __half2float(ah0.y) + __half2float(al0.y);
    float a2 = __half2float(ah1.x) + __half2float(al1.x);
    float a3 = __half2float(ah1.y) + __half2float(al1.y);
    float ss = a0 * a0 + a1 * a1 + a2 * a2 + a3 * a3;
    int lane = t & 31, w = t >> 5;
#pragma unroll
    for (int off = 16; off > 0; off >>= 1)
        ss += __shfl_down_sync(0xffffffffu, ss, off);
    if (lane == 0) red[w] = ss;
    __syncthreads();
    float tot = red[0] + red[1] + red[2] + red[3];
    float rms = rsqrtf(tot * (1.f / DIM) + 1e-6f);

    long long grow = (long long)r * C4 + 1536 + dg;
    __half2 gh0 = *(const __half2*)(g_ythi + grow);
    __half2 gh1 = *(const __half2*)(g_ythi + grow + 2);
    __half2 gl0 = *(const __half2*)(g_ytlo + grow);
    __half2 gl1 = *(const __half2*)(g_ytlo + grow + 2);
    float yg0 = __half2float(gh0.x) + __half2float(gl0.x);
    float yg1 = __half2float(gh0.y) + __half2float(gl0.y);
    float yg2 = __half2float(gh1.x) + __half2float(gl1.x);
    float yg3 = __half2float(gh1.y) + __half2float(gl1.y);
    float4 ga = *(const float4*)(g_a1 + 1536 + dg);
    float4 gb = *(const float4*)(g_b1 + 1536 + dg);
    float4 wn = *(const float4*)(anw + dg);
    float g0 = ga.x * yg0 + gb.x, g1 = ga.y * yg1 + gb.y;
    float g2 = ga.z * yg2 + gb.z, g3 = ga.w * yg3 + gb.w;
    float o0 = a0 * rms * wn.x * (g0 / (1.f + expf(-g0)));
    float o1 = a1 * rms * wn.y * (g1 / (1.f + expf(-g1)));
    float o2 = a2 * rms * wn.z * (g2 / (1.f + expf(-g2)));
    float o3 = a3 * rms * wn.w * (g3 / (1.f + expf(-g3)));
    __half2 l0, l1;
    __half2 h0 = splith2(o0, o1, l0);
    __half2 h1 = splith2(o2, o3, l1);
    long long o = (long long)r * DIM + dg;
    *(__half2*)(g_othi + o)     = h0;
    *(__half2*)(g_othi + o + 2) = h1;
    *(__half2*)(g_otlo + o)     = l0;
    *(__half2*)(g_otlo + o + 2) = l1;
}

__global__ void bnapply_kernel(float* __restrict__ out)
{
    long long i = (long long)(blockIdx.x * blockDim.x + threadIdx.x) * 4;
    int c = (int)((i >> 12) & 511);
    float a = g_a2[c], bb = g_b2[c];
    float4 v = *reinterpret_cast<const float4*>(g_ypre + i);
    v.x = a * v.x + bb; v.y = a * v.y + bb;
    v.z = a * v.z + bb; v.w = a * v.w + bb;
    *reinterpret_cast<float4*>(out + i) = v;
}

// f32 -> fp16 hi/lo
__global__ void convert_split(const float* __restrict__ s,
                              __half* __restrict__ hi,
                              __half* __restrict__ lo, int n)
{
    int i = blockIdx.x * blockDim.x + threadIdx.x;
    if (i < n) {
        float v = s[i];
        __half h = __float2half_rn(v);
        hi[i] = h;
        lo[i] = __float2half_rn(v - __half2float(h));
    }
}

// f32 -> fp16 (hi only)
__global__ void convert_half(const float* __restrict__ s,
                             __half* __restrict__ hi, int n)
{
    int i = blockIdx.x * blockDim.x + threadIdx.x;
    if (i < n) hi[i] = __float2half_rn(s[i]);
}

// transpose f32 src [b][R][Cc] -> fp16 hi-only dst [b][Cc][R]
__global__ void transpose_half(const float* __restrict__ src,
                               __half* __restrict__ dhi, int R, int Cc)
{
    __shared__ float t[32][33];
    int b = blockIdx.z;
    long long o = (long long)b * R * Cc;
    src += o; dhi += o;
    int c0 = blockIdx.x * 32, r0 = blockIdx.y * 32;
    int tx = threadIdx.x, ty = threadIdx.y;
#pragma unroll
    for (int i = 0; i < 4; i++)
        t[ty + 8 * i][tx] = src[(long long)(r0 + ty + 8 * i) * Cc + c0 + tx];
    __syncthreads();
#pragma unroll
    for (int i = 0; i < 4; i++) {
        int cc = c0 + ty + 8 * i;
        dhi[(long long)cc * R + r0 + tx] = __float2half_rn(t[tx][ty + 8 * i]);
    }
}

// ---------------------------------------------------------------------------
extern "C" void kernel_launch(void* const* d_in, const int* in_sizes, int n_in,
                              void* d_out, int out_size)
{
    const float* x           = (const float*)d_in[0];
    const float* qkvg_w      = (const float*)d_in[1];
    const float* qkvg_gamma  = (const float*)d_in[2];
    const float* qkvg_beta   = (const float*)d_in[3];
    const float* attn_norm_w = (const float*)d_in[4];
    const float* proj_w      = (const float*)d_in[5];
    const float* proj_gamma  = (const float*)d_in[6];
    const float* proj_beta   = (const float*)d_in[7];
    float* out = (float*)d_out;

    cudaFuncSetAttribute(gemm_mma<true, false, true, true, false>,
                         cudaFuncAttributeMaxDynamicSharedMemorySize, GSMEM2);
    cudaFuncSetAttribute(gemm_mma<false, false, false, false, false>,
                         cudaFuncAttributeMaxDynamicSharedMemorySize, GSMEM1);
    cudaFuncSetAttribute(gemm_mma<false, true, true, false, false>,
                         cudaFuncAttributeMaxDynamicSharedMemorySize, GSMEM1);
    cudaFuncSetAttribute(gemm_mma<true, false, false, false, true>,
                         cudaFuncAttributeMaxDynamicSharedMemorySize, GSMEM2);

    float *pypre, *pvkp, *pz;
    __half *pythi, *pytlo, *pathi, *patlo;
    __half *pkhi, *pvhi, *pqthi, *pxthi;
    __half *pothi, *potlo, *pvkhi, *pwqhi, *pwqlo, *ppwhi;
    cudaGetSymbolAddress((void**)&pythi, g_ythi);
    cudaGetSymbolAddress((void**)&pytlo, g_ytlo);
    cudaGetSymbolAddress((void**)&pathi, g_athi);
    cudaGetSymbolAddress((void**)&patlo, g_atlo);
    cudaGetSymbolAddress((void**)&pypre, g_ypre);
    cudaGetSymbolAddress((void**)&pvkp,  g_vkp);
    cudaGetSymbolAddress((void**)&pz,    g_z);
    cudaGetSymbolAddress((void**)&pkhi,  g_khi);
    cudaGetSymbolAddress((void**)&pvhi,  g_vhi);
    cudaGetSymbolAddress((void**)&pqthi, g_qthi);
    cudaGetSymbolAddress((void**)&pxthi, g_xthi);
    cudaGetSymbolAddress((void**)&pothi, g_othi);
    cudaGetSymbolAddress((void**)&potlo, g_otlo);
    cudaGetSymbolAddress((void**)&pvkhi, g_vkhi);
    cudaGetSymbolAddress((void**)&pwqhi, g_wqhi);
    cudaGetSymbolAddress((void**)&pwqlo, g_wqlo);
    cudaGetSymbolAddress((void**)&ppwhi, g_pwhi);

    const long long sQKV = (long long)DIM * NPIX;   // 2097152
    const long long sYT  = (long long)NPIX * C4;    // 8388608
    const long long sVK  = (long long)DIM * DIM;    // 262144

    zero_kernel<<<32, 256>>>();
    convert_split<<<4096, 256>>>(qkvg_w, pwqhi, pwqlo, C4 * DIM);
    convert_half<<<1024, 256>>>(proj_w, ppwhi, DIM * DIM);
    transpose_half<<<dim3(128, 16, BATCH), dim3(32, 8)>>>(x, pxthi, DIM, NPIX);

    // 1) y^T = x^T @ w^T (2-product) -> fp16 hi/lo + fused BN1 column stats
    gemm_mma<true, false, true, true, false><<<dim3(16, 32, BATCH), 128, GSMEM2>>>(
        pxthi, pwqhi, pwqlo, nullptr, pythi, pytlo,
        2048, 512, 512, 1, sQKV, 0, sYT, 1.f, nullptr);

    // 2) BN1 finalize
    bn1_finalize<<<8, 256>>>(qkvg_gamma, qkvg_beta);

    // 3) q^T fp16; k hi + v hi -> [d][n] + ksum
    q_kernel<<<16384, 256>>>();
    kvt_kernel<<<dim3(64, 8, BATCH), dim3(32, 8)>>>();

    // 4) z
    z_kernel<<<4096, 256>>>();

    // 5) vk = v @ k^T (1-product), split-K x4; reduce -> fp16 hi
    gemm_mma<false, false, false, false, false><<<dim3(4, 4, BATCH * 4), 128, GSMEM1>>>(
        pvhi, pkhi, nullptr, pvkp, nullptr, nullptr,
        512, 1024, 4096, 4, sQKV, sQKV, sVK, 1.f, nullptr);
    vkred_kernel<<<2048, 256>>>();

    // 6) attn^T = q^T @ vk^T / z (1-product) -> hi/lo fp16
    gemm_mma<false, true, true, false, false><<<dim3(4, 32, BATCH), 128, GSMEM1>>>(
        pqthi, pvkhi, nullptr, nullptr, pathi, patlo,
        512, 512, 512, 1, sQKV, sVK, sQKV, 1.f, pz);

    // 7) RMSNorm + gate -> o^T hi/lo
    rmsgate_kernel<<<32768, 128>>>(attn_norm_w);

    // 8) ypre = proj_w @ o (2-product) + fused BN2 row stats
    gemm_mma<true, false, false, false, true><<<dim3(32, 4, BATCH), 128, GSMEM2>>>(
        ppwhi, pothi, potlo, pypre, nullptr, nullptr,
        4096, 512, 512, 1, 0, sQKV, sQKV, 1.f, nullptr);

    // 9) BN2 finalize + apply
    bn2_finalize<<<2, 256>>>(proj_gamma, proj_beta);
    bnapply_kernel<<<16384, 256>>>(out);
}

// round 14
// speedup vs baseline: 2.4607x; 1.2859x over previous
#include <cuda_runtime.h>
#include <cuda_fp16.h>
#include <math.h>
#include <stdint.h>

// ---------------------------------------------------------------------------
// SHMA block: pure fp16 mma.sync GEMMs (fp32 accum), BK=64, n-major
// dataflow. Accuracy anchors: y and attn kept as fp16 hi/lo pairs; BN
// stats computed in f32 from GEMM accumulators (fused epilogues).
// B=8, dim=d=512, N=4096, qkvg=2048.
// ---------------------------------------------------------------------------

#define BATCH 8
#define DIM   512
#define NPIX  4096
#define C4    2048

// ---------------- scratch (static device globals) --------------------------
__device__ __half g_ythi[67108864], g_ytlo[67108864]; // y^T (8*4096,2048)
__device__ __half g_athi[16777216], g_atlo[16777216]; // attn^T (8*4096,512)
__device__ float g_ypre[16777216];                    // ypre (8, 512, 4096) f32
__device__ float g_vkp[8388608];                      // vk split-K partials
__device__ __half g_khi[16777216];                    // k [b][d][n]
__device__ __half g_vhi[16777216];                    // v [b][d][n]
__device__ __half g_qthi[16777216];                   // q^T [b][n][d]
__device__ __half g_xthi[16777216];                   // x^T [b][n][c]
__device__ __half g_othi[16777216];                   // o^T [b][n][d]
__device__ __half g_vkhi[2097152];                    // vk [b][d][e]
__device__ __half g_wqhi[1048576];                    // qkvg_w
__device__ __half g_pwhi[262144];                     // proj_w
__device__ float g_a1[2048], g_b1[2048], g_a2[512], g_b2[512];
__device__ float g_s1[2048], g_s2[2048];              // BN1 accum
__device__ float g_t1[512], g_t2[512];                // BN2 accum
__device__ float g_ksum[4096], g_z[32768];

// ---------------- helpers ---------------------------------------------------
__device__ __forceinline__ uint32_t smem_u32(const void* p) {
    uint32_t a;
    asm("{ .reg .u64 t; cvta.to.shared.u64 t, %1; cvt.u32.u64 %0, t; }"
        : "=r"(a) : "l"(p));
    return a;
}
__device__ __forceinline__ void ldsm_x4(uint32_t& r0, uint32_t& r1,
                                        uint32_t& r2, uint32_t& r3,
                                        uint32_t addr) {
    asm volatile("ldmatrix.sync.aligned.m8n8.x4.shared.b16 {%0,%1,%2,%3}, [%4];"
                 : "=r"(r0), "=r"(r1), "=r"(r2), "=r"(r3) : "r"(addr));
}
__device__ __forceinline__ void mma16816(float* c, const uint32_t* a,
                                         uint32_t b0, uint32_t b1) {
    asm volatile(
        "mma.sync.aligned.m16n8k16.row.col.f32.f16.f16.f32 "
        "{%0,%1,%2,%3}, {%4,%5,%6,%7}, {%8,%9}, {%0,%1,%2,%3};"
        : "+f"(c[0]), "+f"(c[1]), "+f"(c[2]), "+f"(c[3])
        : "r"(a[0]), "r"(a[1]), "r"(a[2]), "r"(a[3]), "r"(b0), "r"(b1));
}
__device__ __forceinline__ void cpasync16(uint32_t dst, const void* src) {
    asm volatile("cp.async.cg.shared.global [%0], [%1], 16;"
                 :: "r"(dst), "l"(src));
}
#define CP_COMMIT() asm volatile("cp.async.commit_group;" ::: "memory")
#define CP_WAIT(n)  asm volatile("cp.async.wait_group %0;" :: "n"(n) : "memory")

// fp16 hi/lo split of a pair
__device__ __forceinline__ __half2 splith2(float a, float b, __half2& lo) {
    __half h0 = __float2half_rn(a), h1 = __float2half_rn(b);
    lo = __halves2half2(__float2half_rn(a - __half2float(h0)),
                        __float2half_rn(b - __half2float(h1)));
    return __halves2half2(h0, h1);
}
__device__ __forceinline__ __half2 h2_rn(float a, float b) {
    return __halves2half2(__float2half_rn(a), __float2half_rn(b));
}

// ---------------------------------------------------------------------------
// mma.sync fp16 GEMM: C = alpha * A @ B^T (fp32 accum).
//   A [M][ldk] fp16, B [N][ldk] fp16 (K-major rows).
//   128x128 CTA tile, BK=64, 128 threads (2x2 warps, 64x64 warp tiles),
//   2-stage cp.async double buffer, padded smem (SROW=72: 144B rows).
//   Split-K via blockIdx.z = b*kchunks + ks (f32 C offset by zi*sC).
//   ZDIV: row-divide by zb. OUTSPLIT: hi/lo fp16 out.
//   STATS: per-column sum/sumsq atomics. ROWSTATS: per-row sum/sumsq atomics.
// ---------------------------------------------------------------------------
#define SROW 72
#define BUFB (128u * SROW * 2u)        // 18432 B per operand tile
#define GSMEM (2 * 2 * BUFB + 512)     // 2 stages x (A,B) + zsm

template <bool ZDIV, bool OUTSPLIT, bool STATS, bool ROWSTATS>
__global__ void __launch_bounds__(128)
gemm_mma(const __half* __restrict__ A_, const __half* __restrict__ B_,
         float* __restrict__ C_, __half* __restrict__ Chi_,
         __half* __restrict__ Clo_,
         int N, int K, int ldk, int kchunks,
         long long sA, long long sB, long long sC,
         float alpha, const float* __restrict__ zb)
{
    extern __shared__ char smem[];
    const int zi = blockIdx.z;
    const int b  = zi / kchunks;
    const int ks = zi - b * kchunks;
    const long long koff = (long long)ks * K;

    const __half* A = A_ + (long long)b * sA + koff;
    const __half* B = B_ + (long long)b * sB + koff;
    const int m0 = blockIdx.y << 7, n0 = blockIdx.x << 7;
    const int tid = threadIdx.x, wid = tid >> 5, lane = tid & 31;
    const int wm = wid & 1, wn = wid >> 1;
    const int tig = lane & 3, grp = lane >> 2;

    const uint32_t sb = smem_u32(smem);
    float* zsm = (float*)(smem + 4 * BUFB);
    if (ZDIV) zsm[tid] = 1.f / zb[(long long)b * 4096 + m0 + tid];

    const int CH = K >> 6;

    float acc[4][8][4];
#pragma unroll
    for (int i = 0; i < 4; i++)
#pragma unroll
        for (int j = 0; j < 8; j++)
#pragma unroll
            for (int t = 0; t < 4; t++) acc[i][j][t] = 0.f;

    // load A,B tiles (128 rows x 64 fp16 each) for K-chunk c into stage st
    auto load = [&](int c, int st) {
        long long kp = (long long)c << 6;
        uint32_t base = sb + (uint32_t)st * (2u * BUFB);
#pragma unroll
        for (int i = 0; i < 8; i++) {
            int slot = tid + (i << 7);
            int row = slot >> 3, u = slot & 7;
            uint32_t d = (uint32_t)(row * (SROW * 2) + (u << 4));
            cpasync16(base + d, A + (long long)(m0 + row) * ldk + kp + (u << 3));
            cpasync16(base + BUFB + d,
                      B + (long long)(n0 + row) * ldk + kp + (u << 3));
        }
        CP_COMMIT();
    };

    load(0, 0);

    const uint32_t lrow16 = lane & 15;
    const uint32_t lcol8 = (lane >> 4) << 3;

    int buf = 0;
    for (int c = 0; c < CH; c++) {
        if (c + 1 < CH) { load(c + 1, buf ^ 1); CP_WAIT(1); }
        else            { CP_WAIT(0); }
        __syncthreads();

        uint32_t base = sb + (uint32_t)buf * (2u * BUFB);
#pragma unroll
        for (int ko2 = 0; ko2 < 4; ko2++) {
            const uint32_t ko = ko2 << 4;
            uint32_t a[4][4], bb[4][4];
#pragma unroll
            for (int mi = 0; mi < 4; mi++) {
                uint32_t ad = base +
                    (((wm << 6) + (mi << 4) + lrow16) * SROW + ko + lcol8) * 2;
                ldsm_x4(a[mi][0], a[mi][1], a[mi][2], a[mi][3], ad);
            }
#pragma unroll
            for (int nb = 0; nb < 4; nb++) {
                uint32_t bd = base + BUFB +
                    (((wn << 6) + (nb << 4) + lrow16) * SROW + ko + lcol8) * 2;
                ldsm_x4(bb[nb][0], bb[nb][1], bb[nb][2], bb[nb][3], bd);
            }
#pragma unroll
            for (int mi = 0; mi < 4; mi++)
#pragma unroll
                for (int ni = 0; ni < 8; ni++) {
                    int nb = ni >> 1, hf = ni & 1;
                    mma16816(acc[mi][ni], a[mi], bb[nb][hf], bb[nb][hf + 2]);
                }
        }
        __syncthreads();
        buf ^= 1;
    }

    // epilogue
    float* C = C_ + (long long)zi * sC;
    __half* Chi = Chi_ + (long long)b * sC;
    __half* Clo = Clo_ + (long long)b * sC;
    float cs1[8][2], cs2[8][2];
    float rs1[4][2], rs2[4][2];
    if (STATS) {
#pragma unroll
        for (int ni = 0; ni < 8; ni++) {
            cs1[ni][0] = cs1[ni][1] = 0.f;
            cs2[ni][0] = cs2[ni][1] = 0.f;
        }
    }
    if (ROWSTATS) {
#pragma unroll
        for (int mi = 0; mi < 4; mi++) {
            rs1[mi][0] = rs1[mi][1] = 0.f;
            rs2[mi][0] = rs2[mi][1] = 0.f;
        }
    }
#pragma unroll
    for (int mi = 0; mi < 4; mi++) {
        int rl = (wm << 6) + (mi << 4) + grp;
        int row = m0 + rl;
        float zr0 = 1.f, zr1 = 1.f;
        if (ZDIV) { zr0 = zsm[rl]; zr1 = zsm[rl + 8]; }
#pragma unroll
        for (int ni = 0; ni < 8; ni++) {
            int col = n0 + (wn << 6) + (ni << 3) + (tig << 1);
            float v0 = acc[mi][ni][0] * alpha;
            float v1 = acc[mi][ni][1] * alpha;
            float v2 = acc[mi][ni][2] * alpha;
            float v3 = acc[mi][ni][3] * alpha;
            if (ZDIV) { v0 *= zr0; v1 *= zr0; v2 *= zr1; v3 *= zr1; }
            if (STATS) {
                cs1[ni][0] += v0 + v2;
                cs1[ni][1] += v1 + v3;
                cs2[ni][0] += v0 * v0 + v2 * v2;
                cs2[ni][1] += v1 * v1 + v3 * v3;
            }
            if (ROWSTATS) {
                rs1[mi][0] += v0 + v1;
                rs2[mi][0] += v0 * v0 + v1 * v1;
                rs1[mi][1] += v2 + v3;
                rs2[mi][1] += v2 * v2 + v3 * v3;
            }
            if (OUTSPLIT) {
                __half2 l0, l1;
                __half2 h0 = splith2(v0, v1, l0);
                __half2 h1 = splith2(v2, v3, l1);
                *(__half2*)(Chi + (long long)row * N + col) = h0;
                *(__half2*)(Chi + (long long)(row + 8) * N + col) = h1;
                *(__half2*)(Clo + (long long)row * N + col) = l0;
                *(__half2*)(Clo + (long long)(row + 8) * N + col) = l1;
            } else {
                float2 p0; p0.x = v0; p0.y = v1;
                float2 p1; p1.x = v2; p1.y = v3;
                *(float2*)(C + (long long)row * N + col) = p0;
                *(float2*)(C + (long long)(row + 8) * N + col) = p1;
            }
        }
    }
    if (STATS) {
#pragma unroll
        for (int ni = 0; ni < 8; ni++)
#pragma unroll
            for (int h = 0; h < 2; h++) {
                float s1 = cs1[ni][h], s2 = cs2[ni][h];
                s1 += __shfl_down_sync(0xffffffffu, s1, 16);
                s2 += __shfl_down_sync(0xffffffffu, s2, 16);
                s1 += __shfl_down_sync(0xffffffffu, s1, 8);
                s2 += __shfl_down_sync(0xffffffffu, s2, 8);
                s1 += __shfl_down_sync(0xffffffffu, s1, 4);
                s2 += __shfl_down_sync(0xffffffffu, s2, 4);
                if (lane < 4) {
                    int col = n0 + (wn << 6) + (ni << 3) + (lane << 1) + h;
                    atomicAdd(&g_s1[col], s1);
                    atomicAdd(&g_s2[col], s2);
                }
            }
    }
    if (ROWSTATS) {
#pragma unroll
        for (int mi = 0; mi < 4; mi++)
#pragma unroll
            for (int h = 0; h < 2; h++) {
                float s1 = rs1[mi][h], s2 = rs2[mi][h];
                s1 += __shfl_down_sync(0xffffffffu, s1, 2, 4);
                s2 += __shfl_down_sync(0xffffffffu, s2, 2, 4);
                s1 += __shfl_down_sync(0xffffffffu, s1, 1, 4);
                s2 += __shfl_down_sync(0xffffffffu, s2, 1, 4);
                if (tig == 0) {
                    int row = m0 + (wm << 6) + (mi << 4) + grp + (h << 3);
                    atomicAdd(&g_t1[row], s1);
                    atomicAdd(&g_t2[row], s2);
                }
            }
    }
}

// ---------------------------------------------------------------------------
// vk split-K reduce -> fp16 (hi only) with alpha
// ---------------------------------------------------------------------------
__global__ void vkred_kernel()
{
    long long i4 = (long long)(blockIdx.x * 256 + threadIdx.x) * 4;
    int b = (int)(i4 >> 18);
    long long off = i4 & 262143;
    const float* p = g_vkp + ((long long)b * 4) * 262144 + off;
    float4 s0 = *(const float4*)p;
    float4 s1 = *(const float4*)(p + 262144);
    float4 s2 = *(const float4*)(p + 2 * 262144);
    float4 s3 = *(const float4*)(p + 3 * 262144);
    const float al = 1.f / 4096.f;
    float v0 = ((s0.x + s1.x) + (s2.x + s3.x)) * al;
    float v1 = ((s0.y + s1.y) + (s2.y + s3.y)) * al;
    float v2 = ((s0.z + s1.z) + (s2.z + s3.z)) * al;
    float v3 = ((s0.w + s1.w) + (s2.w + s3.w)) * al;
    *(__half2*)(g_vkhi + i4)     = h2_rn(v0, v1);
    *(__half2*)(g_vkhi + i4 + 2) = h2_rn(v2, v3);
}

// ---------------------------------------------------------------------------
__global__ void zero_kernel()
{
    int i = blockIdx.x * 256 + threadIdx.x;
    if (i < 2048) { g_s1[i] = 0.f; g_s2[i] = 0.f; }
    if (i < 512)  { g_t1[i] = 0.f; g_t2[i] = 0.f; }
    if (i < 4096) g_ksum[i] = 0.f;
}

__global__ void bn1_finalize(const float* __restrict__ gamma,
                             const float* __restrict__ beta)
{
    int c = blockIdx.x * 256 + threadIdx.x;
    const float inv = 1.f / (BATCH * NPIX);
    float mean = g_s1[c] * inv;
    float var = g_s2[c] * inv - mean * mean;
    float av = gamma[c] * rsqrtf(var + 1e-5f);
    g_a1[c] = av;
    g_b1[c] = beta[c] - mean * av;
}

__global__ void bn2_finalize(const float* __restrict__ gamma,
                             const float* __restrict__ beta)
{
    int c = blockIdx.x * 256 + threadIdx.x;
    const float inv = 1.f / (BATCH * NPIX);
    float mean = g_t1[c] * inv;
    float var = g_t2[c] * inv - mean * mean;
    float av = gamma[c] * rsqrtf(var + 1e-5f);
    g_a2[c] = av;
    g_b2[c] = beta[c] - mean * av;
}

// q: sigmoid(affine(y[:, 0:512])) -> q^T fp16
__global__ void q_kernel()
{
    int i = blockIdx.x * 256 + threadIdx.x;
    int r = i >> 7;
    int dg = (i & 127) << 2;
    long long yb = (long long)r * C4 + dg;
    __half2 yh0 = *(const __half2*)(g_ythi + yb);
    __half2 yh1 = *(const __half2*)(g_ythi + yb + 2);
    __half2 yl0 = *(const __half2*)(g_ytlo + yb);
    __half2 yl1 = *(const __half2*)(g_ytlo + yb + 2);
    float4 a4 = *(const float4*)(g_a1 + dg);
    float4 b4 = *(const float4*)(g_b1 + dg);
    float y0 = __half2float(yh0.x) + __half2float(yl0.x);
    float y1 = __half2float(yh0.y) + __half2float(yl0.y);
    float y2 = __half2float(yh1.x) + __half2float(yl1.x);
    float y3 = __half2float(yh1.y) + __half2float(yl1.y);
    float q0 = 1.f / (1.f + expf(-(a4.x * y0 + b4.x)));
    float q1 = 1.f / (1.f + expf(-(a4.y * y1 + b4.y)));
    float q2 = 1.f / (1.f + expf(-(a4.z * y2 + b4.z)));
    float q3 = 1.f / (1.f + expf(-(a4.w * y3 + b4.w)));
    long long o = (long long)r * DIM + dg;
    *(__half2*)(g_qthi + o)     = h2_rn(q0, q1);
    *(__half2*)(g_qthi + o + 2) = h2_rn(q2, q3);
}

// k,v: 64x64 transpose y^T -> [b][d][n]; k hi fp16, v hi fp16, ksum
__global__ void kvt_kernel()
{
    __shared__ float tk[64][65], tv[64][65];
    int bz = blockIdx.z;
    int n0 = blockIdx.x << 6, d0 = blockIdx.y << 6;
    int tx = threadIdx.x, ty = threadIdx.y;
    int dloc = tx << 1;
    float2 akp = *(const float2*)(g_a1 + 512 + d0 + dloc);
    float2 bkp = *(const float2*)(g_b1 + 512 + d0 + dloc);
    float2 avp = *(const float2*)(g_a1 + 1024 + d0 + dloc);
    float2 bvp = *(const float2*)(g_b1 + 1024 + d0 + dloc);
#pragma unroll
    for (int i = 0; i < 8; i++) {
        int nl = ty + (i << 3);
        long long rb = ((long long)(bz << 12) + n0 + nl) * C4;
        __half2 kh2 = *(const __half2*)(g_ythi + rb + 512 + d0 + dloc);
        __half2 kl2 = *(const __half2*)(g_ytlo + rb + 512 + d0 + dloc);
        __half2 vh2 = *(const __half2*)(g_ythi + rb + 1024 + d0 + dloc);
        __half2 vl2 = *(const __half2*)(g_ytlo + rb + 1024 + d0 + dloc);
        float k0 = __half2float(kh2.x) + __half2float(kl2.x);
        float k1 = __half2float(kh2.y) + __half2float(kl2.y);
        float v0 = __half2float(vh2.x) + __half2float(vl2.x);
        float v1 = __half2float(vh2.y) + __half2float(vl2.y);
        tk[nl][dloc]     = 1.f / (1.f + expf(-(akp.x * k0 + bkp.x)));
        tk[nl][dloc + 1] = 1.f / (1.f + expf(-(akp.y * k1 + bkp.y)));
        tv[nl][dloc]     = avp.x * v0 + bvp.x;
        tv[nl][dloc + 1] = avp.y * v1 + bvp.y;
    }
    __syncthreads();
#pragma unroll
    for (int i = 0; i < 8; i++) {
        int dl = ty + (i << 3);
        int d = d0 + dl;
        int nl = tx << 1;
        float k0 = tk[nl][dl], k1 = tk[nl + 1][dl];
        float v0 = tv[nl][dl], v1 = tv[nl + 1][dl];
        long long o = ((long long)(bz << 9) + d) * NPIX + n0 + nl;
        *(__half2*)(g_khi + o) = h2_rn(k0, k1);
        *(__half2*)(g_vhi + o) = h2_rn(v0, v1);
        float s = k0 + k1;
#pragma unroll
        for (int off = 16; off > 0; off >>= 1)
            s += __shfl_down_sync(0xffffffffu, s, off);
        if (tx == 0) atomicAdd(&g_ksum[(bz << 9) + d], s);
    }
}

// z[r] = sum_d kmean[d] * q[r][d] + eps
__global__ void z_kernel()
{
    __shared__ float km[512];
    int r0 = blockIdx.x << 3;
    int bb = r0 >> 12;
    for (int i = threadIdx.x; i < 512; i += 256)
        km[i] = g_ksum[(bb << 9) + i] * (1.f / NPIX);
    __syncthreads();
    int w = threadIdx.x >> 5, lane = threadIdx.x & 31;
    int r = r0 + w;
    const __half* qh = g_qthi + (long long)r * DIM;
    float s = 0.f;
#pragma unroll
    for (int i = 0; i < 16; i++) {
        int d = lane + (i << 5);
        s += km[d] * __half2float(qh[d]);
    }
#pragma unroll
    for (int off = 16; off > 0; off >>= 1)
        s += __shfl_down_sync(0xffffffffu, s, off);
    if (lane == 0) g_z[r] = s + 5e-4f;
}

// RMSNorm row + anw + SiLU(gate) -> o^T fp16 (hi only)
__global__ void rmsgate_kernel(const float* __restrict__ anw)
{
    __shared__ float red[4];
    int r = blockIdx.x;
    int t = threadIdx.x;
    int dg = t << 2;
    long long arow = (long long)r * DIM + dg;
    __half2 ah0 = *(const __half2*)(g_athi + arow);
    __half2 ah1 = *(const __half2*)(g_athi + arow + 2);
    __half2 al0 = *(const __half2*)(g_atlo + arow);
    __half2 al1 = *(const __half2*)(g_atlo + arow + 2);
    float a0 = __half2float(ah0.x) + __half2float(al0.x);
    float a1 = __half2float(ah0.y) + __half2float(al0.y);
    float a2 = __half2float(ah1.x) + __half2float(al1.x);
    float a3 = __half2float(ah1.y) + __half2float(al1.y);
    float ss = a0 * a0 + a1 * a1 + a2 * a2 + a3 * a3;
    int lane = t & 31, w = t >> 5;
#pragma unroll
    for (int off = 16; off > 0; off >>= 1)
        ss += __shfl_down_sync(0xffffffffu, ss, off);
    if (lane == 0) red[w] = ss;
    __syncthreads();
    float tot = red[0] + red[1] + red[2] + red[3];
    float rms = rsqrtf(tot * (1.f / DIM) + 1e-6f);

    long long grow = (long long)r * C4 + 1536 + dg;
    __half2 gh0 = *(const __half2*)(g_ythi + grow);
    __half2 gh1 = *(const __half2*)(g_ythi + grow + 2);
    __half2 gl0 = *(const __half2*)(g_ytlo + grow);
    __half2 gl1 = *(const __half2*)(g_ytlo + grow + 2);
    float yg0 = __half2float(gh0.x) + __half2float(gl0.x);
    float yg1 = __half2float(gh0.y) + __half2float(gl0.y);
    float yg2 = __half2float(gh1.x) + __half2float(gl1.x);
    float yg3 = __half2float(gh1.y) + __half2float(gl1.y);
    float4 ga = *(const float4*)(g_a1 + 1536 + dg);
    float4 gb = *(const float4*)(g_b1 + 1536 + dg);
    float4 wn = *(const float4*)(anw + dg);
    float g0 = ga.x * yg0 + gb.x, g1 = ga.y * yg1 + gb.y;
    float g2 = ga.z * yg2 + gb.z, g3 = ga.w * yg3 + gb.w;
    float o0 = a0 * rms * wn.x * (g0 / (1.f + expf(-g0)));
    float o1 = a1 * rms * wn.y * (g1 / (1.f + expf(-g1)));
    float o2 = a2 * rms * wn.z * (g2 / (1.f + expf(-g2)));
    float o3 = a3 * rms * wn.w * (g3 / (1.f + expf(-g3)));
    long long o = (long long)r * DIM + dg;
    *(__half2*)(g_othi + o)     = h2_rn(o0, o1);
    *(__half2*)(g_othi + o + 2) = h2_rn(o2, o3);
}

__global__ void bnapply_kernel(float* __restrict__ out)
{
    long long i = (long long)(blockIdx.x * blockDim.x + threadIdx.x) * 4;
    int c = (int)((i >> 12) & 511);
    float a = g_a2[c], bb = g_b2[c];
    float4 v = *reinterpret_cast<const float4*>(g_ypre + i);
    v.x = a * v.x + bb; v.y = a * v.y + bb;
    v.z = a * v.z + bb; v.w = a * v.w + bb;
    *reinterpret_cast<float4*>(out + i) = v;
}

// f32 -> fp16 (hi only)
__global__ void convert_half(const float* __restrict__ s,
                             __half* __restrict__ hi, int n)
{
    int i = blockIdx.x * blockDim.x + threadIdx.x;
    if (i < n) hi[i] = __float2half_rn(s[i]);
}

// transpose f32 src [b][R][Cc] -> fp16 hi-only dst [b][Cc][R]
__global__ void transpose_half(const float* __restrict__ src,
                               __half* __restrict__ dhi, int R, int Cc)
{
    __shared__ float t[32][33];
    int b = blockIdx.z;
    long long o = (long long)b * R * Cc;
    src += o; dhi += o;
    int c0 = blockIdx.x * 32, r0 = blockIdx.y * 32;
    int tx = threadIdx.x, ty = threadIdx.y;
#pragma unroll
    for (int i = 0; i < 4; i++)
        t[ty + 8 * i][tx] = src[(long long)(r0 + ty + 8 * i) * Cc + c0 + tx];
    __syncthreads();
#pragma unroll
    for (int i = 0; i < 4; i++) {
        int cc = c0 + ty + 8 * i;
        dhi[(long long)cc * R + r0 + tx] = __float2half_rn(t[tx][ty + 8 * i]);
    }
}

// ---------------------------------------------------------------------------
extern "C" void kernel_launch(void* const* d_in, const int* in_sizes, int n_in,
                              void* d_out, int out_size)
{
    const float* x           = (const float*)d_in[0];
    const float* qkvg_w      = (const float*)d_in[1];
    const float* qkvg_gamma  = (const float*)d_in[2];
    const float* qkvg_beta   = (const float*)d_in[3];
    const float* attn_norm_w = (const float*)d_in[4];
    const float* proj_w      = (const float*)d_in[5];
    const float* proj_gamma  = (const float*)d_in[6];
    const float* proj_beta   = (const float*)d_in[7];
    float* out = (float*)d_out;

    cudaFuncSetAttribute(gemm_mma<false, true, true, false>,
                         cudaFuncAttributeMaxDynamicSharedMemorySize, GSMEM);
    cudaFuncSetAttribute(gemm_mma<false, false, false, false>,
                         cudaFuncAttributeMaxDynamicSharedMemorySize, GSMEM);
    cudaFuncSetAttribute(gemm_mma<true, true, false, false>,
                         cudaFuncAttributeMaxDynamicSharedMemorySize, GSMEM);
    cudaFuncSetAttribute(gemm_mma<false, false, false, true>,
                         cudaFuncAttributeMaxDynamicSharedMemorySize, GSMEM);

    float *pypre, *pvkp, *pz;
    __half *pythi, *pytlo, *pathi, *patlo;
    __half *pkhi, *pvhi, *pqthi, *pxthi, *pothi, *pvkhi, *pwqhi, *ppwhi;
    cudaGetSymbolAddress((void**)&pythi, g_ythi);
    cudaGetSymbolAddress((void**)&pytlo, g_ytlo);
    cudaGetSymbolAddress((void**)&pathi, g_athi);
    cudaGetSymbolAddress((void**)&patlo, g_atlo);
    cudaGetSymbolAddress((void**)&pypre, g_ypre);
    cudaGetSymbolAddress((void**)&pvkp,  g_vkp);
    cudaGetSymbolAddress((void**)&pz,    g_z);
    cudaGetSymbolAddress((void**)&pkhi,  g_khi);
    cudaGetSymbolAddress((void**)&pvhi,  g_vhi);
    cudaGetSymbolAddress((void**)&pqthi, g_qthi);
    cudaGetSymbolAddress((void**)&pxthi, g_xthi);
    cudaGetSymbolAddress((void**)&pothi, g_othi);
    cudaGetSymbolAddress((void**)&pvkhi, g_vkhi);
    cudaGetSymbolAddress((void**)&pwqhi, g_wqhi);
    cudaGetSymbolAddress((void**)&ppwhi, g_pwhi);

    const long long sQKV = (long long)DIM * NPIX;   // 2097152
    const long long sYT  = (long long)NPIX * C4;    // 8388608
    const long long sVK  = (long long)DIM * DIM;    // 262144

    zero_kernel<<<32, 256>>>();
    convert_half<<<4096, 256>>>(qkvg_w, pwqhi, C4 * DIM);
    convert_half<<<1024, 256>>>(proj_w, ppwhi, DIM * DIM);
    transpose_half<<<dim3(128, 16, BATCH), dim3(32, 8)>>>(x, pxthi, DIM, NPIX);

    // 1) y^T = x^T @ w^T -> fp16 hi/lo + fused BN1 column stats
    gemm_mma<false, true, true, false><<<dim3(16, 32, BATCH), 128, GSMEM>>>(
        pxthi, pwqhi, nullptr, pythi, pytlo,
        2048, 512, 512, 1, sQKV, 0, sYT, 1.f, nullptr);

    // 2) BN1 finalize
    bn1_finalize<<<8, 256>>>(qkvg_gamma, qkvg_beta);

    // 3) q^T fp16; k hi + v hi -> [d][n] + ksum
    q_kernel<<<16384, 256>>>();
    kvt_kernel<<<dim3(64, 8, BATCH), dim3(32, 8)>>>();

    // 4) z
    z_kernel<<<4096, 256>>>();

    // 5) vk = v @ k^T, split-K x4; reduce -> fp16 hi
    gemm_mma<false, false, false, false><<<dim3(4, 4, BATCH * 4), 128, GSMEM>>>(
        pvhi, pkhi, pvkp, nullptr, nullptr,
        512, 1024, 4096, 4, sQKV, sQKV, sVK, 1.f, nullptr);
    vkred_kernel<<<2048, 256>>>();

    // 6) attn^T = q^T @ vk^T / z -> hi/lo fp16
    gemm_mma<true, true, false, false><<<dim3(4, 32, BATCH), 128, GSMEM>>>(
        pqthi, pvkhi, nullptr, pathi, patlo,
        512, 512, 512, 1, sQKV, sVK, sQKV, 1.f, pz);

    // 7) RMSNorm + gate -> o^T fp16
    rmsgate_kernel<<<32768, 128>>>(attn_norm_w);

    // 8) ypre = proj_w @ o + fused BN2 row stats
    gemm_mma<false, false, false, true><<<dim3(32, 4, BATCH), 128, GSMEM>>>(
        ppwhi, pothi, pypre, nullptr, nullptr,
        4096, 512, 512, 1, 0, sQKV, sQKV, 1.f, nullptr);

    // 9) BN2 finalize + apply
    bn2_finalize<<<2, 256>>>(proj_gamma, proj_beta);
    bnapply_kernel<<<16384, 256>>>(out);
}